// round 1
// baseline (speedup 1.0000x reference)
#include <cuda_runtime.h>
#include <math.h>

#define TT   2048
#define HIDN 2048
#define NH   32
#define NKV  8
#define DH   64
#define GRP  4
#define SCALE 0.125f

// Scratch (static __device__ arrays — no allocation at runtime)
__device__ float g_q[TT * NH * DH];     // [t][h][d]  16 MB
__device__ float g_k[TT * NKV * DH];    // [t][kvh][d] 4 MB
__device__ float g_v[TT * NKV * DH];    //             4 MB
__device__ float g_att[TT * NH * DH];   // [t][h][d]  16 MB

// ---------------------------------------------------------------------------
// C[M,N] = A[M,K] @ B[N,K]^T   (fp32, 128x128 block tile, 8 k-step, 8x8/thread)
// ---------------------------------------------------------------------------
__global__ void __launch_bounds__(256) gemm_nt(const float* __restrict__ A,
                                               const float* __restrict__ B,
                                               float* __restrict__ C,
                                               int M, int N, int K) {
    __shared__ float As[8][128];
    __shared__ float Bs[8][128];
    const int tid = threadIdx.x;
    const int tx = tid & 15;
    const int ty = tid >> 4;
    const int row0 = blockIdx.y * 128;
    const int col0 = blockIdx.x * 128;
    const int lr = tid >> 1;          // 0..127
    const int lc = (tid & 1) * 4;     // 0 or 4

    float acc[8][8];
#pragma unroll
    for (int i = 0; i < 8; i++)
#pragma unroll
        for (int j = 0; j < 8; j++) acc[i][j] = 0.f;

    const float* Aptr = A + (size_t)(row0 + lr) * K + lc;
    const float* Bptr = B + (size_t)(col0 + lr) * K + lc;

    for (int k0 = 0; k0 < K; k0 += 8) {
        float4 a = *(const float4*)(Aptr + k0);
        float4 b = *(const float4*)(Bptr + k0);
        As[lc + 0][lr] = a.x; As[lc + 1][lr] = a.y;
        As[lc + 2][lr] = a.z; As[lc + 3][lr] = a.w;
        Bs[lc + 0][lr] = b.x; Bs[lc + 1][lr] = b.y;
        Bs[lc + 2][lr] = b.z; Bs[lc + 3][lr] = b.w;
        __syncthreads();
#pragma unroll
        for (int kk = 0; kk < 8; kk++) {
            float ar[8], br[8];
#pragma unroll
            for (int i = 0; i < 8; i++) ar[i] = As[kk][ty * 8 + i];
#pragma unroll
            for (int j = 0; j < 8; j++) br[j] = Bs[kk][tx * 8 + j];
#pragma unroll
            for (int i = 0; i < 8; i++)
#pragma unroll
                for (int j = 0; j < 8; j++)
                    acc[i][j] = fmaf(ar[i], br[j], acc[i][j]);
        }
        __syncthreads();
    }
#pragma unroll
    for (int i = 0; i < 8; i++) {
        float* crow = C + (size_t)(row0 + ty * 8 + i) * N + col0 + tx * 8;
#pragma unroll
        for (int j = 0; j < 8; j += 4) {
            float4 v = make_float4(acc[i][j], acc[i][j + 1], acc[i][j + 2], acc[i][j + 3]);
            *(float4*)(crow + j) = v;
        }
    }
}

// ---------------------------------------------------------------------------
// RoPE in-place on g_q and g_k. One thread per (t, head, d<32) pair.
// ---------------------------------------------------------------------------
__global__ void rope_kernel(const float* __restrict__ cosb,
                            const float* __restrict__ sinb) {
    int idx = blockIdx.x * blockDim.x + threadIdx.x;
    const int total = TT * (NH + NKV) * (DH / 2);
    if (idx >= total) return;
    int d = idx & 31;
    int r = idx >> 5;
    int head = r % (NH + NKV);
    int t = r / (NH + NKV);
    float c = cosb[t * DH + d];
    float s = sinb[t * DH + d];
    float* ptr;
    int off;
    if (head < NH) { ptr = g_q; off = (t * NH + head) * DH; }
    else           { ptr = g_k; off = (t * NKV + (head - NH)) * DH; }
    float x1 = ptr[off + d];
    float x2 = ptr[off + d + 32];
    ptr[off + d]      = x1 * c - x2 * s;   // first half: x1*c + (-x2)*s
    ptr[off + d + 32] = x2 * c + x1 * s;   // second half: x2*c + x1*s
}

// ---------------------------------------------------------------------------
// Flash-style causal attention. One block = 64 query rows of one head.
// 256 threads. Tiles in dynamic shared, pad=68 floats/row.
// ---------------------------------------------------------------------------
#define SPAD 68

__global__ void __launch_bounds__(256) attn_kernel() {
    extern __shared__ float sm[];
    float (*Qs)[SPAD] = (float(*)[SPAD])(sm);
    float (*Ks)[SPAD] = (float(*)[SPAD])(sm + 64 * SPAD);
    float (*Vs)[SPAD] = (float(*)[SPAD])(sm + 2 * 64 * SPAD);
    float (*Ss)[SPAD] = (float(*)[SPAD])(sm + 3 * 64 * SPAD);

    const int tid = threadIdx.x;
    const int h = blockIdx.y;
    const int kvh = h / GRP;
    const int m0 = blockIdx.x * 64;

    // Q tile load: [64 rows][64 d] from g_q
    for (int e = tid; e < 64 * 16; e += 256) {
        int r = e >> 4;
        int c = (e & 15) * 4;
        float4 q4 = *(const float4*)&g_q[(size_t)(m0 + r) * (NH * DH) + h * DH + c];
        Qs[r][c] = q4.x; Qs[r][c + 1] = q4.y; Qs[r][c + 2] = q4.z; Qs[r][c + 3] = q4.w;
    }

    const int tx = tid & 15, ty = tid >> 4;   // S-compute roles (4x4 micro-tile)
    const int row = tid >> 2;                 // softmax/PV role: 4 threads per row
    const int c0 = (tid & 3) * 16;            // 16-col quarter

    float m = -1e30f, l = 0.f;
    float o[16];
#pragma unroll
    for (int j = 0; j < 16; j++) o[j] = 0.f;

    const int ntiles = blockIdx.x + 1;        // causal: only key tiles <= query tile
    for (int jt = 0; jt < ntiles; jt++) {
        const int n0 = jt * 64;
        __syncthreads();  // protect Ks/Vs/Ss from previous iteration readers
        for (int e = tid; e < 64 * 16; e += 256) {
            int r = e >> 4;
            int c = (e & 15) * 4;
            size_t gb = (size_t)(n0 + r) * (NKV * DH) + kvh * DH + c;
            float4 k4 = *(const float4*)&g_k[gb];
            Ks[r][c] = k4.x; Ks[r][c + 1] = k4.y; Ks[r][c + 2] = k4.z; Ks[r][c + 3] = k4.w;
            float4 v4 = *(const float4*)&g_v[gb];
            Vs[r][c] = v4.x; Vs[r][c + 1] = v4.y; Vs[r][c + 2] = v4.z; Vs[r][c + 3] = v4.w;
        }
        __syncthreads();

        // S = Q @ K^T  (raw dots) -> Ss
        float s[4][4];
#pragma unroll
        for (int i = 0; i < 4; i++)
#pragma unroll
            for (int j = 0; j < 4; j++) s[i][j] = 0.f;
#pragma unroll
        for (int d = 0; d < 64; d += 4) {
            float4 qv[4], kv[4];
#pragma unroll
            for (int i = 0; i < 4; i++) qv[i] = *(const float4*)&Qs[ty * 4 + i][d];
#pragma unroll
            for (int j = 0; j < 4; j++) kv[j] = *(const float4*)&Ks[tx * 4 + j][d];
#pragma unroll
            for (int i = 0; i < 4; i++)
#pragma unroll
                for (int j = 0; j < 4; j++) {
                    s[i][j] = fmaf(qv[i].x, kv[j].x, s[i][j]);
                    s[i][j] = fmaf(qv[i].y, kv[j].y, s[i][j]);
                    s[i][j] = fmaf(qv[i].z, kv[j].z, s[i][j]);
                    s[i][j] = fmaf(qv[i].w, kv[j].w, s[i][j]);
                }
        }
#pragma unroll
        for (int i = 0; i < 4; i++)
#pragma unroll
            for (int j = 0; j < 4; j++)
                Ss[ty * 4 + i][tx * 4 + j] = s[i][j];
        __syncthreads();

        // Online softmax: 4 threads cooperate per row via shfl (lanes 4k..4k+3)
        const bool diag = (jt == blockIdx.x);
        float pv[16];
        float tmax = -1e30f;
#pragma unroll
        for (int j = 0; j < 16; j++) {
            int col = c0 + j;
            float v = Ss[row][col] * SCALE;
            if (diag && (n0 + col > m0 + row)) v = -1e30f;
            pv[j] = v;
            tmax = fmaxf(tmax, v);
        }
        tmax = fmaxf(tmax, __shfl_xor_sync(0xffffffffu, tmax, 1));
        tmax = fmaxf(tmax, __shfl_xor_sync(0xffffffffu, tmax, 2));
        float newm = fmaxf(m, tmax);
        float fac = __expf(m - newm);
        float psum = 0.f;
#pragma unroll
        for (int j = 0; j < 16; j++) {
            float p = __expf(pv[j] - newm);
            psum += p;
            Ss[row][c0 + j] = p;
        }
        psum += __shfl_xor_sync(0xffffffffu, psum, 1);
        psum += __shfl_xor_sync(0xffffffffu, psum, 2);
        l = l * fac + psum;
        m = newm;
#pragma unroll
        for (int j = 0; j < 16; j++) o[j] *= fac;
        __syncthreads();

        // O += P @ V  (thread owns row `row`, cols c0..c0+15)
        for (int sI = 0; sI < 64; sI++) {
            float p = Ss[row][sI];
            float4 v0 = *(const float4*)&Vs[sI][c0];
            float4 v1 = *(const float4*)&Vs[sI][c0 + 4];
            float4 v2 = *(const float4*)&Vs[sI][c0 + 8];
            float4 v3 = *(const float4*)&Vs[sI][c0 + 12];
            o[0]  = fmaf(p, v0.x, o[0]);  o[1]  = fmaf(p, v0.y, o[1]);
            o[2]  = fmaf(p, v0.z, o[2]);  o[3]  = fmaf(p, v0.w, o[3]);
            o[4]  = fmaf(p, v1.x, o[4]);  o[5]  = fmaf(p, v1.y, o[5]);
            o[6]  = fmaf(p, v1.z, o[6]);  o[7]  = fmaf(p, v1.w, o[7]);
            o[8]  = fmaf(p, v2.x, o[8]);  o[9]  = fmaf(p, v2.y, o[9]);
            o[10] = fmaf(p, v2.z, o[10]); o[11] = fmaf(p, v2.w, o[11]);
            o[12] = fmaf(p, v3.x, o[12]); o[13] = fmaf(p, v3.y, o[13]);
            o[14] = fmaf(p, v3.z, o[14]); o[15] = fmaf(p, v3.w, o[15]);
        }
    }

    float inv = 1.f / l;
    float* optr = &g_att[(size_t)(m0 + row) * (NH * DH) + h * DH + c0];
#pragma unroll
    for (int j = 0; j < 16; j += 4) {
        float4 v = make_float4(o[j] * inv, o[j + 1] * inv, o[j + 2] * inv, o[j + 3] * inv);
        *(float4*)(optr + j) = v;
    }
}

// ---------------------------------------------------------------------------
extern "C" void kernel_launch(void* const* d_in, const int* in_sizes, int n_in,
                              void* d_out, int out_size) {
    const float* x    = (const float*)d_in[0];
    const float* cosb = (const float*)d_in[1];
    const float* sinb = (const float*)d_in[2];
    // d_in[3] = attention_mask_4d (causal; applied analytically)
    const float* Wq   = (const float*)d_in[4];
    const float* Wk   = (const float*)d_in[5];
    const float* Wv   = (const float*)d_in[6];
    const float* Wo   = (const float*)d_in[7];
    float* out = (float*)d_out;

    float *q, *k, *v, *att;
    cudaGetSymbolAddress((void**)&q, g_q);
    cudaGetSymbolAddress((void**)&k, g_k);
    cudaGetSymbolAddress((void**)&v, g_v);
    cudaGetSymbolAddress((void**)&att, g_att);

    // QKV projections
    gemm_nt<<<dim3(16, 16), 256>>>(x, Wq, q, TT, NH * DH, HIDN);
    gemm_nt<<<dim3(4, 16), 256>>>(x, Wk, k, TT, NKV * DH, HIDN);
    gemm_nt<<<dim3(4, 16), 256>>>(x, Wv, v, TT, NKV * DH, HIDN);

    // RoPE on q, k
    {
        int total = TT * (NH + NKV) * (DH / 2);
        rope_kernel<<<(total + 255) / 256, 256>>>(cosb, sinb);
    }

    // Causal GQA attention
    {
        const int smem = 4 * 64 * SPAD * (int)sizeof(float);
        cudaFuncSetAttribute(attn_kernel, cudaFuncAttributeMaxDynamicSharedMemorySize, smem);
        attn_kernel<<<dim3(TT / 64, NH), 256, smem>>>();
    }

    // Output projection
    gemm_nt<<<dim3(16, 16), 256>>>(att, Wo, out, TT, HIDN, NH * DH);
}

// round 2
// speedup vs baseline: 4.7452x; 4.7452x over previous
#include <cuda_runtime.h>
#include <stdint.h>
#include <math.h>

#define TT   2048
#define HIDN 2048
#define NH   32
#define NKV  8
#define DH   64
#define GRP  4
#define SCALE 0.125f

// Scratch (static __device__ arrays — no allocation at runtime)
__device__ float g_q[TT * NH * DH];
__device__ float g_k[TT * NKV * DH];
__device__ float g_v[TT * NKV * DH];
__device__ float g_att[TT * NH * DH];

__device__ __forceinline__ uint32_t f2tf(float x) {
    uint32_t r;
    asm("cvt.rna.tf32.f32 %0, %1;" : "=r"(r) : "f"(x));
    return r;
}

__device__ __forceinline__ void mma_tf32(float* c,
                                         uint32_t a0, uint32_t a1, uint32_t a2, uint32_t a3,
                                         uint32_t b0, uint32_t b1) {
    asm volatile(
        "mma.sync.aligned.m16n8k8.row.col.f32.tf32.tf32.f32 "
        "{%0,%1,%2,%3},{%4,%5,%6,%7},{%8,%9},{%0,%1,%2,%3};"
        : "+f"(c[0]), "+f"(c[1]), "+f"(c[2]), "+f"(c[3])
        : "r"(a0), "r"(a1), "r"(a2), "r"(a3), "r"(b0), "r"(b1));
}

// ---------------------------------------------------------------------------
// C[M,N] = A[M,K] @ B[N,K]^T  via tf32 mma. 128x128 block tile, K-step 32.
// 256 threads = 8 warps, warp grid 2(m) x 4(n), warp tile 64x32.
// ---------------------------------------------------------------------------
#define GP 36   // smem row stride (floats): (4*row + t) % 32 unique => conflict-free frags

__global__ void __launch_bounds__(256) gemm_tf32(const float* __restrict__ A,
                                                 const float* __restrict__ B,
                                                 float* __restrict__ C,
                                                 int M, int N, int K) {
    __shared__ uint32_t As[128 * GP];
    __shared__ uint32_t Bs[128 * GP];

    const int tid = threadIdx.x;
    const int wid = tid >> 5, lane = tid & 31;
    const int g = lane >> 2, t = lane & 3;
    const int wm = (wid >> 2) * 64;      // warp m offset in tile (0 or 64)
    const int wn = (wid & 3) * 32;       // warp n offset in tile
    const int row0 = blockIdx.y * 128;
    const int col0 = blockIdx.x * 128;

    float acc[4][4][4];
#pragma unroll
    for (int i = 0; i < 4; i++)
#pragma unroll
        for (int j = 0; j < 4; j++)
#pragma unroll
            for (int q = 0; q < 4; q++) acc[i][j][q] = 0.f;

    for (int k0 = 0; k0 < K; k0 += 32) {
#pragma unroll
        for (int i = 0; i < 4; i++) {
            int idx = tid + i * 256;
            int r = idx >> 3;
            int c = (idx & 7) * 4;
            float4 a = *(const float4*)(A + (size_t)(row0 + r) * K + k0 + c);
            As[r * GP + c + 0] = f2tf(a.x); As[r * GP + c + 1] = f2tf(a.y);
            As[r * GP + c + 2] = f2tf(a.z); As[r * GP + c + 3] = f2tf(a.w);
            float4 b = *(const float4*)(B + (size_t)(col0 + r) * K + k0 + c);
            Bs[r * GP + c + 0] = f2tf(b.x); Bs[r * GP + c + 1] = f2tf(b.y);
            Bs[r * GP + c + 2] = f2tf(b.z); Bs[r * GP + c + 3] = f2tf(b.w);
        }
        __syncthreads();

#pragma unroll
        for (int ks = 0; ks < 4; ks++) {
            const int kk = ks * 8;
            uint32_t af[4][4], bf[4][2];
#pragma unroll
            for (int mi = 0; mi < 4; mi++) {
                int base = wm + mi * 16;
                af[mi][0] = As[(base + g)     * GP + kk + t];
                af[mi][1] = As[(base + g + 8) * GP + kk + t];
                af[mi][2] = As[(base + g)     * GP + kk + t + 4];
                af[mi][3] = As[(base + g + 8) * GP + kk + t + 4];
            }
#pragma unroll
            for (int nj = 0; nj < 4; nj++) {
                int nb = wn + nj * 8;
                bf[nj][0] = Bs[(nb + g) * GP + kk + t];
                bf[nj][1] = Bs[(nb + g) * GP + kk + t + 4];
            }
#pragma unroll
            for (int mi = 0; mi < 4; mi++)
#pragma unroll
                for (int nj = 0; nj < 4; nj++)
                    mma_tf32(acc[mi][nj], af[mi][0], af[mi][1], af[mi][2], af[mi][3],
                             bf[nj][0], bf[nj][1]);
        }
        __syncthreads();
    }

#pragma unroll
    for (int mi = 0; mi < 4; mi++) {
#pragma unroll
        for (int nj = 0; nj < 4; nj++) {
            int r = row0 + wm + mi * 16 + g;
            int c = col0 + wn + nj * 8 + 2 * t;
            float2 v0 = make_float2(acc[mi][nj][0], acc[mi][nj][1]);
            float2 v1 = make_float2(acc[mi][nj][2], acc[mi][nj][3]);
            *(float2*)(C + (size_t)r * N + c)       = v0;
            *(float2*)(C + (size_t)(r + 8) * N + c) = v1;
        }
    }
}

// ---------------------------------------------------------------------------
// RoPE in-place on g_q and g_k.
// ---------------------------------------------------------------------------
__global__ void rope_kernel(const float* __restrict__ cosb,
                            const float* __restrict__ sinb) {
    int idx = blockIdx.x * blockDim.x + threadIdx.x;
    const int total = TT * (NH + NKV) * (DH / 2);
    if (idx >= total) return;
    int d = idx & 31;
    int r = idx >> 5;
    int head = r % (NH + NKV);
    int t = r / (NH + NKV);
    float c = cosb[t * DH + d];
    float s = sinb[t * DH + d];
    float* ptr;
    int off;
    if (head < NH) { ptr = g_q; off = (t * NH + head) * DH; }
    else           { ptr = g_k; off = (t * NKV + (head - NH)) * DH; }
    float x1 = ptr[off + d];
    float x2 = ptr[off + d + 32];
    ptr[off + d]      = x1 * c - x2 * s;
    ptr[off + d + 32] = x2 * c + x1 * s;
}

// ---------------------------------------------------------------------------
// Flash attention with tf32 mma for S=QK^T and O+=P@V.
// Block = 64 query rows x 1 head. 128 threads = 4 warps (each warp: 16 rows).
// ---------------------------------------------------------------------------
#define AP 68   // padded row stride for 64-wide tiles

__global__ void __launch_bounds__(128) attn_kernel() {
    extern __shared__ uint32_t smbuf[];
    uint32_t* Qs = smbuf;                 // tf32 bits [64][AP]
    uint32_t* Ks = smbuf + 64 * AP;
    uint32_t* Vs = smbuf + 2 * 64 * AP;
    float*    Ss = (float*)(smbuf + 3 * 64 * AP);   // S then P(tf32 bits) [64][AP]
    float*    fac = (float*)(smbuf + 4 * 64 * AP);  // per-row rescale / 1/l [64]

    const int tid = threadIdx.x;
    const int wid = tid >> 5, lane = tid & 31;
    const int g = lane >> 2, t = lane & 3;
    const int wm = wid * 16;
    const int h = blockIdx.y;
    const int kvh = h / GRP;
    const int m0 = blockIdx.x * 64;

    // Load Q tile (rope'd fp32 -> tf32 bits)
    for (int e = tid; e < 64 * 16; e += 128) {
        int r = e >> 4;
        int c = (e & 15) * 4;
        float4 q = *(const float4*)&g_q[(size_t)(m0 + r) * (NH * DH) + h * DH + c];
        Qs[r * AP + c + 0] = f2tf(q.x); Qs[r * AP + c + 1] = f2tf(q.y);
        Qs[r * AP + c + 2] = f2tf(q.z); Qs[r * AP + c + 3] = f2tf(q.w);
    }

    // Softmax role: 2 threads per row
    const int srow = tid >> 1;
    const int sc0 = (tid & 1) * 32;
    float mrow = -1e30f, lrow = 0.f;

    float o[8][4];
#pragma unroll
    for (int j = 0; j < 8; j++)
#pragma unroll
        for (int q = 0; q < 4; q++) o[j][q] = 0.f;

    const int ntiles = blockIdx.x + 1;
    for (int jt = 0; jt < ntiles; jt++) {
        const int n0 = jt * 64;
        __syncthreads();   // previous iteration's readers done with Ks/Vs/Ss
        for (int e = tid; e < 64 * 16; e += 128) {
            int r = e >> 4;
            int c = (e & 15) * 4;
            size_t gb = (size_t)(n0 + r) * (NKV * DH) + kvh * DH + c;
            float4 k4 = *(const float4*)&g_k[gb];
            Ks[r * AP + c + 0] = f2tf(k4.x); Ks[r * AP + c + 1] = f2tf(k4.y);
            Ks[r * AP + c + 2] = f2tf(k4.z); Ks[r * AP + c + 3] = f2tf(k4.w);
            float4 v4 = *(const float4*)&g_v[gb];
            Vs[r * AP + c + 0] = f2tf(v4.x); Vs[r * AP + c + 1] = f2tf(v4.y);
            Vs[r * AP + c + 2] = f2tf(v4.z); Vs[r * AP + c + 3] = f2tf(v4.w);
        }
        __syncthreads();

        // S = Q @ K^T : warp computes rows [wm, wm+16), all 64 cols
        float s[8][4];
#pragma unroll
        for (int j = 0; j < 8; j++)
#pragma unroll
            for (int q = 0; q < 4; q++) s[j][q] = 0.f;
#pragma unroll
        for (int ks = 0; ks < 8; ks++) {
            const int kk = ks * 8;
            uint32_t a0 = Qs[(wm + g)     * AP + kk + t];
            uint32_t a1 = Qs[(wm + g + 8) * AP + kk + t];
            uint32_t a2 = Qs[(wm + g)     * AP + kk + t + 4];
            uint32_t a3 = Qs[(wm + g + 8) * AP + kk + t + 4];
#pragma unroll
            for (int nj = 0; nj < 8; nj++) {
                uint32_t b0 = Ks[(nj * 8 + g) * AP + kk + t];
                uint32_t b1 = Ks[(nj * 8 + g) * AP + kk + t + 4];
                mma_tf32(s[nj], a0, a1, a2, a3, b0, b1);
            }
        }
#pragma unroll
        for (int nj = 0; nj < 8; nj++) {
            int c = nj * 8 + 2 * t;
            Ss[(wm + g)     * AP + c]     = s[nj][0];
            Ss[(wm + g)     * AP + c + 1] = s[nj][1];
            Ss[(wm + g + 8) * AP + c]     = s[nj][2];
            Ss[(wm + g + 8) * AP + c + 1] = s[nj][3];
        }
        __syncthreads();

        // Online softmax over this tile (2 threads per row, shfl pair-combine)
        const bool diag = (jt == blockIdx.x);
        float pv[32];
        float tmax = -1e30f;
#pragma unroll
        for (int j = 0; j < 32; j++) {
            int col = sc0 + j;
            float v = Ss[srow * AP + col] * SCALE;
            if (diag && (n0 + col > m0 + srow)) v = -1e30f;
            pv[j] = v;
            tmax = fmaxf(tmax, v);
        }
        tmax = fmaxf(tmax, __shfl_xor_sync(0xffffffffu, tmax, 1));
        float nm = fmaxf(mrow, tmax);
        float f = __expf(mrow - nm);
        float ps = 0.f;
        uint32_t* Ps = (uint32_t*)Ss;
#pragma unroll
        for (int j = 0; j < 32; j++) {
            float p = __expf(pv[j] - nm);
            ps += p;
            Ps[srow * AP + sc0 + j] = f2tf(p);
        }
        ps += __shfl_xor_sync(0xffffffffu, ps, 1);
        lrow = lrow * f + ps;
        mrow = nm;
        if ((tid & 1) == 0) fac[srow] = f;
        __syncthreads();

        // Rescale O accumulators
        float f0 = fac[wm + g], f1 = fac[wm + g + 8];
#pragma unroll
        for (int nj = 0; nj < 8; nj++) {
            o[nj][0] *= f0; o[nj][1] *= f0;
            o[nj][2] *= f1; o[nj][3] *= f1;
        }

        // O += P @ V
#pragma unroll
        for (int ks = 0; ks < 8; ks++) {
            const int kk = ks * 8;
            uint32_t a0 = Ps[(wm + g)     * AP + kk + t];
            uint32_t a1 = Ps[(wm + g + 8) * AP + kk + t];
            uint32_t a2 = Ps[(wm + g)     * AP + kk + t + 4];
            uint32_t a3 = Ps[(wm + g + 8) * AP + kk + t + 4];
#pragma unroll
            for (int nj = 0; nj < 8; nj++) {
                uint32_t b0 = Vs[(kk + t)     * AP + nj * 8 + g];
                uint32_t b1 = Vs[(kk + t + 4) * AP + nj * 8 + g];
                mma_tf32(o[nj], a0, a1, a2, a3, b0, b1);
            }
        }
    }

    // Final normalize and store
    __syncthreads();
    if ((tid & 1) == 0) fac[srow] = 1.f / lrow;
    __syncthreads();
    float i0 = fac[wm + g], i1 = fac[wm + g + 8];
#pragma unroll
    for (int nj = 0; nj < 8; nj++) {
        int c = nj * 8 + 2 * t;
        float* p0 = &g_att[(size_t)(m0 + wm + g) * (NH * DH) + h * DH + c];
        float* p1 = &g_att[(size_t)(m0 + wm + g + 8) * (NH * DH) + h * DH + c];
        p0[0] = o[nj][0] * i0; p0[1] = o[nj][1] * i0;
        p1[0] = o[nj][2] * i1; p1[1] = o[nj][3] * i1;
    }
}

// ---------------------------------------------------------------------------
extern "C" void kernel_launch(void* const* d_in, const int* in_sizes, int n_in,
                              void* d_out, int out_size) {
    const float* x    = (const float*)d_in[0];
    const float* cosb = (const float*)d_in[1];
    const float* sinb = (const float*)d_in[2];
    // d_in[3] = attention_mask_4d (causal; applied analytically)
    const float* Wq   = (const float*)d_in[4];
    const float* Wk   = (const float*)d_in[5];
    const float* Wv   = (const float*)d_in[6];
    const float* Wo   = (const float*)d_in[7];
    float* out = (float*)d_out;

    float *q, *k, *v, *att;
    cudaGetSymbolAddress((void**)&q, g_q);
    cudaGetSymbolAddress((void**)&k, g_k);
    cudaGetSymbolAddress((void**)&v, g_v);
    cudaGetSymbolAddress((void**)&att, g_att);

    // QKV projections (tf32 tensor cores)
    gemm_tf32<<<dim3(16, 16), 256>>>(x, Wq, q, TT, NH * DH, HIDN);
    gemm_tf32<<<dim3(4, 16), 256>>>(x, Wk, k, TT, NKV * DH, HIDN);
    gemm_tf32<<<dim3(4, 16), 256>>>(x, Wv, v, TT, NKV * DH, HIDN);

    // RoPE on q, k
    {
        int total = TT * (NH + NKV) * (DH / 2);
        rope_kernel<<<(total + 255) / 256, 256>>>(cosb, sinb);
    }

    // Causal GQA attention (tf32 tensor cores)
    {
        const int smem = (4 * 64 * AP + 64) * (int)sizeof(float);
        cudaFuncSetAttribute(attn_kernel, cudaFuncAttributeMaxDynamicSharedMemorySize, smem);
        attn_kernel<<<dim3(TT / 64, NH), 128, smem>>>();
    }

    // Output projection
    gemm_tf32<<<dim3(16, 16), 256>>>(att, Wo, out, TT, HIDN, NH * DH);
}

// round 3
// speedup vs baseline: 5.7916x; 1.2205x over previous
#include <cuda_runtime.h>
#include <stdint.h>
#include <math.h>

#define TT   2048
#define HIDN 2048
#define NH   32
#define NKV  8
#define DH   64
#define GRP  4
#define SCALE 0.125f

__device__ float g_q[TT * NH * DH];
__device__ float g_k[TT * NKV * DH];
__device__ float g_v[TT * NKV * DH];
__device__ float g_att[TT * NH * DH];

__device__ __forceinline__ uint32_t f2tf(float x) {
    uint32_t r;
    asm("cvt.rna.tf32.f32 %0, %1;" : "=r"(r) : "f"(x));
    return r;
}

__device__ __forceinline__ void mma_tf32(float* c,
                                         uint32_t a0, uint32_t a1, uint32_t a2, uint32_t a3,
                                         uint32_t b0, uint32_t b1) {
    asm volatile(
        "mma.sync.aligned.m16n8k8.row.col.f32.tf32.tf32.f32 "
        "{%0,%1,%2,%3},{%4,%5,%6,%7},{%8,%9},{%0,%1,%2,%3};"
        : "+f"(c[0]), "+f"(c[1]), "+f"(c[2]), "+f"(c[3])
        : "r"(a0), "r"(a1), "r"(a2), "r"(a3), "r"(b0), "r"(b1));
}

// ---------------------------------------------------------------------------
// GEMM body: C[row0:+128, col0:+128] += A[M,K] @ B[N,K]^T, tf32 MMA,
// register double-buffered global->smem pipeline. 256 threads.
// ---------------------------------------------------------------------------
#define GP 36

__device__ __forceinline__ void gemm_body(const float* __restrict__ A,
                                          const float* __restrict__ B,
                                          float* __restrict__ C,
                                          int N, int K, int row0, int col0,
                                          uint32_t* As, uint32_t* Bs) {
    const int tid = threadIdx.x;
    const int wid = tid >> 5, lane = tid & 31;
    const int g = lane >> 2, t = lane & 3;
    const int wm = (wid >> 2) * 64;
    const int wn = (wid & 3) * 32;

    const int rbase = tid >> 3;
    const int cc = (tid & 7) * 4;
    const float* Ap = A + (size_t)(row0 + rbase) * K + cc;
    const float* Bp = B + (size_t)(col0 + rbase) * K + cc;

    float acc[4][4][4];
#pragma unroll
    for (int i = 0; i < 4; i++)
#pragma unroll
        for (int j = 0; j < 4; j++)
#pragma unroll
            for (int q = 0; q < 4; q++) acc[i][j][q] = 0.f;

    float4 pa[4], pb[4];
#pragma unroll
    for (int i = 0; i < 4; i++) {
        pa[i] = *(const float4*)(Ap + (size_t)i * 32 * K);
        pb[i] = *(const float4*)(Bp + (size_t)i * 32 * K);
    }

    for (int k0 = 0; k0 < K; k0 += 32) {
#pragma unroll
        for (int i = 0; i < 4; i++) {
            int r = rbase + 32 * i;
            As[r * GP + cc + 0] = f2tf(pa[i].x); As[r * GP + cc + 1] = f2tf(pa[i].y);
            As[r * GP + cc + 2] = f2tf(pa[i].z); As[r * GP + cc + 3] = f2tf(pa[i].w);
            Bs[r * GP + cc + 0] = f2tf(pb[i].x); Bs[r * GP + cc + 1] = f2tf(pb[i].y);
            Bs[r * GP + cc + 2] = f2tf(pb[i].z); Bs[r * GP + cc + 3] = f2tf(pb[i].w);
        }
        __syncthreads();

        if (k0 + 32 < K) {
#pragma unroll
            for (int i = 0; i < 4; i++) {
                pa[i] = *(const float4*)(Ap + (size_t)i * 32 * K + k0 + 32);
                pb[i] = *(const float4*)(Bp + (size_t)i * 32 * K + k0 + 32);
            }
        }

#pragma unroll
        for (int ks = 0; ks < 4; ks++) {
            const int kk = ks * 8;
            uint32_t af[4][4], bf[4][2];
#pragma unroll
            for (int mi = 0; mi < 4; mi++) {
                int base = wm + mi * 16;
                af[mi][0] = As[(base + g)     * GP + kk + t];
                af[mi][1] = As[(base + g + 8) * GP + kk + t];
                af[mi][2] = As[(base + g)     * GP + kk + t + 4];
                af[mi][3] = As[(base + g + 8) * GP + kk + t + 4];
            }
#pragma unroll
            for (int nj = 0; nj < 4; nj++) {
                int nb = wn + nj * 8;
                bf[nj][0] = Bs[(nb + g) * GP + kk + t];
                bf[nj][1] = Bs[(nb + g) * GP + kk + t + 4];
            }
#pragma unroll
            for (int mi = 0; mi < 4; mi++)
#pragma unroll
                for (int nj = 0; nj < 4; nj++)
                    mma_tf32(acc[mi][nj], af[mi][0], af[mi][1], af[mi][2], af[mi][3],
                             bf[nj][0], bf[nj][1]);
        }
        __syncthreads();
    }

#pragma unroll
    for (int mi = 0; mi < 4; mi++) {
#pragma unroll
        for (int nj = 0; nj < 4; nj++) {
            int r = row0 + wm + mi * 16 + g;
            int c = col0 + wn + nj * 8 + 2 * t;
            *(float2*)(C + (size_t)r * N + c)       = make_float2(acc[mi][nj][0], acc[mi][nj][1]);
            *(float2*)(C + (size_t)(r + 8) * N + c) = make_float2(acc[mi][nj][2], acc[mi][nj][3]);
        }
    }
}

// Fused QKV projection: blockIdx.x picks Wq (0-15), Wk (16-19), Wv (20-23)
__global__ void __launch_bounds__(256) qkv_gemm(const float* __restrict__ x,
                                                const float* __restrict__ Wq,
                                                const float* __restrict__ Wk,
                                                const float* __restrict__ Wv,
                                                float* q, float* k, float* v) {
    __shared__ uint32_t As[128 * GP];
    __shared__ uint32_t Bs[128 * GP];
    int bx = blockIdx.x;
    int row0 = blockIdx.y * 128;
    if (bx < 16)      gemm_body(x, Wq, q, NH * DH,  HIDN, row0, bx * 128,        As, Bs);
    else if (bx < 20) gemm_body(x, Wk, k, NKV * DH, HIDN, row0, (bx - 16) * 128, As, Bs);
    else              gemm_body(x, Wv, v, NKV * DH, HIDN, row0, (bx - 20) * 128, As, Bs);
}

__global__ void __launch_bounds__(256) o_gemm(const float* __restrict__ A,
                                              const float* __restrict__ Wo,
                                              float* __restrict__ C) {
    __shared__ uint32_t As[128 * GP];
    __shared__ uint32_t Bs[128 * GP];
    gemm_body(A, Wo, C, HIDN, NH * DH, blockIdx.y * 128, blockIdx.x * 128, As, Bs);
}

// ---------------------------------------------------------------------------
// RoPE in-place on g_q and g_k.
// ---------------------------------------------------------------------------
__global__ void rope_kernel(const float* __restrict__ cosb,
                            const float* __restrict__ sinb) {
    int idx = blockIdx.x * blockDim.x + threadIdx.x;
    const int total = TT * (NH + NKV) * (DH / 2);
    if (idx >= total) return;
    int d = idx & 31;
    int r = idx >> 5;
    int head = r % (NH + NKV);
    int t = r / (NH + NKV);
    float c = cosb[t * DH + d];
    float s = sinb[t * DH + d];
    float* ptr;
    int off;
    if (head < NH) { ptr = g_q; off = (t * NH + head) * DH; }
    else           { ptr = g_k; off = (t * NKV + (head - NH)) * DH; }
    float x1 = ptr[off + d];
    float x2 = ptr[off + d + 32];
    ptr[off + d]      = x1 * c - x2 * s;
    ptr[off + d + 32] = x2 * c + x1 * s;
}

// ---------------------------------------------------------------------------
// Flash attention, tf32 MMA, register softmax.
// Block = 128 query rows x 1 head, 256 threads = 8 warps (16 rows each).
// ---------------------------------------------------------------------------
#define AP 68

__global__ void __launch_bounds__(256) attn_kernel() {
    extern __shared__ uint32_t smbuf[];
    uint32_t* Ks = smbuf;                  // [64][AP] tf32
    uint32_t* Vs = smbuf + 64 * AP;        // [64][AP] tf32
    uint32_t* Ps = smbuf + 2 * 64 * AP;    // [128][AP] Q staging, then P tf32

    const int tid = threadIdx.x;
    const int wid = tid >> 5, lane = tid & 31;
    const int g = lane >> 2, t = lane & 3;
    const int wm = wid * 16;
    const int h = blockIdx.y;
    const int kvh = h / GRP;
    const int m0 = blockIdx.x * 128;

    // Stage Q tile (coalesced, scaled, tf32) then pick up fragments into regs
    for (int e = tid; e < 128 * 16; e += 256) {
        int r = e >> 4;
        int c = (e & 15) * 4;
        float4 q = *(const float4*)&g_q[(size_t)(m0 + r) * (NH * DH) + h * DH + c];
        Ps[r * AP + c + 0] = f2tf(q.x * SCALE); Ps[r * AP + c + 1] = f2tf(q.y * SCALE);
        Ps[r * AP + c + 2] = f2tf(q.z * SCALE); Ps[r * AP + c + 3] = f2tf(q.w * SCALE);
    }
    __syncthreads();
    uint32_t qf[8][4];
#pragma unroll
    for (int ks = 0; ks < 8; ks++) {
        const int kk = ks * 8;
        qf[ks][0] = Ps[(wm + g)     * AP + kk + t];
        qf[ks][1] = Ps[(wm + g + 8) * AP + kk + t];
        qf[ks][2] = Ps[(wm + g)     * AP + kk + t + 4];
        qf[ks][3] = Ps[(wm + g + 8) * AP + kk + t + 4];
    }

    float mr0 = -1e30f, mr1 = -1e30f, l0 = 0.f, l1 = 0.f;
    float o[8][4];
#pragma unroll
    for (int j = 0; j < 8; j++)
#pragma unroll
        for (int q = 0; q < 4; q++) o[j][q] = 0.f;

    const int ntiles = 2 * blockIdx.x + 2;
    for (int jt = 0; jt < ntiles; jt++) {
        const int n0 = jt * 64;
        __syncthreads();   // prior readers of Ks/Vs/Ps done
        for (int e = tid; e < 64 * 16; e += 256) {
            int r = e >> 4;
            int c = (e & 15) * 4;
            size_t gb = (size_t)(n0 + r) * (NKV * DH) + kvh * DH + c;
            float4 k4 = *(const float4*)&g_k[gb];
            Ks[r * AP + c + 0] = f2tf(k4.x); Ks[r * AP + c + 1] = f2tf(k4.y);
            Ks[r * AP + c + 2] = f2tf(k4.z); Ks[r * AP + c + 3] = f2tf(k4.w);
            float4 v4 = *(const float4*)&g_v[gb];
            Vs[r * AP + c + 0] = f2tf(v4.x); Vs[r * AP + c + 1] = f2tf(v4.y);
            Vs[r * AP + c + 2] = f2tf(v4.z); Vs[r * AP + c + 3] = f2tf(v4.w);
        }
        __syncthreads();

        // S = Q @ K^T (scaled already)
        float s[8][4];
#pragma unroll
        for (int j = 0; j < 8; j++)
#pragma unroll
            for (int q = 0; q < 4; q++) s[j][q] = 0.f;
#pragma unroll
        for (int ks = 0; ks < 8; ks++) {
            const int kk = ks * 8;
#pragma unroll
            for (int nj = 0; nj < 8; nj++) {
                uint32_t b0 = Ks[(nj * 8 + g) * AP + kk + t];
                uint32_t b1 = Ks[(nj * 8 + g) * AP + kk + t + 4];
                mma_tf32(s[nj], qf[ks][0], qf[ks][1], qf[ks][2], qf[ks][3], b0, b1);
            }
        }

        // Causal mask (only last two tiles can be masked)
        if (jt >= 2 * (int)blockIdx.x) {
            const int r0 = m0 + wm + g, r1 = r0 + 8;
#pragma unroll
            for (int nj = 0; nj < 8; nj++) {
                int c0 = n0 + nj * 8 + 2 * t;
                if (c0     > r0) s[nj][0] = -1e30f;
                if (c0 + 1 > r0) s[nj][1] = -1e30f;
                if (c0     > r1) s[nj][2] = -1e30f;
                if (c0 + 1 > r1) s[nj][3] = -1e30f;
            }
        }

        // Register softmax (quad shfl over t lanes)
        float mx0 = -1e30f, mx1 = -1e30f;
#pragma unroll
        for (int nj = 0; nj < 8; nj++) {
            mx0 = fmaxf(mx0, fmaxf(s[nj][0], s[nj][1]));
            mx1 = fmaxf(mx1, fmaxf(s[nj][2], s[nj][3]));
        }
        mx0 = fmaxf(mx0, __shfl_xor_sync(0xffffffffu, mx0, 1));
        mx0 = fmaxf(mx0, __shfl_xor_sync(0xffffffffu, mx0, 2));
        mx1 = fmaxf(mx1, __shfl_xor_sync(0xffffffffu, mx1, 1));
        mx1 = fmaxf(mx1, __shfl_xor_sync(0xffffffffu, mx1, 2));
        float nm0 = fmaxf(mr0, mx0), nm1 = fmaxf(mr1, mx1);
        float f0 = __expf(mr0 - nm0), f1 = __expf(mr1 - nm1);
        float ps0 = 0.f, ps1 = 0.f;
#pragma unroll
        for (int nj = 0; nj < 8; nj++) {
            int c = nj * 8 + 2 * t;
            float p0 = __expf(s[nj][0] - nm0);
            float p1 = __expf(s[nj][1] - nm0);
            float p2 = __expf(s[nj][2] - nm1);
            float p3 = __expf(s[nj][3] - nm1);
            ps0 += p0 + p1; ps1 += p2 + p3;
            Ps[(wm + g)     * AP + c]     = f2tf(p0);
            Ps[(wm + g)     * AP + c + 1] = f2tf(p1);
            Ps[(wm + g + 8) * AP + c]     = f2tf(p2);
            Ps[(wm + g + 8) * AP + c + 1] = f2tf(p3);
        }
        ps0 += __shfl_xor_sync(0xffffffffu, ps0, 1);
        ps0 += __shfl_xor_sync(0xffffffffu, ps0, 2);
        ps1 += __shfl_xor_sync(0xffffffffu, ps1, 1);
        ps1 += __shfl_xor_sync(0xffffffffu, ps1, 2);
        l0 = l0 * f0 + ps0; l1 = l1 * f1 + ps1;
        mr0 = nm0; mr1 = nm1;
#pragma unroll
        for (int nj = 0; nj < 8; nj++) {
            o[nj][0] *= f0; o[nj][1] *= f0;
            o[nj][2] *= f1; o[nj][3] *= f1;
        }
        __syncthreads();

        // O += P @ V
#pragma unroll
        for (int ks = 0; ks < 8; ks++) {
            const int kk = ks * 8;
            uint32_t a0 = Ps[(wm + g)     * AP + kk + t];
            uint32_t a1 = Ps[(wm + g + 8) * AP + kk + t];
            uint32_t a2 = Ps[(wm + g)     * AP + kk + t + 4];
            uint32_t a3 = Ps[(wm + g + 8) * AP + kk + t + 4];
#pragma unroll
            for (int nj = 0; nj < 8; nj++) {
                uint32_t b0 = Vs[(kk + t)     * AP + nj * 8 + g];
                uint32_t b1 = Vs[(kk + t + 4) * AP + nj * 8 + g];
                mma_tf32(o[nj], a0, a1, a2, a3, b0, b1);
            }
        }
    }

    // Normalize and store
    float i0 = 1.f / l0, i1 = 1.f / l1;
#pragma unroll
    for (int nj = 0; nj < 8; nj++) {
        int c = nj * 8 + 2 * t;
        float* p0 = &g_att[(size_t)(m0 + wm + g)     * (NH * DH) + h * DH + c];
        float* p1 = &g_att[(size_t)(m0 + wm + g + 8) * (NH * DH) + h * DH + c];
        *(float2*)p0 = make_float2(o[nj][0] * i0, o[nj][1] * i0);
        *(float2*)p1 = make_float2(o[nj][2] * i1, o[nj][3] * i1);
    }
}

// ---------------------------------------------------------------------------
extern "C" void kernel_launch(void* const* d_in, const int* in_sizes, int n_in,
                              void* d_out, int out_size) {
    const float* x    = (const float*)d_in[0];
    const float* cosb = (const float*)d_in[1];
    const float* sinb = (const float*)d_in[2];
    const float* Wq   = (const float*)d_in[4];
    const float* Wk   = (const float*)d_in[5];
    const float* Wv   = (const float*)d_in[6];
    const float* Wo   = (const float*)d_in[7];
    float* out = (float*)d_out;

    float *q, *k, *v, *att;
    cudaGetSymbolAddress((void**)&q, g_q);
    cudaGetSymbolAddress((void**)&k, g_k);
    cudaGetSymbolAddress((void**)&v, g_v);
    cudaGetSymbolAddress((void**)&att, g_att);

    qkv_gemm<<<dim3(24, 16), 256>>>(x, Wq, Wk, Wv, q, k, v);

    {
        int total = TT * (NH + NKV) * (DH / 2);
        rope_kernel<<<(total + 255) / 256, 256>>>(cosb, sinb);
    }

    {
        const int smem = (2 * 64 * AP + 128 * AP) * (int)sizeof(uint32_t);
        cudaFuncSetAttribute(attn_kernel, cudaFuncAttributeMaxDynamicSharedMemorySize, smem);
        attn_kernel<<<dim3(TT / 128, NH), 256, smem>>>();
    }

    o_gemm<<<dim3(16, 16), 256>>>(att, Wo, out);
}

// round 4
// speedup vs baseline: 5.8288x; 1.0064x over previous
#include <cuda_runtime.h>
#include <stdint.h>
#include <math.h>

#define TT   2048
#define HIDN 2048
#define NH   32
#define NKV  8
#define DH   64
#define GRP  4
#define QSCALE 0.1803368801111204f   // (1/8) * log2(e)

__device__ float g_q[TT * NH * DH];
__device__ float g_k[TT * NKV * DH];
__device__ float g_v[TT * NKV * DH];
__device__ float g_att[TT * NH * DH];

__device__ __forceinline__ uint32_t f2tf(float x) {
    uint32_t r;
    asm("cvt.rna.tf32.f32 %0, %1;" : "=r"(r) : "f"(x));
    return r;
}

__device__ __forceinline__ void mma_tf32(float* c,
                                         uint32_t a0, uint32_t a1, uint32_t a2, uint32_t a3,
                                         uint32_t b0, uint32_t b1) {
    asm volatile(
        "mma.sync.aligned.m16n8k8.row.col.f32.tf32.tf32.f32 "
        "{%0,%1,%2,%3},{%4,%5,%6,%7},{%8,%9},{%0,%1,%2,%3};"
        : "+f"(c[0]), "+f"(c[1]), "+f"(c[2]), "+f"(c[3])
        : "r"(a0), "r"(a1), "r"(a2), "r"(a3), "r"(b0), "r"(b1));
}

// ---------------------------------------------------------------------------
// GEMM: C[row0:+128, col0:+128] = A[M,K] @ B[N,K]^T, tf32 MMA,
// double-buffered smem (1 sync per 32-K slab). 256 threads.
// ---------------------------------------------------------------------------
#define GP 36
#define SLAB (128 * GP)

__device__ __forceinline__ void gemm_body(const float* __restrict__ A,
                                          const float* __restrict__ B,
                                          float* __restrict__ C,
                                          int N, int K, int row0, int col0,
                                          uint32_t* __restrict__ sm) {
    // sm layout: As[2][SLAB], Bs[2][SLAB]
    uint32_t* As = sm;
    uint32_t* Bs = sm + 2 * SLAB;

    const int tid = threadIdx.x;
    const int wid = tid >> 5, lane = tid & 31;
    const int g = lane >> 2, t = lane & 3;
    const int wm = (wid >> 2) * 64;
    const int wn = (wid & 3) * 32;

    const int rbase = tid >> 3;
    const int cc = (tid & 7) * 4;
    const float* Ap = A + (size_t)(row0 + rbase) * K + cc;
    const float* Bp = B + (size_t)(col0 + rbase) * K + cc;

    float acc[4][4][4];
#pragma unroll
    for (int i = 0; i < 4; i++)
#pragma unroll
        for (int j = 0; j < 4; j++)
#pragma unroll
            for (int q = 0; q < 4; q++) acc[i][j][q] = 0.f;

    float4 pa[4], pb[4];
#pragma unroll
    for (int i = 0; i < 4; i++) {
        pa[i] = *(const float4*)(Ap + (size_t)i * 32 * K);
        pb[i] = *(const float4*)(Bp + (size_t)i * 32 * K);
    }
    // stage 0 fill
#pragma unroll
    for (int i = 0; i < 4; i++) {
        int r = rbase + 32 * i;
        As[r * GP + cc + 0] = f2tf(pa[i].x); As[r * GP + cc + 1] = f2tf(pa[i].y);
        As[r * GP + cc + 2] = f2tf(pa[i].z); As[r * GP + cc + 3] = f2tf(pa[i].w);
        Bs[r * GP + cc + 0] = f2tf(pb[i].x); Bs[r * GP + cc + 1] = f2tf(pb[i].y);
        Bs[r * GP + cc + 2] = f2tf(pb[i].z); Bs[r * GP + cc + 3] = f2tf(pb[i].w);
    }
    __syncthreads();

    for (int k0 = 0; k0 < K; k0 += 32) {
        const int st = (k0 >> 5) & 1;
        uint32_t* Ac = As + st * SLAB;
        uint32_t* Bc = Bs + st * SLAB;
        const bool more = (k0 + 32 < K);

        if (more) {
#pragma unroll
            for (int i = 0; i < 4; i++) {
                pa[i] = *(const float4*)(Ap + (size_t)i * 32 * K + k0 + 32);
                pb[i] = *(const float4*)(Bp + (size_t)i * 32 * K + k0 + 32);
            }
        }

#pragma unroll
        for (int ks = 0; ks < 4; ks++) {
            const int kk = ks * 8;
            uint32_t af[4][4], bf[4][2];
#pragma unroll
            for (int mi = 0; mi < 4; mi++) {
                int base = wm + mi * 16;
                af[mi][0] = Ac[(base + g)     * GP + kk + t];
                af[mi][1] = Ac[(base + g + 8) * GP + kk + t];
                af[mi][2] = Ac[(base + g)     * GP + kk + t + 4];
                af[mi][3] = Ac[(base + g + 8) * GP + kk + t + 4];
            }
#pragma unroll
            for (int nj = 0; nj < 4; nj++) {
                int nb = wn + nj * 8;
                bf[nj][0] = Bc[(nb + g) * GP + kk + t];
                bf[nj][1] = Bc[(nb + g) * GP + kk + t + 4];
            }
#pragma unroll
            for (int mi = 0; mi < 4; mi++)
#pragma unroll
                for (int nj = 0; nj < 4; nj++)
                    mma_tf32(acc[mi][nj], af[mi][0], af[mi][1], af[mi][2], af[mi][3],
                             bf[nj][0], bf[nj][1]);
        }

        if (more) {
            uint32_t* An = As + (st ^ 1) * SLAB;
            uint32_t* Bn = Bs + (st ^ 1) * SLAB;
#pragma unroll
            for (int i = 0; i < 4; i++) {
                int r = rbase + 32 * i;
                An[r * GP + cc + 0] = f2tf(pa[i].x); An[r * GP + cc + 1] = f2tf(pa[i].y);
                An[r * GP + cc + 2] = f2tf(pa[i].z); An[r * GP + cc + 3] = f2tf(pa[i].w);
                Bn[r * GP + cc + 0] = f2tf(pb[i].x); Bn[r * GP + cc + 1] = f2tf(pb[i].y);
                Bn[r * GP + cc + 2] = f2tf(pb[i].z); Bn[r * GP + cc + 3] = f2tf(pb[i].w);
            }
            __syncthreads();
        }
    }

#pragma unroll
    for (int mi = 0; mi < 4; mi++) {
#pragma unroll
        for (int nj = 0; nj < 4; nj++) {
            int r = row0 + wm + mi * 16 + g;
            int c = col0 + wn + nj * 8 + 2 * t;
            *(float2*)(C + (size_t)r * N + c)       = make_float2(acc[mi][nj][0], acc[mi][nj][1]);
            *(float2*)(C + (size_t)(r + 8) * N + c) = make_float2(acc[mi][nj][2], acc[mi][nj][3]);
        }
    }
}

#define GEMM_SMEM (4 * SLAB * (int)sizeof(uint32_t))

__global__ void __launch_bounds__(256) qkv_gemm(const float* __restrict__ x,
                                                const float* __restrict__ Wq,
                                                const float* __restrict__ Wk,
                                                const float* __restrict__ Wv,
                                                float* q, float* k, float* v) {
    extern __shared__ uint32_t sm[];
    int bx = blockIdx.x;
    int row0 = blockIdx.y * 128;
    if (bx < 16)      gemm_body(x, Wq, q, NH * DH,  HIDN, row0, bx * 128,        sm);
    else if (bx < 20) gemm_body(x, Wk, k, NKV * DH, HIDN, row0, (bx - 16) * 128, sm);
    else              gemm_body(x, Wv, v, NKV * DH, HIDN, row0, (bx - 20) * 128, sm);
}

__global__ void __launch_bounds__(256) o_gemm(const float* __restrict__ A,
                                              const float* __restrict__ Wo,
                                              float* __restrict__ C) {
    extern __shared__ uint32_t sm[];
    gemm_body(A, Wo, C, HIDN, NH * DH, blockIdx.y * 128, blockIdx.x * 128, sm);
}

// ---------------------------------------------------------------------------
// RoPE in-place on g_q and g_k.
// ---------------------------------------------------------------------------
__global__ void rope_kernel(const float* __restrict__ cosb,
                            const float* __restrict__ sinb) {
    int idx = blockIdx.x * blockDim.x + threadIdx.x;
    const int total = TT * (NH + NKV) * (DH / 2);
    if (idx >= total) return;
    int d = idx & 31;
    int r = idx >> 5;
    int head = r % (NH + NKV);
    int t = r / (NH + NKV);
    float c = cosb[t * DH + d];
    float s = sinb[t * DH + d];
    float* ptr;
    int off;
    if (head < NH) { ptr = g_q; off = (t * NH + head) * DH; }
    else           { ptr = g_k; off = (t * NKV + (head - NH)) * DH; }
    float x1 = ptr[off + d];
    float x2 = ptr[off + d + 32];
    ptr[off + d]      = x1 * c - x2 * s;
    ptr[off + d + 32] = x2 * c + x1 * s;
}

// ---------------------------------------------------------------------------
// Flash attention, tf32 MMA, base-2 register softmax, 2 syncs per key tile.
// Block = 128 query rows x 1 head, 256 threads = 8 warps (16 rows each).
// ---------------------------------------------------------------------------
#define AP 68

__global__ void __launch_bounds__(256) attn_kernel() {
    extern __shared__ uint32_t smbuf[];
    uint32_t* Ks = smbuf;                  // [64][AP] tf32
    uint32_t* Vs = smbuf + 64 * AP;        // [64][AP] tf32
    uint32_t* Ps = smbuf + 2 * 64 * AP;    // [128][AP] Q staging, then P tf32

    const int tid = threadIdx.x;
    const int wid = tid >> 5, lane = tid & 31;
    const int g = lane >> 2, t = lane & 3;
    const int wm = wid * 16;
    const int h = blockIdx.y;
    const int kvh = h / GRP;
    const int bx = gridDim.x - 1 - blockIdx.x;   // heavy tiles first
    const int m0 = bx * 128;

    // Stage Q (scaled by 1/8 * log2e -> base-2 softmax), pick up fragments
    for (int e = tid; e < 128 * 16; e += 256) {
        int r = e >> 4;
        int c = (e & 15) * 4;
        float4 q = *(const float4*)&g_q[(size_t)(m0 + r) * (NH * DH) + h * DH + c];
        Ps[r * AP + c + 0] = f2tf(q.x * QSCALE); Ps[r * AP + c + 1] = f2tf(q.y * QSCALE);
        Ps[r * AP + c + 2] = f2tf(q.z * QSCALE); Ps[r * AP + c + 3] = f2tf(q.w * QSCALE);
    }
    __syncthreads();
    uint32_t qf[8][4];
#pragma unroll
    for (int ks = 0; ks < 8; ks++) {
        const int kk = ks * 8;
        qf[ks][0] = Ps[(wm + g)     * AP + kk + t];
        qf[ks][1] = Ps[(wm + g + 8) * AP + kk + t];
        qf[ks][2] = Ps[(wm + g)     * AP + kk + t + 4];
        qf[ks][3] = Ps[(wm + g + 8) * AP + kk + t + 4];
    }

    float mr0 = -1e30f, mr1 = -1e30f, l0 = 0.f, l1 = 0.f;
    float o[8][4];
#pragma unroll
    for (int j = 0; j < 8; j++)
#pragma unroll
        for (int q = 0; q < 4; q++) o[j][q] = 0.f;

    const int ntiles = 2 * bx + 2;
    for (int jt = 0; jt < ntiles; jt++) {
        const int n0 = jt * 64;
        __syncthreads();   // prior readers of Ks/Vs done
        for (int e = tid; e < 64 * 16; e += 256) {
            int r = e >> 4;
            int c = (e & 15) * 4;
            size_t gb = (size_t)(n0 + r) * (NKV * DH) + kvh * DH + c;
            float4 k4 = *(const float4*)&g_k[gb];
            Ks[r * AP + c + 0] = f2tf(k4.x); Ks[r * AP + c + 1] = f2tf(k4.y);
            Ks[r * AP + c + 2] = f2tf(k4.z); Ks[r * AP + c + 3] = f2tf(k4.w);
            float4 v4 = *(const float4*)&g_v[gb];
            Vs[r * AP + c + 0] = f2tf(v4.x); Vs[r * AP + c + 1] = f2tf(v4.y);
            Vs[r * AP + c + 2] = f2tf(v4.z); Vs[r * AP + c + 3] = f2tf(v4.w);
        }
        __syncthreads();

        // S = Q @ K^T (log2-domain scores)
        float s[8][4];
#pragma unroll
        for (int j = 0; j < 8; j++)
#pragma unroll
            for (int q = 0; q < 4; q++) s[j][q] = 0.f;
#pragma unroll
        for (int ks = 0; ks < 8; ks++) {
            const int kk = ks * 8;
#pragma unroll
            for (int nj = 0; nj < 8; nj++) {
                uint32_t b0 = Ks[(nj * 8 + g) * AP + kk + t];
                uint32_t b1 = Ks[(nj * 8 + g) * AP + kk + t + 4];
                mma_tf32(s[nj], qf[ks][0], qf[ks][1], qf[ks][2], qf[ks][3], b0, b1);
            }
        }

        // Causal mask (only the last two key tiles intersect the diagonal)
        if (jt >= 2 * bx) {
            const int r0 = m0 + wm + g, r1 = r0 + 8;
#pragma unroll
            for (int nj = 0; nj < 8; nj++) {
                int c0 = n0 + nj * 8 + 2 * t;
                if (c0     > r0) s[nj][0] = -1e30f;
                if (c0 + 1 > r0) s[nj][1] = -1e30f;
                if (c0     > r1) s[nj][2] = -1e30f;
                if (c0 + 1 > r1) s[nj][3] = -1e30f;
            }
        }

        // Register softmax, base 2 (quad shfl over t lanes)
        float mx0 = -1e30f, mx1 = -1e30f;
#pragma unroll
        for (int nj = 0; nj < 8; nj++) {
            mx0 = fmaxf(mx0, fmaxf(s[nj][0], s[nj][1]));
            mx1 = fmaxf(mx1, fmaxf(s[nj][2], s[nj][3]));
        }
        mx0 = fmaxf(mx0, __shfl_xor_sync(0xffffffffu, mx0, 1));
        mx0 = fmaxf(mx0, __shfl_xor_sync(0xffffffffu, mx0, 2));
        mx1 = fmaxf(mx1, __shfl_xor_sync(0xffffffffu, mx1, 1));
        mx1 = fmaxf(mx1, __shfl_xor_sync(0xffffffffu, mx1, 2));
        float nm0 = fmaxf(mr0, mx0), nm1 = fmaxf(mr1, mx1);
        float f0 = exp2f(mr0 - nm0), f1 = exp2f(mr1 - nm1);
        float ps0 = 0.f, ps1 = 0.f;
#pragma unroll
        for (int nj = 0; nj < 8; nj++) {
            int c = nj * 8 + 2 * t;
            float p0 = exp2f(s[nj][0] - nm0);
            float p1 = exp2f(s[nj][1] - nm0);
            float p2 = exp2f(s[nj][2] - nm1);
            float p3 = exp2f(s[nj][3] - nm1);
            ps0 += p0 + p1; ps1 += p2 + p3;
            Ps[(wm + g)     * AP + c]     = f2tf(p0);
            Ps[(wm + g)     * AP + c + 1] = f2tf(p1);
            Ps[(wm + g + 8) * AP + c]     = f2tf(p2);
            Ps[(wm + g + 8) * AP + c + 1] = f2tf(p3);
        }
        ps0 += __shfl_xor_sync(0xffffffffu, ps0, 1);
        ps0 += __shfl_xor_sync(0xffffffffu, ps0, 2);
        ps1 += __shfl_xor_sync(0xffffffffu, ps1, 1);
        ps1 += __shfl_xor_sync(0xffffffffu, ps1, 2);
        l0 = l0 * f0 + ps0; l1 = l1 * f1 + ps1;
        mr0 = nm0; mr1 = nm1;
#pragma unroll
        for (int nj = 0; nj < 8; nj++) {
            o[nj][0] *= f0; o[nj][1] *= f0;
            o[nj][2] *= f1; o[nj][3] *= f1;
        }
        __syncwarp();   // P rows are warp-private: warp-level ordering suffices

        // O += P @ V
#pragma unroll
        for (int ks = 0; ks < 8; ks++) {
            const int kk = ks * 8;
            uint32_t a0 = Ps[(wm + g)     * AP + kk + t];
            uint32_t a1 = Ps[(wm + g + 8) * AP + kk + t];
            uint32_t a2 = Ps[(wm + g)     * AP + kk + t + 4];
            uint32_t a3 = Ps[(wm + g + 8) * AP + kk + t + 4];
#pragma unroll
            for (int nj = 0; nj < 8; nj++) {
                uint32_t b0 = Vs[(kk + t)     * AP + nj * 8 + g];
                uint32_t b1 = Vs[(kk + t + 4) * AP + nj * 8 + g];
                mma_tf32(o[nj], a0, a1, a2, a3, b0, b1);
            }
        }
    }

    // Normalize and store
    float i0 = 1.f / l0, i1 = 1.f / l1;
#pragma unroll
    for (int nj = 0; nj < 8; nj++) {
        int c = nj * 8 + 2 * t;
        float* p0 = &g_att[(size_t)(m0 + wm + g)     * (NH * DH) + h * DH + c];
        float* p1 = &g_att[(size_t)(m0 + wm + g + 8) * (NH * DH) + h * DH + c];
        *(float2*)p0 = make_float2(o[nj][0] * i0, o[nj][1] * i0);
        *(float2*)p1 = make_float2(o[nj][2] * i1, o[nj][3] * i1);
    }
}

// ---------------------------------------------------------------------------
extern "C" void kernel_launch(void* const* d_in, const int* in_sizes, int n_in,
                              void* d_out, int out_size) {
    const float* x    = (const float*)d_in[0];
    const float* cosb = (const float*)d_in[1];
    const float* sinb = (const float*)d_in[2];
    const float* Wq   = (const float*)d_in[4];
    const float* Wk   = (const float*)d_in[5];
    const float* Wv   = (const float*)d_in[6];
    const float* Wo   = (const float*)d_in[7];
    float* out = (float*)d_out;

    float *q, *k, *v, *att;
    cudaGetSymbolAddress((void**)&q, g_q);
    cudaGetSymbolAddress((void**)&k, g_k);
    cudaGetSymbolAddress((void**)&v, g_v);
    cudaGetSymbolAddress((void**)&att, g_att);

    cudaFuncSetAttribute(qkv_gemm, cudaFuncAttributeMaxDynamicSharedMemorySize, GEMM_SMEM);
    cudaFuncSetAttribute(o_gemm,   cudaFuncAttributeMaxDynamicSharedMemorySize, GEMM_SMEM);

    qkv_gemm<<<dim3(24, 16), 256, GEMM_SMEM>>>(x, Wq, Wk, Wv, q, k, v);

    {
        int total = TT * (NH + NKV) * (DH / 2);
        rope_kernel<<<(total + 255) / 256, 256>>>(cosb, sinb);
    }

    {
        const int smem = (2 * 64 * AP + 128 * AP) * (int)sizeof(uint32_t);
        cudaFuncSetAttribute(attn_kernel, cudaFuncAttributeMaxDynamicSharedMemorySize, smem);
        attn_kernel<<<dim3(TT / 128, NH), 256, smem>>>();
    }

    o_gemm<<<dim3(16, 16), 256, GEMM_SMEM>>>(att, Wo, out);
}

// round 6
// speedup vs baseline: 10.5041x; 1.8021x over previous
#include <cuda_runtime.h>
#include <cuda_fp16.h>
#include <stdint.h>
#include <math.h>

#define TT   2048
#define HIDN 2048
#define NH   32
#define NKV  8
#define DH   64
#define GRP  4
#define QSCALE 0.1803368801111204f   // (1/8) * log2(e)

// fp32 intermediates from GEMMs
__device__ float g_q[TT * NH * DH];
__device__ float g_k[TT * NKV * DH];
__device__ float g_v[TT * NKV * DH];
__device__ float g_att[TT * NH * DH];
// half-precision attention operands
__device__ __half g_qh[TT * NH * DH];            // pre-scaled by QSCALE
__device__ __half g_kh[TT * NKV * DH];
__device__ __half g_vt[NKV * DH * TT];           // V transposed: [kvh][d][t]

__device__ __forceinline__ uint32_t pack_half2(float lo, float hi) {
    uint32_t r;
    asm("cvt.rn.f16x2.f32 %0, %1, %2;" : "=r"(r) : "f"(hi), "f"(lo));
    return r;
}

__device__ __forceinline__ void mma_fp16(float* c,
                                         uint32_t a0, uint32_t a1, uint32_t a2, uint32_t a3,
                                         uint32_t b0, uint32_t b1) {
    asm volatile(
        "mma.sync.aligned.m16n8k16.row.col.f32.f16.f16.f32 "
        "{%0,%1,%2,%3},{%4,%5,%6,%7},{%8,%9},{%0,%1,%2,%3};"
        : "+f"(c[0]), "+f"(c[1]), "+f"(c[2]), "+f"(c[3])
        : "r"(a0), "r"(a1), "r"(a2), "r"(a3), "r"(b0), "r"(b1));
}

// ---------------------------------------------------------------------------
// fp16 GEMM: C[row0:+128, col0:+128] = A[*,K] @ B[*,K]^T (fp32 in, fp32 out)
// 256 threads, 8 warps (2x4), warp tile 64x32, K-slab 32, double-buffered.
// smem rows stored as half2, stride 20 half2 (bank-conflict-free frags).
// ---------------------------------------------------------------------------
#define ST2 20
#define SLABH (128 * ST2)
#define GEMM_SMEM (4 * SLABH * (int)sizeof(uint32_t))

__device__ __forceinline__ void gemm_body(const float* __restrict__ A,
                                          const float* __restrict__ B,
                                          float* __restrict__ C,
                                          int N, int K, int row0, int col0,
                                          uint32_t* __restrict__ sm) {
    uint32_t* As = sm;
    uint32_t* Bs = sm + 2 * SLABH;

    const int tid = threadIdx.x;
    const int wid = tid >> 5, lane = tid & 31;
    const int g = lane >> 2, t = lane & 3;
    const int wm = (wid >> 2) * 64;
    const int wn = (wid & 3) * 32;

    const int rbase = tid >> 3;
    const int cc = tid & 7;                   // float4 chunk (8 per 32-k row)
    const float* Ap = A + (size_t)(row0 + rbase) * K + cc * 4;
    const float* Bp = B + (size_t)(col0 + rbase) * K + cc * 4;

    float acc[4][4][4];
#pragma unroll
    for (int i = 0; i < 4; i++)
#pragma unroll
        for (int j = 0; j < 4; j++)
#pragma unroll
            for (int q = 0; q < 4; q++) acc[i][j][q] = 0.f;

    float4 pa[4], pb[4];
#pragma unroll
    for (int i = 0; i < 4; i++) {
        pa[i] = *(const float4*)(Ap + (size_t)i * 32 * K);
        pb[i] = *(const float4*)(Bp + (size_t)i * 32 * K);
    }
    // stage 0 fill
#pragma unroll
    for (int i = 0; i < 4; i++) {
        int r = rbase + 32 * i;
        uint2 av = make_uint2(pack_half2(pa[i].x, pa[i].y), pack_half2(pa[i].z, pa[i].w));
        uint2 bv = make_uint2(pack_half2(pb[i].x, pb[i].y), pack_half2(pb[i].z, pb[i].w));
        *(uint2*)&As[r * ST2 + cc * 2] = av;
        *(uint2*)&Bs[r * ST2 + cc * 2] = bv;
    }
    __syncthreads();

    for (int k0 = 0; k0 < K; k0 += 32) {
        const int st = (k0 >> 5) & 1;
        uint32_t* Ac = As + st * SLABH;
        uint32_t* Bc = Bs + st * SLABH;
        const bool more = (k0 + 32 < K);

        if (more) {
#pragma unroll
            for (int i = 0; i < 4; i++) {
                pa[i] = *(const float4*)(Ap + (size_t)i * 32 * K + k0 + 32);
                pb[i] = *(const float4*)(Bp + (size_t)i * 32 * K + k0 + 32);
            }
        }

#pragma unroll
        for (int ks = 0; ks < 2; ks++) {
            const int kk2 = ks * 8;           // half2 offset of this k16 step
            uint32_t af[4][4], bf[4][2];
#pragma unroll
            for (int mi = 0; mi < 4; mi++) {
                int base = wm + mi * 16;
                af[mi][0] = Ac[(base + g)     * ST2 + kk2 + t];
                af[mi][1] = Ac[(base + g + 8) * ST2 + kk2 + t];
                af[mi][2] = Ac[(base + g)     * ST2 + kk2 + t + 4];
                af[mi][3] = Ac[(base + g + 8) * ST2 + kk2 + t + 4];
            }
#pragma unroll
            for (int nj = 0; nj < 4; nj++) {
                int nb = wn + nj * 8;
                bf[nj][0] = Bc[(nb + g) * ST2 + kk2 + t];
                bf[nj][1] = Bc[(nb + g) * ST2 + kk2 + t + 4];
            }
#pragma unroll
            for (int mi = 0; mi < 4; mi++)
#pragma unroll
                for (int nj = 0; nj < 4; nj++)
                    mma_fp16(acc[mi][nj], af[mi][0], af[mi][1], af[mi][2], af[mi][3],
                             bf[nj][0], bf[nj][1]);
        }

        if (more) {
            uint32_t* An = As + (st ^ 1) * SLABH;
            uint32_t* Bn = Bs + (st ^ 1) * SLABH;
#pragma unroll
            for (int i = 0; i < 4; i++) {
                int r = rbase + 32 * i;
                uint2 av = make_uint2(pack_half2(pa[i].x, pa[i].y), pack_half2(pa[i].z, pa[i].w));
                uint2 bv = make_uint2(pack_half2(pb[i].x, pb[i].y), pack_half2(pb[i].z, pb[i].w));
                *(uint2*)&An[r * ST2 + cc * 2] = av;
                *(uint2*)&Bn[r * ST2 + cc * 2] = bv;
            }
            __syncthreads();
        }
    }

#pragma unroll
    for (int mi = 0; mi < 4; mi++) {
#pragma unroll
        for (int nj = 0; nj < 4; nj++) {
            int r = row0 + wm + mi * 16 + g;
            int c = col0 + wn + nj * 8 + 2 * t;
            *(float2*)(C + (size_t)r * N + c)       = make_float2(acc[mi][nj][0], acc[mi][nj][1]);
            *(float2*)(C + (size_t)(r + 8) * N + c) = make_float2(acc[mi][nj][2], acc[mi][nj][3]);
        }
    }
}

__global__ void __launch_bounds__(256, 2) qkv_gemm(const float* __restrict__ x,
                                                   const float* __restrict__ Wq,
                                                   const float* __restrict__ Wk,
                                                   const float* __restrict__ Wv,
                                                   float* q, float* k, float* v) {
    extern __shared__ uint32_t sm[];
    int bx = blockIdx.x;
    int row0 = blockIdx.y * 128;
    if (bx < 16)      gemm_body(x, Wq, q, NH * DH,  HIDN, row0, bx * 128,        sm);
    else if (bx < 20) gemm_body(x, Wk, k, NKV * DH, HIDN, row0, (bx - 16) * 128, sm);
    else              gemm_body(x, Wv, v, NKV * DH, HIDN, row0, (bx - 20) * 128, sm);
}

__global__ void __launch_bounds__(256, 2) o_gemm(const float* __restrict__ A,
                                                 const float* __restrict__ Wo,
                                                 float* __restrict__ C) {
    extern __shared__ uint32_t sm[];
    gemm_body(A, Wo, C, HIDN, NH * DH, blockIdx.y * 128, blockIdx.x * 128, sm);
}

// ---------------------------------------------------------------------------
// RoPE: read fp32 q/k, write half q (pre-scaled by QSCALE) and half k.
// ---------------------------------------------------------------------------
__global__ void rope_kernel(const float* __restrict__ cosb,
                            const float* __restrict__ sinb) {
    int idx = blockIdx.x * blockDim.x + threadIdx.x;
    const int total = TT * (NH + NKV) * (DH / 2);
    if (idx >= total) return;
    int d = idx & 31;
    int r = idx >> 5;
    int head = r % (NH + NKV);
    int t = r / (NH + NKV);
    float c = cosb[t * DH + d];
    float s = sinb[t * DH + d];
    if (head < NH) {
        int off = (t * NH + head) * DH;
        float x1 = g_q[off + d], x2 = g_q[off + d + 32];
        g_qh[off + d]      = __float2half((x1 * c - x2 * s) * QSCALE);
        g_qh[off + d + 32] = __float2half((x2 * c + x1 * s) * QSCALE);
    } else {
        int off = (t * NKV + (head - NH)) * DH;
        float x1 = g_k[off + d], x2 = g_k[off + d + 32];
        g_kh[off + d]      = __float2half(x1 * c - x2 * s);
        g_kh[off + d + 32] = __float2half(x2 * c + x1 * s);
    }
}

// ---------------------------------------------------------------------------
// V transpose: g_v fp32 [t][kvh][d] -> g_vt half [kvh][d][t]
// ---------------------------------------------------------------------------
__global__ void __launch_bounds__(256) vtrans_kernel() {
    __shared__ float sm[64][65];
    const int tid = threadIdx.x;
    const int t0 = blockIdx.x * 64;
    const int kvh = blockIdx.y;
    for (int e = tid; e < 64 * 16; e += 256) {
        int r = e >> 4, c4 = (e & 15) * 4;
        float4 v = *(const float4*)&g_v[(size_t)(t0 + r) * (NKV * DH) + kvh * DH + c4];
        sm[r][c4] = v.x; sm[r][c4 + 1] = v.y; sm[r][c4 + 2] = v.z; sm[r][c4 + 3] = v.w;
    }
    __syncthreads();
    for (int e = tid; e < 64 * 8; e += 256) {
        int d = e >> 3, ch = e & 7;
        int kb = ch * 8;
        uint4 o;
        o.x = pack_half2(sm[kb + 0][d], sm[kb + 1][d]);
        o.y = pack_half2(sm[kb + 2][d], sm[kb + 3][d]);
        o.z = pack_half2(sm[kb + 4][d], sm[kb + 5][d]);
        o.w = pack_half2(sm[kb + 6][d], sm[kb + 7][d]);
        *(uint4*)&g_vt[(size_t)(kvh * DH + d) * TT + t0 + kb] = o;
    }
}

// ---------------------------------------------------------------------------
// Flash attention, fp16 MMA (m16n8k16), base-2 register softmax.
// Block = 128 query rows x 1 head, 256 threads = 8 warps (16 rows each).
// ---------------------------------------------------------------------------
#define KP2 36   // half2 stride for 64-half rows

__global__ void __launch_bounds__(256) attn_kernel() {
    extern __shared__ uint32_t smbuf[];
    uint32_t* Ks = smbuf;                    // [64][KP2]   keys x d
    uint32_t* Vs = smbuf + 64 * KP2;         // [64][KP2]   d x keys (V^T)
    uint32_t* Ps = smbuf + 2 * 64 * KP2;     // [128][KP2]  Q staging, then P

    const int tid = threadIdx.x;
    const int wid = tid >> 5, lane = tid & 31;
    const int g = lane >> 2, t = lane & 3;
    const int wm = wid * 16;
    const int h = blockIdx.y;
    const int kvh = h / GRP;
    const int bx = gridDim.x - 1 - blockIdx.x;   // heavy CTAs first
    const int m0 = bx * 128;

    // Stage Q (already half + scaled) and pick up fragments
    for (int e = tid; e < 128 * 8; e += 256) {
        int r = e >> 3, ch = e & 7;
        uint4 qv = *(const uint4*)&g_qh[(size_t)(m0 + r) * (NH * DH) + h * DH + ch * 8];
        *(uint4*)&Ps[r * KP2 + ch * 4] = qv;
    }
    __syncthreads();
    uint32_t qf[4][4];
#pragma unroll
    for (int ks = 0; ks < 4; ks++) {
        const int kk2 = ks * 8;
        qf[ks][0] = Ps[(wm + g)     * KP2 + kk2 + t];
        qf[ks][1] = Ps[(wm + g + 8) * KP2 + kk2 + t];
        qf[ks][2] = Ps[(wm + g)     * KP2 + kk2 + t + 4];
        qf[ks][3] = Ps[(wm + g + 8) * KP2 + kk2 + t + 4];
    }

    float mr0 = -1e30f, mr1 = -1e30f, l0 = 0.f, l1 = 0.f;
    float o[8][4];
#pragma unroll
    for (int j = 0; j < 8; j++)
#pragma unroll
        for (int q = 0; q < 4; q++) o[j][q] = 0.f;

    const int ntiles = 2 * bx + 2;
    for (int jt = 0; jt < ntiles; jt++) {
        const int n0 = jt * 64;
        __syncthreads();   // prior readers of Ks/Vs done
        for (int e = tid; e < 64 * 8; e += 256) {
            int r = e >> 3, ch = e & 7;
            uint4 kv = *(const uint4*)&g_kh[(size_t)(n0 + r) * (NKV * DH) + kvh * DH + ch * 8];
            *(uint4*)&Ks[r * KP2 + ch * 4] = kv;
            uint4 vv = *(const uint4*)&g_vt[(size_t)(kvh * DH + r) * TT + n0 + ch * 8];
            *(uint4*)&Vs[r * KP2 + ch * 4] = vv;
        }
        __syncthreads();

        // S = Q @ K^T (log2-domain, pre-scaled)
        float s[8][4];
#pragma unroll
        for (int j = 0; j < 8; j++)
#pragma unroll
            for (int q = 0; q < 4; q++) s[j][q] = 0.f;
#pragma unroll
        for (int ks = 0; ks < 4; ks++) {
            const int kk2 = ks * 8;
#pragma unroll
            for (int nj = 0; nj < 8; nj++) {
                uint32_t b0 = Ks[(nj * 8 + g) * KP2 + kk2 + t];
                uint32_t b1 = Ks[(nj * 8 + g) * KP2 + kk2 + t + 4];
                mma_fp16(s[nj], qf[ks][0], qf[ks][1], qf[ks][2], qf[ks][3], b0, b1);
            }
        }

        // Causal mask
        if (jt >= 2 * bx) {
            const int r0 = m0 + wm + g, r1 = r0 + 8;
#pragma unroll
            for (int nj = 0; nj < 8; nj++) {
                int c0 = n0 + nj * 8 + 2 * t;
                if (c0     > r0) s[nj][0] = -1e30f;
                if (c0 + 1 > r0) s[nj][1] = -1e30f;
                if (c0     > r1) s[nj][2] = -1e30f;
                if (c0 + 1 > r1) s[nj][3] = -1e30f;
            }
        }

        // Register softmax, base 2
        float mx0 = -1e30f, mx1 = -1e30f;
#pragma unroll
        for (int nj = 0; nj < 8; nj++) {
            mx0 = fmaxf(mx0, fmaxf(s[nj][0], s[nj][1]));
            mx1 = fmaxf(mx1, fmaxf(s[nj][2], s[nj][3]));
        }
        mx0 = fmaxf(mx0, __shfl_xor_sync(0xffffffffu, mx0, 1));
        mx0 = fmaxf(mx0, __shfl_xor_sync(0xffffffffu, mx0, 2));
        mx1 = fmaxf(mx1, __shfl_xor_sync(0xffffffffu, mx1, 1));
        mx1 = fmaxf(mx1, __shfl_xor_sync(0xffffffffu, mx1, 2));
        float nm0 = fmaxf(mr0, mx0), nm1 = fmaxf(mr1, mx1);
        float f0 = exp2f(mr0 - nm0), f1 = exp2f(mr1 - nm1);
        float ps0 = 0.f, ps1 = 0.f;
#pragma unroll
        for (int nj = 0; nj < 8; nj++) {
            float p0 = exp2f(s[nj][0] - nm0);
            float p1 = exp2f(s[nj][1] - nm0);
            float p2 = exp2f(s[nj][2] - nm1);
            float p3 = exp2f(s[nj][3] - nm1);
            ps0 += p0 + p1; ps1 += p2 + p3;
            Ps[(wm + g)     * KP2 + nj * 4 + t] = pack_half2(p0, p1);
            Ps[(wm + g + 8) * KP2 + nj * 4 + t] = pack_half2(p2, p3);
        }
        ps0 += __shfl_xor_sync(0xffffffffu, ps0, 1);
        ps0 += __shfl_xor_sync(0xffffffffu, ps0, 2);
        ps1 += __shfl_xor_sync(0xffffffffu, ps1, 1);
        ps1 += __shfl_xor_sync(0xffffffffu, ps1, 2);
        l0 = l0 * f0 + ps0; l1 = l1 * f1 + ps1;
        mr0 = nm0; mr1 = nm1;
#pragma unroll
        for (int nj = 0; nj < 8; nj++) {
            o[nj][0] *= f0; o[nj][1] *= f0;
            o[nj][2] *= f1; o[nj][3] *= f1;
        }
        __syncwarp();   // P rows are warp-private

        // O += P @ V   (A = P[rows][keys], B = V^T[d][keys])
#pragma unroll
        for (int ks = 0; ks < 4; ks++) {
            const int kk2 = ks * 8;
            uint32_t a0 = Ps[(wm + g)     * KP2 + kk2 + t];
            uint32_t a1 = Ps[(wm + g + 8) * KP2 + kk2 + t];
            uint32_t a2 = Ps[(wm + g)     * KP2 + kk2 + t + 4];
            uint32_t a3 = Ps[(wm + g + 8) * KP2 + kk2 + t + 4];
#pragma unroll
            for (int nj = 0; nj < 8; nj++) {
                uint32_t b0 = Vs[(nj * 8 + g) * KP2 + kk2 + t];
                uint32_t b1 = Vs[(nj * 8 + g) * KP2 + kk2 + t + 4];
                mma_fp16(o[nj], a0, a1, a2, a3, b0, b1);
            }
        }
    }

    // Normalize and store
    float i0 = 1.f / l0, i1 = 1.f / l1;
#pragma unroll
    for (int nj = 0; nj < 8; nj++) {
        int c = nj * 8 + 2 * t;
        float* p0 = &g_att[(size_t)(m0 + wm + g)     * (NH * DH) + h * DH + c];
        float* p1 = &g_att[(size_t)(m0 + wm + g + 8) * (NH * DH) + h * DH + c];
        *(float2*)p0 = make_float2(o[nj][0] * i0, o[nj][1] * i0);
        *(float2*)p1 = make_float2(o[nj][2] * i1, o[nj][3] * i1);
    }
}

// ---------------------------------------------------------------------------
extern "C" void kernel_launch(void* const* d_in, const int* in_sizes, int n_in,
                              void* d_out, int out_size) {
    const float* x    = (const float*)d_in[0];
    const float* cosb = (const float*)d_in[1];
    const float* sinb = (const float*)d_in[2];
    const float* Wq   = (const float*)d_in[4];
    const float* Wk   = (const float*)d_in[5];
    const float* Wv   = (const float*)d_in[6];
    const float* Wo   = (const float*)d_in[7];
    float* out = (float*)d_out;

    float *q, *k, *v, *att;
    cudaGetSymbolAddress((void**)&q, g_q);
    cudaGetSymbolAddress((void**)&k, g_k);
    cudaGetSymbolAddress((void**)&v, g_v);
    cudaGetSymbolAddress((void**)&att, g_att);

    cudaFuncSetAttribute(qkv_gemm, cudaFuncAttributeMaxDynamicSharedMemorySize, GEMM_SMEM);
    cudaFuncSetAttribute(o_gemm,   cudaFuncAttributeMaxDynamicSharedMemorySize, GEMM_SMEM);

    qkv_gemm<<<dim3(24, 16), 256, GEMM_SMEM>>>(x, Wq, Wk, Wv, q, k, v);

    {
        int total = TT * (NH + NKV) * (DH / 2);
        rope_kernel<<<(total + 255) / 256, 256>>>(cosb, sinb);
    }
    vtrans_kernel<<<dim3(TT / 64, NKV), 256>>>();

    {
        const int smem = (2 * 64 * KP2 + 128 * KP2) * (int)sizeof(uint32_t);
        cudaFuncSetAttribute(attn_kernel, cudaFuncAttributeMaxDynamicSharedMemorySize, smem);
        attn_kernel<<<dim3(TT / 128, NH), 256, smem>>>();
    }

    o_gemm<<<dim3(16, 16), 256, GEMM_SMEM>>>(att, Wo, out);
}

// round 7
// speedup vs baseline: 10.9363x; 1.0411x over previous
#include <cuda_runtime.h>
#include <cuda_fp16.h>
#include <stdint.h>
#include <math.h>

#define TT   2048
#define HIDN 2048
#define NH   32
#define NKV  8
#define DH   64
#define GRP  4
#define QSCALE 0.1803368801111204f   // (1/8) * log2(e)

// fp32 intermediates from GEMMs
__device__ float g_q[TT * NH * DH];
__device__ float g_k[TT * NKV * DH];
__device__ float g_v[TT * NKV * DH];
__device__ float g_att[TT * NH * DH];
// half-precision attention operands
__device__ __half g_qh[TT * NH * DH];            // pre-scaled by QSCALE
__device__ __half g_kh[TT * NKV * DH];
__device__ __half g_vt[NKV * DH * TT];           // V transposed: [kvh][d][t]

__device__ __forceinline__ uint32_t pack_half2(float lo, float hi) {
    uint32_t r;
    asm("cvt.rn.f16x2.f32 %0, %1, %2;" : "=r"(r) : "f"(hi), "f"(lo));
    return r;
}

__device__ __forceinline__ void mma_fp16(float* c,
                                         uint32_t a0, uint32_t a1, uint32_t a2, uint32_t a3,
                                         uint32_t b0, uint32_t b1) {
    asm volatile(
        "mma.sync.aligned.m16n8k16.row.col.f32.f16.f16.f32 "
        "{%0,%1,%2,%3},{%4,%5,%6,%7},{%8,%9},{%0,%1,%2,%3};"
        : "+f"(c[0]), "+f"(c[1]), "+f"(c[2]), "+f"(c[3])
        : "r"(a0), "r"(a1), "r"(a2), "r"(a3), "r"(b0), "r"(b1));
}

// ---------------------------------------------------------------------------
// fp16 GEMM: C[row0:+128, col0:+128] = A[*,K] @ B[*,K]^T (fp32 in, fp32 out)
// 256 threads, 8 warps (2x4), warp tile 64x32, K-slab 32, double-buffered.
// ---------------------------------------------------------------------------
#define ST2 20
#define SLABH (128 * ST2)
#define GEMM_SMEM (4 * SLABH * (int)sizeof(uint32_t))

__device__ __forceinline__ void gemm_body(const float* __restrict__ A,
                                          const float* __restrict__ B,
                                          float* __restrict__ C,
                                          int N, int K, int row0, int col0,
                                          uint32_t* __restrict__ sm) {
    uint32_t* As = sm;
    uint32_t* Bs = sm + 2 * SLABH;

    const int tid = threadIdx.x;
    const int wid = tid >> 5, lane = tid & 31;
    const int g = lane >> 2, t = lane & 3;
    const int wm = (wid >> 2) * 64;
    const int wn = (wid & 3) * 32;

    const int rbase = tid >> 3;
    const int cc = tid & 7;
    const float* Ap = A + (size_t)(row0 + rbase) * K + cc * 4;
    const float* Bp = B + (size_t)(col0 + rbase) * K + cc * 4;

    float acc[4][4][4];
#pragma unroll
    for (int i = 0; i < 4; i++)
#pragma unroll
        for (int j = 0; j < 4; j++)
#pragma unroll
            for (int q = 0; q < 4; q++) acc[i][j][q] = 0.f;

    float4 pa[4], pb[4];
#pragma unroll
    for (int i = 0; i < 4; i++) {
        pa[i] = *(const float4*)(Ap + (size_t)i * 32 * K);
        pb[i] = *(const float4*)(Bp + (size_t)i * 32 * K);
    }
#pragma unroll
    for (int i = 0; i < 4; i++) {
        int r = rbase + 32 * i;
        uint2 av = make_uint2(pack_half2(pa[i].x, pa[i].y), pack_half2(pa[i].z, pa[i].w));
        uint2 bv = make_uint2(pack_half2(pb[i].x, pb[i].y), pack_half2(pb[i].z, pb[i].w));
        *(uint2*)&As[r * ST2 + cc * 2] = av;
        *(uint2*)&Bs[r * ST2 + cc * 2] = bv;
    }
    __syncthreads();

    for (int k0 = 0; k0 < K; k0 += 32) {
        const int st = (k0 >> 5) & 1;
        uint32_t* Ac = As + st * SLABH;
        uint32_t* Bc = Bs + st * SLABH;
        const bool more = (k0 + 32 < K);

        if (more) {
#pragma unroll
            for (int i = 0; i < 4; i++) {
                pa[i] = *(const float4*)(Ap + (size_t)i * 32 * K + k0 + 32);
                pb[i] = *(const float4*)(Bp + (size_t)i * 32 * K + k0 + 32);
            }
        }

#pragma unroll
        for (int ks = 0; ks < 2; ks++) {
            const int kk2 = ks * 8;
            uint32_t af[4][4], bf[4][2];
#pragma unroll
            for (int mi = 0; mi < 4; mi++) {
                int base = wm + mi * 16;
                af[mi][0] = Ac[(base + g)     * ST2 + kk2 + t];
                af[mi][1] = Ac[(base + g + 8) * ST2 + kk2 + t];
                af[mi][2] = Ac[(base + g)     * ST2 + kk2 + t + 4];
                af[mi][3] = Ac[(base + g + 8) * ST2 + kk2 + t + 4];
            }
#pragma unroll
            for (int nj = 0; nj < 4; nj++) {
                int nb = wn + nj * 8;
                bf[nj][0] = Bc[(nb + g) * ST2 + kk2 + t];
                bf[nj][1] = Bc[(nb + g) * ST2 + kk2 + t + 4];
            }
#pragma unroll
            for (int mi = 0; mi < 4; mi++)
#pragma unroll
                for (int nj = 0; nj < 4; nj++)
                    mma_fp16(acc[mi][nj], af[mi][0], af[mi][1], af[mi][2], af[mi][3],
                             bf[nj][0], bf[nj][1]);
        }

        if (more) {
            uint32_t* An = As + (st ^ 1) * SLABH;
            uint32_t* Bn = Bs + (st ^ 1) * SLABH;
#pragma unroll
            for (int i = 0; i < 4; i++) {
                int r = rbase + 32 * i;
                uint2 av = make_uint2(pack_half2(pa[i].x, pa[i].y), pack_half2(pa[i].z, pa[i].w));
                uint2 bv = make_uint2(pack_half2(pb[i].x, pb[i].y), pack_half2(pb[i].z, pb[i].w));
                *(uint2*)&An[r * ST2 + cc * 2] = av;
                *(uint2*)&Bn[r * ST2 + cc * 2] = bv;
            }
            __syncthreads();
        }
    }

#pragma unroll
    for (int mi = 0; mi < 4; mi++) {
#pragma unroll
        for (int nj = 0; nj < 4; nj++) {
            int r = row0 + wm + mi * 16 + g;
            int c = col0 + wn + nj * 8 + 2 * t;
            *(float2*)(C + (size_t)r * N + c)       = make_float2(acc[mi][nj][0], acc[mi][nj][1]);
            *(float2*)(C + (size_t)(r + 8) * N + c) = make_float2(acc[mi][nj][2], acc[mi][nj][3]);
        }
    }
}

__global__ void __launch_bounds__(256, 2) qkv_gemm(const float* __restrict__ x,
                                                   const float* __restrict__ Wq,
                                                   const float* __restrict__ Wk,
                                                   const float* __restrict__ Wv,
                                                   float* q, float* k, float* v) {
    extern __shared__ uint32_t sm[];
    int bx = blockIdx.x;
    int row0 = blockIdx.y * 128;
    if (bx < 16)      gemm_body(x, Wq, q, NH * DH,  HIDN, row0, bx * 128,        sm);
    else if (bx < 20) gemm_body(x, Wk, k, NKV * DH, HIDN, row0, (bx - 16) * 128, sm);
    else              gemm_body(x, Wv, v, NKV * DH, HIDN, row0, (bx - 20) * 128, sm);
}

__global__ void __launch_bounds__(256, 2) o_gemm(const float* __restrict__ A,
                                                 const float* __restrict__ Wo,
                                                 float* __restrict__ C) {
    extern __shared__ uint32_t sm[];
    gemm_body(A, Wo, C, HIDN, NH * DH, blockIdx.y * 128, blockIdx.x * 128, sm);
}

// ---------------------------------------------------------------------------
// RoPE: read fp32 q/k, write half q (pre-scaled by QSCALE) and half k.
// ---------------------------------------------------------------------------
__global__ void rope_kernel(const float* __restrict__ cosb,
                            const float* __restrict__ sinb) {
    int idx = blockIdx.x * blockDim.x + threadIdx.x;
    const int total = TT * (NH + NKV) * (DH / 2);
    if (idx >= total) return;
    int d = idx & 31;
    int r = idx >> 5;
    int head = r % (NH + NKV);
    int t = r / (NH + NKV);
    float c = cosb[t * DH + d];
    float s = sinb[t * DH + d];
    if (head < NH) {
        int off = (t * NH + head) * DH;
        float x1 = g_q[off + d], x2 = g_q[off + d + 32];
        g_qh[off + d]      = __float2half((x1 * c - x2 * s) * QSCALE);
        g_qh[off + d + 32] = __float2half((x2 * c + x1 * s) * QSCALE);
    } else {
        int off = (t * NKV + (head - NH)) * DH;
        float x1 = g_k[off + d], x2 = g_k[off + d + 32];
        g_kh[off + d]      = __float2half(x1 * c - x2 * s);
        g_kh[off + d + 32] = __float2half(x2 * c + x1 * s);
    }
}

// ---------------------------------------------------------------------------
// V transpose: g_v fp32 [t][kvh][d] -> g_vt half [kvh][d][t]
// ---------------------------------------------------------------------------
__global__ void __launch_bounds__(256) vtrans_kernel() {
    __shared__ float sm[64][65];
    const int tid = threadIdx.x;
    const int t0 = blockIdx.x * 64;
    const int kvh = blockIdx.y;
    for (int e = tid; e < 64 * 16; e += 256) {
        int r = e >> 4, c4 = (e & 15) * 4;
        float4 v = *(const float4*)&g_v[(size_t)(t0 + r) * (NKV * DH) + kvh * DH + c4];
        sm[r][c4] = v.x; sm[r][c4 + 1] = v.y; sm[r][c4 + 2] = v.z; sm[r][c4 + 3] = v.w;
    }
    __syncthreads();
    for (int e = tid; e < 64 * 8; e += 256) {
        int d = e >> 3, ch = e & 7;
        int kb = ch * 8;
        uint4 o;
        o.x = pack_half2(sm[kb + 0][d], sm[kb + 1][d]);
        o.y = pack_half2(sm[kb + 2][d], sm[kb + 3][d]);
        o.z = pack_half2(sm[kb + 4][d], sm[kb + 5][d]);
        o.w = pack_half2(sm[kb + 6][d], sm[kb + 7][d]);
        *(uint4*)&g_vt[(size_t)(kvh * DH + d) * TT + t0 + kb] = o;
    }
}

// ---------------------------------------------------------------------------
// Flash attention, fp16 MMA, register-resident P (accumulator->A-operand
// fragment identity), Q fragments from gmem. 128 q-rows x 1 head per block,
// 256 threads = 8 warps.
// ---------------------------------------------------------------------------
#define KP2 36   // half2 stride for 64-half rows

__global__ void __launch_bounds__(256) attn_kernel() {
    __shared__ uint32_t Ks[64 * KP2];   // [key][d] half2
    __shared__ uint32_t Vs[64 * KP2];   // [d][key] half2 (V^T)

    const int tid = threadIdx.x;
    const int wid = tid >> 5, lane = tid & 31;
    const int g = lane >> 2, t = lane & 3;
    const int wm = wid * 16;
    const int h = blockIdx.y;
    const int kvh = h / GRP;
    const int bx = gridDim.x - 1 - blockIdx.x;   // heavy CTAs first
    const int m0 = bx * 128;

    // Q fragments straight from gmem (half, pre-scaled). r0/r1 = frag rows.
    const int r0 = m0 + wm + g, r1 = r0 + 8;
    uint32_t qf[4][4];
    {
        const __half* q0 = &g_qh[(size_t)r0 * (NH * DH) + h * DH];
        const __half* q1 = &g_qh[(size_t)r1 * (NH * DH) + h * DH];
#pragma unroll
        for (int ks = 0; ks < 4; ks++) {
            qf[ks][0] = *(const uint32_t*)(q0 + ks * 16 + 2 * t);
            qf[ks][1] = *(const uint32_t*)(q1 + ks * 16 + 2 * t);
            qf[ks][2] = *(const uint32_t*)(q0 + ks * 16 + 8 + 2 * t);
            qf[ks][3] = *(const uint32_t*)(q1 + ks * 16 + 8 + 2 * t);
        }
    }

    float mr0 = -1e30f, mr1 = -1e30f, l0 = 0.f, l1 = 0.f;
    float o[8][4];
#pragma unroll
    for (int j = 0; j < 8; j++)
#pragma unroll
        for (int q = 0; q < 4; q++) o[j][q] = 0.f;

    const int ntiles = 2 * bx + 2;
    for (int jt = 0; jt < ntiles; jt++) {
        const int n0 = jt * 64;
        __syncthreads();   // prior readers of Ks/Vs done
        for (int e = tid; e < 64 * 8; e += 256) {
            int r = e >> 3, ch = e & 7;
            uint4 kv = *(const uint4*)&g_kh[(size_t)(n0 + r) * (NKV * DH) + kvh * DH + ch * 8];
            *(uint4*)&Ks[r * KP2 + ch * 4] = kv;
            uint4 vv = *(const uint4*)&g_vt[(size_t)(kvh * DH + r) * TT + n0 + ch * 8];
            *(uint4*)&Vs[r * KP2 + ch * 4] = vv;
        }
        __syncthreads();

        // S = Q @ K^T (log2-domain, pre-scaled)
        float s[8][4];
#pragma unroll
        for (int j = 0; j < 8; j++)
#pragma unroll
            for (int q = 0; q < 4; q++) s[j][q] = 0.f;
#pragma unroll
        for (int ks = 0; ks < 4; ks++) {
            const int kk2 = ks * 8;
#pragma unroll
            for (int nj = 0; nj < 8; nj++) {
                uint32_t b0 = Ks[(nj * 8 + g) * KP2 + kk2 + t];
                uint32_t b1 = Ks[(nj * 8 + g) * KP2 + kk2 + t + 4];
                mma_fp16(s[nj], qf[ks][0], qf[ks][1], qf[ks][2], qf[ks][3], b0, b1);
            }
        }

        // Causal mask
        if (jt >= 2 * bx) {
#pragma unroll
            for (int nj = 0; nj < 8; nj++) {
                int c0 = n0 + nj * 8 + 2 * t;
                if (c0     > r0) s[nj][0] = -1e30f;
                if (c0 + 1 > r0) s[nj][1] = -1e30f;
                if (c0     > r1) s[nj][2] = -1e30f;
                if (c0 + 1 > r1) s[nj][3] = -1e30f;
            }
        }

        // Register softmax, base 2; P stays in registers.
        float mx0 = -1e30f, mx1 = -1e30f;
#pragma unroll
        for (int nj = 0; nj < 8; nj++) {
            mx0 = fmaxf(mx0, fmaxf(s[nj][0], s[nj][1]));
            mx1 = fmaxf(mx1, fmaxf(s[nj][2], s[nj][3]));
        }
        mx0 = fmaxf(mx0, __shfl_xor_sync(0xffffffffu, mx0, 1));
        mx0 = fmaxf(mx0, __shfl_xor_sync(0xffffffffu, mx0, 2));
        mx1 = fmaxf(mx1, __shfl_xor_sync(0xffffffffu, mx1, 1));
        mx1 = fmaxf(mx1, __shfl_xor_sync(0xffffffffu, mx1, 2));
        float nm0 = fmaxf(mr0, mx0), nm1 = fmaxf(mr1, mx1);
        float f0 = exp2f(mr0 - nm0), f1 = exp2f(mr1 - nm1);
        float ps0 = 0.f, ps1 = 0.f;
#pragma unroll
        for (int nj = 0; nj < 8; nj++) {
            s[nj][0] = exp2f(s[nj][0] - nm0);
            s[nj][1] = exp2f(s[nj][1] - nm0);
            s[nj][2] = exp2f(s[nj][2] - nm1);
            s[nj][3] = exp2f(s[nj][3] - nm1);
            ps0 += s[nj][0] + s[nj][1];
            ps1 += s[nj][2] + s[nj][3];
        }
        ps0 += __shfl_xor_sync(0xffffffffu, ps0, 1);
        ps0 += __shfl_xor_sync(0xffffffffu, ps0, 2);
        ps1 += __shfl_xor_sync(0xffffffffu, ps1, 1);
        ps1 += __shfl_xor_sync(0xffffffffu, ps1, 2);
        l0 = l0 * f0 + ps0; l1 = l1 * f1 + ps1;
        mr0 = nm0; mr1 = nm1;
#pragma unroll
        for (int nj = 0; nj < 8; nj++) {
            o[nj][0] *= f0; o[nj][1] *= f0;
            o[nj][2] *= f1; o[nj][3] *= f1;
        }

        // O += P @ V. P accumulator fragments ARE the A-operand fragments:
        // a0 = P[g][ks*16+2t,+1]   = pack(s[2ks][0],   s[2ks][1])
        // a1 = P[g+8][ks*16+2t,+1] = pack(s[2ks][2],   s[2ks][3])
        // a2 = P[g][ks*16+8+2t,+1] = pack(s[2ks+1][0], s[2ks+1][1])
        // a3 = P[g+8][...]         = pack(s[2ks+1][2], s[2ks+1][3])
#pragma unroll
        for (int ks = 0; ks < 4; ks++) {
            uint32_t a0 = pack_half2(s[2 * ks][0],     s[2 * ks][1]);
            uint32_t a1 = pack_half2(s[2 * ks][2],     s[2 * ks][3]);
            uint32_t a2 = pack_half2(s[2 * ks + 1][0], s[2 * ks + 1][1]);
            uint32_t a3 = pack_half2(s[2 * ks + 1][2], s[2 * ks + 1][3]);
            const int kk2 = ks * 8;
#pragma unroll
            for (int nj = 0; nj < 8; nj++) {
                uint32_t b0 = Vs[(nj * 8 + g) * KP2 + kk2 + t];
                uint32_t b1 = Vs[(nj * 8 + g) * KP2 + kk2 + t + 4];
                mma_fp16(o[nj], a0, a1, a2, a3, b0, b1);
            }
        }
    }

    // Normalize and store
    float i0 = 1.f / l0, i1 = 1.f / l1;
#pragma unroll
    for (int nj = 0; nj < 8; nj++) {
        int c = nj * 8 + 2 * t;
        float* p0 = &g_att[(size_t)r0 * (NH * DH) + h * DH + c];
        float* p1 = &g_att[(size_t)r1 * (NH * DH) + h * DH + c];
        *(float2*)p0 = make_float2(o[nj][0] * i0, o[nj][1] * i0);
        *(float2*)p1 = make_float2(o[nj][2] * i1, o[nj][3] * i1);
    }
}

// ---------------------------------------------------------------------------
extern "C" void kernel_launch(void* const* d_in, const int* in_sizes, int n_in,
                              void* d_out, int out_size) {
    const float* x    = (const float*)d_in[0];
    const float* cosb = (const float*)d_in[1];
    const float* sinb = (const float*)d_in[2];
    const float* Wq   = (const float*)d_in[4];
    const float* Wk   = (const float*)d_in[5];
    const float* Wv   = (const float*)d_in[6];
    const float* Wo   = (const float*)d_in[7];
    float* out = (float*)d_out;

    float *q, *k, *v, *att;
    cudaGetSymbolAddress((void**)&q, g_q);
    cudaGetSymbolAddress((void**)&k, g_k);
    cudaGetSymbolAddress((void**)&v, g_v);
    cudaGetSymbolAddress((void**)&att, g_att);

    cudaFuncSetAttribute(qkv_gemm, cudaFuncAttributeMaxDynamicSharedMemorySize, GEMM_SMEM);
    cudaFuncSetAttribute(o_gemm,   cudaFuncAttributeMaxDynamicSharedMemorySize, GEMM_SMEM);

    qkv_gemm<<<dim3(24, 16), 256, GEMM_SMEM>>>(x, Wq, Wk, Wv, q, k, v);

    {
        int total = TT * (NH + NKV) * (DH / 2);
        rope_kernel<<<(total + 255) / 256, 256>>>(cosb, sinb);
    }
    vtrans_kernel<<<dim3(TT / 64, NKV), 256>>>();

    attn_kernel<<<dim3(TT / 128, NH), 256>>>();

    o_gemm<<<dim3(16, 16), 256, GEMM_SMEM>>>(att, Wo, out);
}

// round 8
// speedup vs baseline: 11.6218x; 1.0627x over previous
#include <cuda_runtime.h>
#include <cuda_fp16.h>
#include <stdint.h>
#include <math.h>

#define TT   2048
#define HIDN 2048
#define NH   32
#define NKV  8
#define DH   64
#define GRP  4
#define QSCALE 0.1803368801111204f   // (1/8) * log2(e)

// fp32 intermediates from GEMMs
__device__ float g_q[TT * NH * DH];
__device__ float g_k[TT * NKV * DH];
__device__ float g_v[TT * NKV * DH];
__device__ float g_att[TT * NH * DH];
// half-precision attention operands
__device__ __half g_qh[TT * NH * DH];            // pre-scaled by QSCALE
__device__ __half g_kh[TT * NKV * DH];
__device__ __half g_vt[NKV * DH * TT];           // V transposed: [kvh][d][t]

__device__ __forceinline__ uint32_t pack_half2(float lo, float hi) {
    uint32_t r;
    asm("cvt.rn.f16x2.f32 %0, %1, %2;" : "=r"(r) : "f"(hi), "f"(lo));
    return r;
}

__device__ __forceinline__ void mma_fp16(float* c,
                                         uint32_t a0, uint32_t a1, uint32_t a2, uint32_t a3,
                                         uint32_t b0, uint32_t b1) {
    asm volatile(
        "mma.sync.aligned.m16n8k16.row.col.f32.f16.f16.f32 "
        "{%0,%1,%2,%3},{%4,%5,%6,%7},{%8,%9},{%0,%1,%2,%3};"
        : "+f"(c[0]), "+f"(c[1]), "+f"(c[2]), "+f"(c[3])
        : "r"(a0), "r"(a1), "r"(a2), "r"(a3), "r"(b0), "r"(b1));
}

__device__ __forceinline__ void ldsm4(uint32_t& r0, uint32_t& r1,
                                      uint32_t& r2, uint32_t& r3, uint32_t addr) {
    asm volatile("ldmatrix.sync.aligned.m8n8.x4.shared.b16 {%0,%1,%2,%3}, [%4];"
                 : "=r"(r0), "=r"(r1), "=r"(r2), "=r"(r3) : "r"(addr));
}

// ---------------------------------------------------------------------------
// fp16 GEMM: C[row0:+128, col0:+128] = A[*,K] @ B[*,K]^T (fp32 in, fp32 out)
// 256 threads, 8 warps (2x4), warp tile 64x32, K-slab 32, double-buffered,
// ldmatrix fragment loads.
// ---------------------------------------------------------------------------
#define ST2 20
#define SLABH (128 * ST2)
#define GEMM_SMEM (4 * SLABH * (int)sizeof(uint32_t))

__device__ __forceinline__ void gemm_body(const float* __restrict__ A,
                                          const float* __restrict__ B,
                                          float* __restrict__ C,
                                          int N, int K, int row0, int col0,
                                          uint32_t* __restrict__ sm) {
    const int tid = threadIdx.x;
    const int wid = tid >> 5, lane = tid & 31;
    const int g = lane >> 2, t = lane & 3;
    const int wm = (wid >> 2) * 64;
    const int wn = (wid & 3) * 32;

    // ldmatrix lane->row/col mapping.
    // A x4: m0=(r, kk), m1=(r+8, kk), m2=(r, kk+4), m3=(r+8, kk+4)
    const int rA = ((lane >> 3) & 1) * 8 + (lane & 7);
    const int cA = ((lane >> 4) & 1) * 4;
    // B x4: m0=(nj, b0), m1=(nj, b1), m2=(nj+1, b0), m3=(nj+1, b1)
    const int rB = ((lane >> 4) & 1) * 8 + (lane & 7);
    const int cB = ((lane >> 3) & 1) * 4;

    const uint32_t smb = (uint32_t)__cvta_generic_to_shared(sm);

    const int rbase = tid >> 3;
    const int cc = tid & 7;
    const float* Ap = A + (size_t)(row0 + rbase) * K + cc * 4;
    const float* Bp = B + (size_t)(col0 + rbase) * K + cc * 4;

    float acc[4][4][4];
#pragma unroll
    for (int i = 0; i < 4; i++)
#pragma unroll
        for (int j = 0; j < 4; j++)
#pragma unroll
            for (int q = 0; q < 4; q++) acc[i][j][q] = 0.f;

    uint32_t* As = sm;
    uint32_t* Bs = sm + 2 * SLABH;

    float4 pa[4], pb[4];
#pragma unroll
    for (int i = 0; i < 4; i++) {
        pa[i] = *(const float4*)(Ap + (size_t)i * 32 * K);
        pb[i] = *(const float4*)(Bp + (size_t)i * 32 * K);
    }
#pragma unroll
    for (int i = 0; i < 4; i++) {
        int r = rbase + 32 * i;
        uint2 av = make_uint2(pack_half2(pa[i].x, pa[i].y), pack_half2(pa[i].z, pa[i].w));
        uint2 bv = make_uint2(pack_half2(pb[i].x, pb[i].y), pack_half2(pb[i].z, pb[i].w));
        *(uint2*)&As[r * ST2 + cc * 2] = av;
        *(uint2*)&Bs[r * ST2 + cc * 2] = bv;
    }
    __syncthreads();

    for (int k0 = 0; k0 < K; k0 += 32) {
        const int st = (k0 >> 5) & 1;
        const uint32_t Ab = smb + (uint32_t)st * SLABH * 4u;
        const uint32_t Bb = smb + (uint32_t)(2 + st) * SLABH * 4u;
        const bool more = (k0 + 32 < K);

        if (more) {
#pragma unroll
            for (int i = 0; i < 4; i++) {
                pa[i] = *(const float4*)(Ap + (size_t)i * 32 * K + k0 + 32);
                pb[i] = *(const float4*)(Bp + (size_t)i * 32 * K + k0 + 32);
            }
        }

#pragma unroll
        for (int ks = 0; ks < 2; ks++) {
            const int kk2 = ks * 8;
            uint32_t af[4][4], bf[4][2];
#pragma unroll
            for (int mi = 0; mi < 4; mi++) {
                uint32_t addr = Ab + (uint32_t)(((wm + mi * 16 + rA) * ST2 + kk2 + cA) * 4);
                ldsm4(af[mi][0], af[mi][1], af[mi][2], af[mi][3], addr);
            }
#pragma unroll
            for (int njp = 0; njp < 2; njp++) {
                uint32_t addr = Bb + (uint32_t)(((wn + njp * 16 + rB) * ST2 + kk2 + cB) * 4);
                ldsm4(bf[2 * njp][0], bf[2 * njp][1], bf[2 * njp + 1][0], bf[2 * njp + 1][1], addr);
            }
#pragma unroll
            for (int mi = 0; mi < 4; mi++)
#pragma unroll
                for (int nj = 0; nj < 4; nj++)
                    mma_fp16(acc[mi][nj], af[mi][0], af[mi][1], af[mi][2], af[mi][3],
                             bf[nj][0], bf[nj][1]);
        }

        if (more) {
            uint32_t* An = As + (st ^ 1) * SLABH;
            uint32_t* Bn = Bs + (st ^ 1) * SLABH;
#pragma unroll
            for (int i = 0; i < 4; i++) {
                int r = rbase + 32 * i;
                uint2 av = make_uint2(pack_half2(pa[i].x, pa[i].y), pack_half2(pa[i].z, pa[i].w));
                uint2 bv = make_uint2(pack_half2(pb[i].x, pb[i].y), pack_half2(pb[i].z, pb[i].w));
                *(uint2*)&An[r * ST2 + cc * 2] = av;
                *(uint2*)&Bn[r * ST2 + cc * 2] = bv;
            }
            __syncthreads();
        }
    }

#pragma unroll
    for (int mi = 0; mi < 4; mi++) {
#pragma unroll
        for (int nj = 0; nj < 4; nj++) {
            int r = row0 + wm + mi * 16 + g;
            int c = col0 + wn + nj * 8 + 2 * t;
            *(float2*)(C + (size_t)r * N + c)       = make_float2(acc[mi][nj][0], acc[mi][nj][1]);
            *(float2*)(C + (size_t)(r + 8) * N + c) = make_float2(acc[mi][nj][2], acc[mi][nj][3]);
        }
    }
}

__global__ void __launch_bounds__(256, 2) qkv_gemm(const float* __restrict__ x,
                                                   const float* __restrict__ Wq,
                                                   const float* __restrict__ Wk,
                                                   const float* __restrict__ Wv,
                                                   float* q, float* k, float* v) {
    extern __shared__ uint32_t sm[];
    int bx = blockIdx.x;
    int row0 = blockIdx.y * 128;
    if (bx < 16)      gemm_body(x, Wq, q, NH * DH,  HIDN, row0, bx * 128,        sm);
    else if (bx < 20) gemm_body(x, Wk, k, NKV * DH, HIDN, row0, (bx - 16) * 128, sm);
    else              gemm_body(x, Wv, v, NKV * DH, HIDN, row0, (bx - 20) * 128, sm);
}

__global__ void __launch_bounds__(256, 2) o_gemm(const float* __restrict__ A,
                                                 const float* __restrict__ Wo,
                                                 float* __restrict__ C) {
    extern __shared__ uint32_t sm[];
    gemm_body(A, Wo, C, HIDN, NH * DH, blockIdx.y * 128, blockIdx.x * 128, sm);
}

// ---------------------------------------------------------------------------
// RoPE: read fp32 q/k, write half q (pre-scaled by QSCALE) and half k.
// ---------------------------------------------------------------------------
__global__ void rope_kernel(const float* __restrict__ cosb,
                            const float* __restrict__ sinb) {
    int idx = blockIdx.x * blockDim.x + threadIdx.x;
    const int total = TT * (NH + NKV) * (DH / 2);
    if (idx >= total) return;
    int d = idx & 31;
    int r = idx >> 5;
    int head = r % (NH + NKV);
    int t = r / (NH + NKV);
    float c = cosb[t * DH + d];
    float s = sinb[t * DH + d];
    if (head < NH) {
        int off = (t * NH + head) * DH;
        float x1 = g_q[off + d], x2 = g_q[off + d + 32];
        g_qh[off + d]      = __float2half((x1 * c - x2 * s) * QSCALE);
        g_qh[off + d + 32] = __float2half((x2 * c + x1 * s) * QSCALE);
    } else {
        int off = (t * NKV + (head - NH)) * DH;
        float x1 = g_k[off + d], x2 = g_k[off + d + 32];
        g_kh[off + d]      = __float2half(x1 * c - x2 * s);
        g_kh[off + d + 32] = __float2half(x2 * c + x1 * s);
    }
}

// ---------------------------------------------------------------------------
// V transpose: g_v fp32 [t][kvh][d] -> g_vt half [kvh][d][t]
// ---------------------------------------------------------------------------
__global__ void __launch_bounds__(256) vtrans_kernel() {
    __shared__ float sm[64][65];
    const int tid = threadIdx.x;
    const int t0 = blockIdx.x * 64;
    const int kvh = blockIdx.y;
    for (int e = tid; e < 64 * 16; e += 256) {
        int r = e >> 4, c4 = (e & 15) * 4;
        float4 v = *(const float4*)&g_v[(size_t)(t0 + r) * (NKV * DH) + kvh * DH + c4];
        sm[r][c4] = v.x; sm[r][c4 + 1] = v.y; sm[r][c4 + 2] = v.z; sm[r][c4 + 3] = v.w;
    }
    __syncthreads();
    for (int e = tid; e < 64 * 8; e += 256) {
        int d = e >> 3, ch = e & 7;
        int kb = ch * 8;
        uint4 o;
        o.x = pack_half2(sm[kb + 0][d], sm[kb + 1][d]);
        o.y = pack_half2(sm[kb + 2][d], sm[kb + 3][d]);
        o.z = pack_half2(sm[kb + 4][d], sm[kb + 5][d]);
        o.w = pack_half2(sm[kb + 6][d], sm[kb + 7][d]);
        *(uint4*)&g_vt[(size_t)(kvh * DH + d) * TT + t0 + kb] = o;
    }
}

// ---------------------------------------------------------------------------
// Flash attention, fp16 MMA, register-resident P, ldmatrix fragment loads.
// 128 q-rows x 1 head per block, 256 threads = 8 warps.
// ---------------------------------------------------------------------------
#define KP2 36   // half2 stride for 64-half rows

__global__ void __launch_bounds__(256) attn_kernel() {
    __shared__ uint32_t Ks[64 * KP2];   // [key][d] half2
    __shared__ uint32_t Vs[64 * KP2];   // [d][key] half2 (V^T)

    const int tid = threadIdx.x;
    const int wid = tid >> 5, lane = tid & 31;
    const int g = lane >> 2, t = lane & 3;
    const int wm = wid * 16;
    const int h = blockIdx.y;
    const int kvh = h / GRP;
    const int bx = gridDim.x - 1 - blockIdx.x;   // heavy CTAs first
    const int m0 = bx * 128;

    // ldmatrix B mapping: m0=(nj,b0), m1=(nj,b1), m2=(nj+1,b0), m3=(nj+1,b1)
    const int rB = ((lane >> 4) & 1) * 8 + (lane & 7);
    const int cB = ((lane >> 3) & 1) * 4;
    const uint32_t ksb = (uint32_t)__cvta_generic_to_shared(Ks);
    const uint32_t vsb = (uint32_t)__cvta_generic_to_shared(Vs);

    // Q fragments straight from gmem (half, pre-scaled). r0/r1 = frag rows.
    const int r0 = m0 + wm + g, r1 = r0 + 8;
    uint32_t qf[4][4];
    {
        const __half* q0 = &g_qh[(size_t)r0 * (NH * DH) + h * DH];
        const __half* q1 = &g_qh[(size_t)r1 * (NH * DH) + h * DH];
#pragma unroll
        for (int ks = 0; ks < 4; ks++) {
            qf[ks][0] = *(const uint32_t*)(q0 + ks * 16 + 2 * t);
            qf[ks][1] = *(const uint32_t*)(q1 + ks * 16 + 2 * t);
            qf[ks][2] = *(const uint32_t*)(q0 + ks * 16 + 8 + 2 * t);
            qf[ks][3] = *(const uint32_t*)(q1 + ks * 16 + 8 + 2 * t);
        }
    }

    float mr0 = -1e30f, mr1 = -1e30f, l0 = 0.f, l1 = 0.f;
    float o[8][4];
#pragma unroll
    for (int j = 0; j < 8; j++)
#pragma unroll
        for (int q = 0; q < 4; q++) o[j][q] = 0.f;

    const int ntiles = 2 * bx + 2;
    for (int jt = 0; jt < ntiles; jt++) {
        const int n0 = jt * 64;
        __syncthreads();   // prior readers of Ks/Vs done
        for (int e = tid; e < 64 * 8; e += 256) {
            int r = e >> 3, ch = e & 7;
            uint4 kv = *(const uint4*)&g_kh[(size_t)(n0 + r) * (NKV * DH) + kvh * DH + ch * 8];
            *(uint4*)&Ks[r * KP2 + ch * 4] = kv;
            uint4 vv = *(const uint4*)&g_vt[(size_t)(kvh * DH + r) * TT + n0 + ch * 8];
            *(uint4*)&Vs[r * KP2 + ch * 4] = vv;
        }
        __syncthreads();

        // S = Q @ K^T (log2-domain, pre-scaled)
        float s[8][4];
#pragma unroll
        for (int j = 0; j < 8; j++)
#pragma unroll
            for (int q = 0; q < 4; q++) s[j][q] = 0.f;
#pragma unroll
        for (int ks = 0; ks < 4; ks++) {
            const int kk2 = ks * 8;
#pragma unroll
            for (int njp = 0; njp < 4; njp++) {
                uint32_t b0, b1, b2, b3;
                uint32_t addr = ksb + (uint32_t)(((njp * 16 + rB) * KP2 + kk2 + cB) * 4);
                ldsm4(b0, b1, b2, b3, addr);
                mma_fp16(s[2 * njp],     qf[ks][0], qf[ks][1], qf[ks][2], qf[ks][3], b0, b1);
                mma_fp16(s[2 * njp + 1], qf[ks][0], qf[ks][1], qf[ks][2], qf[ks][3], b2, b3);
            }
        }

        // Causal mask
        if (jt >= 2 * bx) {
#pragma unroll
            for (int nj = 0; nj < 8; nj++) {
                int c0 = n0 + nj * 8 + 2 * t;
                if (c0     > r0) s[nj][0] = -1e30f;
                if (c0 + 1 > r0) s[nj][1] = -1e30f;
                if (c0     > r1) s[nj][2] = -1e30f;
                if (c0 + 1 > r1) s[nj][3] = -1e30f;
            }
        }

        // Register softmax, base 2; P stays in registers.
        float mx0 = -1e30f, mx1 = -1e30f;
#pragma unroll
        for (int nj = 0; nj < 8; nj++) {
            mx0 = fmaxf(mx0, fmaxf(s[nj][0], s[nj][1]));
            mx1 = fmaxf(mx1, fmaxf(s[nj][2], s[nj][3]));
        }
        mx0 = fmaxf(mx0, __shfl_xor_sync(0xffffffffu, mx0, 1));
        mx0 = fmaxf(mx0, __shfl_xor_sync(0xffffffffu, mx0, 2));
        mx1 = fmaxf(mx1, __shfl_xor_sync(0xffffffffu, mx1, 1));
        mx1 = fmaxf(mx1, __shfl_xor_sync(0xffffffffu, mx1, 2));
        float nm0 = fmaxf(mr0, mx0), nm1 = fmaxf(mr1, mx1);
        float f0 = exp2f(mr0 - nm0), f1 = exp2f(mr1 - nm1);
        float ps0 = 0.f, ps1 = 0.f;
#pragma unroll
        for (int nj = 0; nj < 8; nj++) {
            s[nj][0] = exp2f(s[nj][0] - nm0);
            s[nj][1] = exp2f(s[nj][1] - nm0);
            s[nj][2] = exp2f(s[nj][2] - nm1);
            s[nj][3] = exp2f(s[nj][3] - nm1);
            ps0 += s[nj][0] + s[nj][1];
            ps1 += s[nj][2] + s[nj][3];
        }
        ps0 += __shfl_xor_sync(0xffffffffu, ps0, 1);
        ps0 += __shfl_xor_sync(0xffffffffu, ps0, 2);
        ps1 += __shfl_xor_sync(0xffffffffu, ps1, 1);
        ps1 += __shfl_xor_sync(0xffffffffu, ps1, 2);
        l0 = l0 * f0 + ps0; l1 = l1 * f1 + ps1;
        mr0 = nm0; mr1 = nm1;
#pragma unroll
        for (int nj = 0; nj < 8; nj++) {
            o[nj][0] *= f0; o[nj][1] *= f0;
            o[nj][2] *= f1; o[nj][3] *= f1;
        }

        // O += P @ V. P accumulator fragments ARE the A-operand fragments.
#pragma unroll
        for (int ks = 0; ks < 4; ks++) {
            uint32_t a0 = pack_half2(s[2 * ks][0],     s[2 * ks][1]);
            uint32_t a1 = pack_half2(s[2 * ks][2],     s[2 * ks][3]);
            uint32_t a2 = pack_half2(s[2 * ks + 1][0], s[2 * ks + 1][1]);
            uint32_t a3 = pack_half2(s[2 * ks + 1][2], s[2 * ks + 1][3]);
            const int kk2 = ks * 8;
#pragma unroll
            for (int njp = 0; njp < 4; njp++) {
                uint32_t b0, b1, b2, b3;
                uint32_t addr = vsb + (uint32_t)(((njp * 16 + rB) * KP2 + kk2 + cB) * 4);
                ldsm4(b0, b1, b2, b3, addr);
                mma_fp16(o[2 * njp],     a0, a1, a2, a3, b0, b1);
                mma_fp16(o[2 * njp + 1], a0, a1, a2, a3, b2, b3);
            }
        }
    }

    // Normalize and store
    float i0 = 1.f / l0, i1 = 1.f / l1;
#pragma unroll
    for (int nj = 0; nj < 8; nj++) {
        int c = nj * 8 + 2 * t;
        float* p0 = &g_att[(size_t)r0 * (NH * DH) + h * DH + c];
        float* p1 = &g_att[(size_t)r1 * (NH * DH) + h * DH + c];
        *(float2*)p0 = make_float2(o[nj][0] * i0, o[nj][1] * i0);
        *(float2*)p1 = make_float2(o[nj][2] * i1, o[nj][3] * i1);
    }
}

// ---------------------------------------------------------------------------
extern "C" void kernel_launch(void* const* d_in, const int* in_sizes, int n_in,
                              void* d_out, int out_size) {
    const float* x    = (const float*)d_in[0];
    const float* cosb = (const float*)d_in[1];
    const float* sinb = (const float*)d_in[2];
    const float* Wq   = (const float*)d_in[4];
    const float* Wk   = (const float*)d_in[5];
    const float* Wv   = (const float*)d_in[6];
    const float* Wo   = (const float*)d_in[7];
    float* out = (float*)d_out;

    float *q, *k, *v, *att;
    cudaGetSymbolAddress((void**)&q, g_q);
    cudaGetSymbolAddress((void**)&k, g_k);
    cudaGetSymbolAddress((void**)&v, g_v);
    cudaGetSymbolAddress((void**)&att, g_att);

    cudaFuncSetAttribute(qkv_gemm, cudaFuncAttributeMaxDynamicSharedMemorySize, GEMM_SMEM);
    cudaFuncSetAttribute(o_gemm,   cudaFuncAttributeMaxDynamicSharedMemorySize, GEMM_SMEM);

    qkv_gemm<<<dim3(24, 16), 256, GEMM_SMEM>>>(x, Wq, Wk, Wv, q, k, v);

    {
        int total = TT * (NH + NKV) * (DH / 2);
        rope_kernel<<<(total + 255) / 256, 256>>>(cosb, sinb);
    }
    vtrans_kernel<<<dim3(TT / 64, NKV), 256>>>();

    attn_kernel<<<dim3(TT / 128, NH), 256>>>();

    o_gemm<<<dim3(16, 16), 256, GEMM_SMEM>>>(att, Wo, out);
}

// round 9
// speedup vs baseline: 11.7440x; 1.0105x over previous
#include <cuda_runtime.h>
#include <cuda_fp16.h>
#include <stdint.h>
#include <math.h>

#define TT   2048
#define HIDN 2048
#define NH   32
#define NKV  8
#define DH   64
#define GRP  4
#define QSCALE 0.1803368801111204f   // (1/8) * log2(e)

// fp32 intermediates from GEMMs
__device__ float g_q[TT * NH * DH];
__device__ float g_k[TT * NKV * DH];
__device__ float g_v[TT * NKV * DH];
__device__ float g_att[TT * NH * DH];
// half-precision attention operands
__device__ __half g_qh[TT * NH * DH];            // pre-scaled by QSCALE
__device__ __half g_kh[TT * NKV * DH];
__device__ __half g_vt[NKV * DH * TT];           // V transposed: [kvh][d][t]

__device__ __forceinline__ uint32_t pack_half2(float lo, float hi) {
    uint32_t r;
    asm("cvt.rn.f16x2.f32 %0, %1, %2;" : "=r"(r) : "f"(hi), "f"(lo));
    return r;
}

__device__ __forceinline__ void mma_fp16(float* c,
                                         uint32_t a0, uint32_t a1, uint32_t a2, uint32_t a3,
                                         uint32_t b0, uint32_t b1) {
    asm volatile(
        "mma.sync.aligned.m16n8k16.row.col.f32.f16.f16.f32 "
        "{%0,%1,%2,%3},{%4,%5,%6,%7},{%8,%9},{%0,%1,%2,%3};"
        : "+f"(c[0]), "+f"(c[1]), "+f"(c[2]), "+f"(c[3])
        : "r"(a0), "r"(a1), "r"(a2), "r"(a3), "r"(b0), "r"(b1));
}

__device__ __forceinline__ void ldsm4(uint32_t& r0, uint32_t& r1,
                                      uint32_t& r2, uint32_t& r3, uint32_t addr) {
    asm volatile("ldmatrix.sync.aligned.m8n8.x4.shared.b16 {%0,%1,%2,%3}, [%4];"
                 : "=r"(r0), "=r"(r1), "=r"(r2), "=r"(r3) : "r"(addr));
}

#define CP_ASYNC16(dst, src) \
    asm volatile("cp.async.ca.shared.global [%0], [%1], 16;" :: "r"(dst), "l"(src) : "memory")
#define CP_COMMIT() asm volatile("cp.async.commit_group;" ::: "memory")
#define CP_WAIT(n)  asm volatile("cp.async.wait_group %0;" :: "n"(n) : "memory")

// ---------------------------------------------------------------------------
// fp16 GEMM: C[row0:+128, col0:+128] = A[*,K] @ B[*,K]^T (fp32 in, fp32 out)
// 256 threads, 8 warps (2x4), warp tile 64x32, K-slab 32, double-buffered,
// ldmatrix fragment loads.
// ---------------------------------------------------------------------------
#define ST2 20
#define SLABH (128 * ST2)
#define GEMM_SMEM (4 * SLABH * (int)sizeof(uint32_t))

__device__ __forceinline__ void gemm_body(const float* __restrict__ A,
                                          const float* __restrict__ B,
                                          float* __restrict__ C,
                                          int N, int K, int row0, int col0,
                                          uint32_t* __restrict__ sm) {
    const int tid = threadIdx.x;
    const int wid = tid >> 5, lane = tid & 31;
    const int g = lane >> 2, t = lane & 3;
    const int wm = (wid >> 2) * 64;
    const int wn = (wid & 3) * 32;

    const int rA = ((lane >> 3) & 1) * 8 + (lane & 7);
    const int cA = ((lane >> 4) & 1) * 4;
    const int rB = ((lane >> 4) & 1) * 8 + (lane & 7);
    const int cB = ((lane >> 3) & 1) * 4;

    const uint32_t smb = (uint32_t)__cvta_generic_to_shared(sm);

    const int rbase = tid >> 3;
    const int cc = tid & 7;
    const float* Ap = A + (size_t)(row0 + rbase) * K + cc * 4;
    const float* Bp = B + (size_t)(col0 + rbase) * K + cc * 4;

    float acc[4][4][4];
#pragma unroll
    for (int i = 0; i < 4; i++)
#pragma unroll
        for (int j = 0; j < 4; j++)
#pragma unroll
            for (int q = 0; q < 4; q++) acc[i][j][q] = 0.f;

    uint32_t* As = sm;
    uint32_t* Bs = sm + 2 * SLABH;

    float4 pa[4], pb[4];
#pragma unroll
    for (int i = 0; i < 4; i++) {
        pa[i] = *(const float4*)(Ap + (size_t)i * 32 * K);
        pb[i] = *(const float4*)(Bp + (size_t)i * 32 * K);
    }
#pragma unroll
    for (int i = 0; i < 4; i++) {
        int r = rbase + 32 * i;
        uint2 av = make_uint2(pack_half2(pa[i].x, pa[i].y), pack_half2(pa[i].z, pa[i].w));
        uint2 bv = make_uint2(pack_half2(pb[i].x, pb[i].y), pack_half2(pb[i].z, pb[i].w));
        *(uint2*)&As[r * ST2 + cc * 2] = av;
        *(uint2*)&Bs[r * ST2 + cc * 2] = bv;
    }
    __syncthreads();

    for (int k0 = 0; k0 < K; k0 += 32) {
        const int st = (k0 >> 5) & 1;
        const uint32_t Ab = smb + (uint32_t)st * SLABH * 4u;
        const uint32_t Bb = smb + (uint32_t)(2 + st) * SLABH * 4u;
        const bool more = (k0 + 32 < K);

        if (more) {
#pragma unroll
            for (int i = 0; i < 4; i++) {
                pa[i] = *(const float4*)(Ap + (size_t)i * 32 * K + k0 + 32);
                pb[i] = *(const float4*)(Bp + (size_t)i * 32 * K + k0 + 32);
            }
        }

#pragma unroll
        for (int ks = 0; ks < 2; ks++) {
            const int kk2 = ks * 8;
            uint32_t af[4][4], bf[4][2];
#pragma unroll
            for (int mi = 0; mi < 4; mi++) {
                uint32_t addr = Ab + (uint32_t)(((wm + mi * 16 + rA) * ST2 + kk2 + cA) * 4);
                ldsm4(af[mi][0], af[mi][1], af[mi][2], af[mi][3], addr);
            }
#pragma unroll
            for (int njp = 0; njp < 2; njp++) {
                uint32_t addr = Bb + (uint32_t)(((wn + njp * 16 + rB) * ST2 + kk2 + cB) * 4);
                ldsm4(bf[2 * njp][0], bf[2 * njp][1], bf[2 * njp + 1][0], bf[2 * njp + 1][1], addr);
            }
#pragma unroll
            for (int mi = 0; mi < 4; mi++)
#pragma unroll
                for (int nj = 0; nj < 4; nj++)
                    mma_fp16(acc[mi][nj], af[mi][0], af[mi][1], af[mi][2], af[mi][3],
                             bf[nj][0], bf[nj][1]);
        }

        if (more) {
            uint32_t* An = As + (st ^ 1) * SLABH;
            uint32_t* Bn = Bs + (st ^ 1) * SLABH;
#pragma unroll
            for (int i = 0; i < 4; i++) {
                int r = rbase + 32 * i;
                uint2 av = make_uint2(pack_half2(pa[i].x, pa[i].y), pack_half2(pa[i].z, pa[i].w));
                uint2 bv = make_uint2(pack_half2(pb[i].x, pb[i].y), pack_half2(pb[i].z, pb[i].w));
                *(uint2*)&An[r * ST2 + cc * 2] = av;
                *(uint2*)&Bn[r * ST2 + cc * 2] = bv;
            }
            __syncthreads();
        }
    }

#pragma unroll
    for (int mi = 0; mi < 4; mi++) {
#pragma unroll
        for (int nj = 0; nj < 4; nj++) {
            int r = row0 + wm + mi * 16 + g;
            int c = col0 + wn + nj * 8 + 2 * t;
            *(float2*)(C + (size_t)r * N + c)       = make_float2(acc[mi][nj][0], acc[mi][nj][1]);
            *(float2*)(C + (size_t)(r + 8) * N + c) = make_float2(acc[mi][nj][2], acc[mi][nj][3]);
        }
    }
}

__global__ void __launch_bounds__(256, 2) qkv_gemm(const float* __restrict__ x,
                                                   const float* __restrict__ Wq,
                                                   const float* __restrict__ Wk,
                                                   const float* __restrict__ Wv,
                                                   float* q, float* k, float* v) {
    extern __shared__ uint32_t sm[];
    int bx = blockIdx.x;
    int row0 = blockIdx.y * 128;
    if (bx < 16)      gemm_body(x, Wq, q, NH * DH,  HIDN, row0, bx * 128,        sm);
    else if (bx < 20) gemm_body(x, Wk, k, NKV * DH, HIDN, row0, (bx - 16) * 128, sm);
    else              gemm_body(x, Wv, v, NKV * DH, HIDN, row0, (bx - 20) * 128, sm);
}

__global__ void __launch_bounds__(256, 2) o_gemm(const float* __restrict__ A,
                                                 const float* __restrict__ Wo,
                                                 float* __restrict__ C) {
    extern __shared__ uint32_t sm[];
    gemm_body(A, Wo, C, HIDN, NH * DH, blockIdx.y * 128, blockIdx.x * 128, sm);
}

// ---------------------------------------------------------------------------
// RoPE: read fp32 q/k, write half q (pre-scaled by QSCALE) and half k.
// ---------------------------------------------------------------------------
__global__ void rope_kernel(const float* __restrict__ cosb,
                            const float* __restrict__ sinb) {
    int idx = blockIdx.x * blockDim.x + threadIdx.x;
    const int total = TT * (NH + NKV) * (DH / 2);
    if (idx >= total) return;
    int d = idx & 31;
    int r = idx >> 5;
    int head = r % (NH + NKV);
    int t = r / (NH + NKV);
    float c = cosb[t * DH + d];
    float s = sinb[t * DH + d];
    if (head < NH) {
        int off = (t * NH + head) * DH;
        float x1 = g_q[off + d], x2 = g_q[off + d + 32];
        g_qh[off + d]      = __float2half((x1 * c - x2 * s) * QSCALE);
        g_qh[off + d + 32] = __float2half((x2 * c + x1 * s) * QSCALE);
    } else {
        int off = (t * NKV + (head - NH)) * DH;
        float x1 = g_k[off + d], x2 = g_k[off + d + 32];
        g_kh[off + d]      = __float2half(x1 * c - x2 * s);
        g_kh[off + d + 32] = __float2half(x2 * c + x1 * s);
    }
}

// ---------------------------------------------------------------------------
// V transpose: g_v fp32 [t][kvh][d] -> g_vt half [kvh][d][t]
// ---------------------------------------------------------------------------
__global__ void __launch_bounds__(256) vtrans_kernel() {
    __shared__ float sm[64][65];
    const int tid = threadIdx.x;
    const int t0 = blockIdx.x * 64;
    const int kvh = blockIdx.y;
    for (int e = tid; e < 64 * 16; e += 256) {
        int r = e >> 4, c4 = (e & 15) * 4;
        float4 v = *(const float4*)&g_v[(size_t)(t0 + r) * (NKV * DH) + kvh * DH + c4];
        sm[r][c4] = v.x; sm[r][c4 + 1] = v.y; sm[r][c4 + 2] = v.z; sm[r][c4 + 3] = v.w;
    }
    __syncthreads();
    for (int e = tid; e < 64 * 8; e += 256) {
        int d = e >> 3, ch = e & 7;
        int kb = ch * 8;
        uint4 o;
        o.x = pack_half2(sm[kb + 0][d], sm[kb + 1][d]);
        o.y = pack_half2(sm[kb + 2][d], sm[kb + 3][d]);
        o.z = pack_half2(sm[kb + 4][d], sm[kb + 5][d]);
        o.w = pack_half2(sm[kb + 6][d], sm[kb + 7][d]);
        *(uint4*)&g_vt[(size_t)(kvh * DH + d) * TT + t0 + kb] = o;
    }
}

// ---------------------------------------------------------------------------
// Flash attention, fp16 MMA, register-resident P, ldmatrix fragment loads,
// cp.async double-buffered K/V tiles. 128 q-rows x 1 head, 256 threads.
// ---------------------------------------------------------------------------
#define KP2 36   // half2 stride for 64-half rows
#define TILEW (64 * KP2)

__global__ void __launch_bounds__(256) attn_kernel() {
    __shared__ uint32_t Ks[2 * TILEW];   // [buf][key][d] half2
    __shared__ uint32_t Vs[2 * TILEW];   // [buf][d][key] half2 (V^T)

    const int tid = threadIdx.x;
    const int wid = tid >> 5, lane = tid & 31;
    const int g = lane >> 2, t = lane & 3;
    const int wm = wid * 16;
    const int h = blockIdx.y;
    const int kvh = h / GRP;
    const int bx = gridDim.x - 1 - blockIdx.x;   // heavy CTAs first
    const int m0 = bx * 128;

    const int rB = ((lane >> 4) & 1) * 8 + (lane & 7);
    const int cB = ((lane >> 3) & 1) * 4;
    const uint32_t ksb = (uint32_t)__cvta_generic_to_shared(Ks);
    const uint32_t vsb = (uint32_t)__cvta_generic_to_shared(Vs);

    // cp.async chunk mapping: 2 chunks each for K and V per thread per tile
    const int pr0 = tid >> 3,          pc0 = tid & 7;          // e = tid
    const int pr1 = (tid + 256) >> 3,  pc1 = tid & 7;          // e = tid + 256
    const __half* kbase = &g_kh[(size_t)kvh * DH];             // + t*NKV*DH
    const __half* vbase = &g_vt[(size_t)kvh * DH * TT];        // + d*TT + t

#define PREFETCH(jt_, buf_) do {                                               \
    const int nn = (jt_) * 64;                                                 \
    uint32_t kd = ksb + (uint32_t)(((buf_) * TILEW + pr0 * KP2 + pc0 * 4) * 4);\
    CP_ASYNC16(kd, kbase + (size_t)(nn + pr0) * (NKV * DH) + pc0 * 8);         \
    kd = ksb + (uint32_t)(((buf_) * TILEW + pr1 * KP2 + pc1 * 4) * 4);         \
    CP_ASYNC16(kd, kbase + (size_t)(nn + pr1) * (NKV * DH) + pc1 * 8);         \
    uint32_t vd = vsb + (uint32_t)(((buf_) * TILEW + pr0 * KP2 + pc0 * 4) * 4);\
    CP_ASYNC16(vd, vbase + (size_t)pr0 * TT + nn + pc0 * 8);                   \
    vd = vsb + (uint32_t)(((buf_) * TILEW + pr1 * KP2 + pc1 * 4) * 4);         \
    CP_ASYNC16(vd, vbase + (size_t)pr1 * TT + nn + pc1 * 8);                   \
    CP_COMMIT();                                                               \
} while (0)

    // Q fragments straight from gmem (half, pre-scaled). r0/r1 = frag rows.
    const int r0 = m0 + wm + g, r1 = r0 + 8;
    uint32_t qf[4][4];
    {
        const __half* q0 = &g_qh[(size_t)r0 * (NH * DH) + h * DH];
        const __half* q1 = &g_qh[(size_t)r1 * (NH * DH) + h * DH];
#pragma unroll
        for (int ks = 0; ks < 4; ks++) {
            qf[ks][0] = *(const uint32_t*)(q0 + ks * 16 + 2 * t);
            qf[ks][1] = *(const uint32_t*)(q1 + ks * 16 + 2 * t);
            qf[ks][2] = *(const uint32_t*)(q0 + ks * 16 + 8 + 2 * t);
            qf[ks][3] = *(const uint32_t*)(q1 + ks * 16 + 8 + 2 * t);
        }
    }

    float mr0 = -1e30f, mr1 = -1e30f, l0 = 0.f, l1 = 0.f;
    float o[8][4];
#pragma unroll
    for (int j = 0; j < 8; j++)
#pragma unroll
        for (int q = 0; q < 4; q++) o[j][q] = 0.f;

    const int ntiles = 2 * bx + 2;
    PREFETCH(0, 0);

    for (int jt = 0; jt < ntiles; jt++) {
        const int n0 = jt * 64;
        const int buf = jt & 1;
        if (jt + 1 < ntiles) {
            PREFETCH(jt + 1, buf ^ 1);
            CP_WAIT(1);
        } else {
            CP_WAIT(0);
        }
        __syncthreads();   // tile jt resident; all warps see it

        const uint32_t kb = ksb + (uint32_t)(buf * TILEW * 4);
        const uint32_t vb = vsb + (uint32_t)(buf * TILEW * 4);

        // S = Q @ K^T (log2-domain, pre-scaled)
        float s[8][4];
#pragma unroll
        for (int j = 0; j < 8; j++)
#pragma unroll
            for (int q = 0; q < 4; q++) s[j][q] = 0.f;
#pragma unroll
        for (int ks = 0; ks < 4; ks++) {
            const int kk2 = ks * 8;
#pragma unroll
            for (int njp = 0; njp < 4; njp++) {
                uint32_t b0, b1, b2, b3;
                uint32_t addr = kb + (uint32_t)(((njp * 16 + rB) * KP2 + kk2 + cB) * 4);
                ldsm4(b0, b1, b2, b3, addr);
                mma_fp16(s[2 * njp],     qf[ks][0], qf[ks][1], qf[ks][2], qf[ks][3], b0, b1);
                mma_fp16(s[2 * njp + 1], qf[ks][0], qf[ks][1], qf[ks][2], qf[ks][3], b2, b3);
            }
        }

        // Causal mask
        if (jt >= 2 * bx) {
#pragma unroll
            for (int nj = 0; nj < 8; nj++) {
                int c0 = n0 + nj * 8 + 2 * t;
                if (c0     > r0) s[nj][0] = -1e30f;
                if (c0 + 1 > r0) s[nj][1] = -1e30f;
                if (c0     > r1) s[nj][2] = -1e30f;
                if (c0 + 1 > r1) s[nj][3] = -1e30f;
            }
        }

        // Register softmax, base 2; P stays in registers.
        float mx0 = -1e30f, mx1 = -1e30f;
#pragma unroll
        for (int nj = 0; nj < 8; nj++) {
            mx0 = fmaxf(mx0, fmaxf(s[nj][0], s[nj][1]));
            mx1 = fmaxf(mx1, fmaxf(s[nj][2], s[nj][3]));
        }
        mx0 = fmaxf(mx0, __shfl_xor_sync(0xffffffffu, mx0, 1));
        mx0 = fmaxf(mx0, __shfl_xor_sync(0xffffffffu, mx0, 2));
        mx1 = fmaxf(mx1, __shfl_xor_sync(0xffffffffu, mx1, 1));
        mx1 = fmaxf(mx1, __shfl_xor_sync(0xffffffffu, mx1, 2));
        float nm0 = fmaxf(mr0, mx0), nm1 = fmaxf(mr1, mx1);
        float f0 = exp2f(mr0 - nm0), f1 = exp2f(mr1 - nm1);
        float ps0 = 0.f, ps1 = 0.f;
#pragma unroll
        for (int nj = 0; nj < 8; nj++) {
            s[nj][0] = exp2f(s[nj][0] - nm0);
            s[nj][1] = exp2f(s[nj][1] - nm0);
            s[nj][2] = exp2f(s[nj][2] - nm1);
            s[nj][3] = exp2f(s[nj][3] - nm1);
            ps0 += s[nj][0] + s[nj][1];
            ps1 += s[nj][2] + s[nj][3];
        }
        ps0 += __shfl_xor_sync(0xffffffffu, ps0, 1);
        ps0 += __shfl_xor_sync(0xffffffffu, ps0, 2);
        ps1 += __shfl_xor_sync(0xffffffffu, ps1, 1);
        ps1 += __shfl_xor_sync(0xffffffffu, ps1, 2);
        l0 = l0 * f0 + ps0; l1 = l1 * f1 + ps1;
        mr0 = nm0; mr1 = nm1;
#pragma unroll
        for (int nj = 0; nj < 8; nj++) {
            o[nj][0] *= f0; o[nj][1] *= f0;
            o[nj][2] *= f1; o[nj][3] *= f1;
        }

        // O += P @ V. P accumulator fragments ARE the A-operand fragments.
#pragma unroll
        for (int ks = 0; ks < 4; ks++) {
            uint32_t a0 = pack_half2(s[2 * ks][0],     s[2 * ks][1]);
            uint32_t a1 = pack_half2(s[2 * ks][2],     s[2 * ks][3]);
            uint32_t a2 = pack_half2(s[2 * ks + 1][0], s[2 * ks + 1][1]);
            uint32_t a3 = pack_half2(s[2 * ks + 1][2], s[2 * ks + 1][3]);
            const int kk2 = ks * 8;
#pragma unroll
            for (int njp = 0; njp < 4; njp++) {
                uint32_t b0, b1, b2, b3;
                uint32_t addr = vb + (uint32_t)(((njp * 16 + rB) * KP2 + kk2 + cB) * 4);
                ldsm4(b0, b1, b2, b3, addr);
                mma_fp16(o[2 * njp],     a0, a1, a2, a3, b0, b1);
                mma_fp16(o[2 * njp + 1], a0, a1, a2, a3, b2, b3);
            }
        }
        __syncthreads();   // readers done before buf is overwritten at jt+2
    }

    // Normalize and store
    float i0 = 1.f / l0, i1 = 1.f / l1;
#pragma unroll
    for (int nj = 0; nj < 8; nj++) {
        int c = nj * 8 + 2 * t;
        float* p0 = &g_att[(size_t)r0 * (NH * DH) + h * DH + c];
        float* p1 = &g_att[(size_t)r1 * (NH * DH) + h * DH + c];
        *(float2*)p0 = make_float2(o[nj][0] * i0, o[nj][1] * i0);
        *(float2*)p1 = make_float2(o[nj][2] * i1, o[nj][3] * i1);
    }
#undef PREFETCH
}

// ---------------------------------------------------------------------------
extern "C" void kernel_launch(void* const* d_in, const int* in_sizes, int n_in,
                              void* d_out, int out_size) {
    const float* x    = (const float*)d_in[0];
    const float* cosb = (const float*)d_in[1];
    const float* sinb = (const float*)d_in[2];
    const float* Wq   = (const float*)d_in[4];
    const float* Wk   = (const float*)d_in[5];
    const float* Wv   = (const float*)d_in[6];
    const float* Wo   = (const float*)d_in[7];
    float* out = (float*)d_out;

    float *q, *k, *v, *att;
    cudaGetSymbolAddress((void**)&q, g_q);
    cudaGetSymbolAddress((void**)&k, g_k);
    cudaGetSymbolAddress((void**)&v, g_v);
    cudaGetSymbolAddress((void**)&att, g_att);

    cudaFuncSetAttribute(qkv_gemm, cudaFuncAttributeMaxDynamicSharedMemorySize, GEMM_SMEM);
    cudaFuncSetAttribute(o_gemm,   cudaFuncAttributeMaxDynamicSharedMemorySize, GEMM_SMEM);

    qkv_gemm<<<dim3(24, 16), 256, GEMM_SMEM>>>(x, Wq, Wk, Wv, q, k, v);

    {
        int total = TT * (NH + NKV) * (DH / 2);
        rope_kernel<<<(total + 255) / 256, 256>>>(cosb, sinb);
    }
    vtrans_kernel<<<dim3(TT / 64, NKV), 256>>>();

    attn_kernel<<<dim3(TT / 128, NH), 256>>>();

    o_gemm<<<dim3(16, 16), 256, GEMM_SMEM>>>(att, Wo, out);
}

// round 10
// speedup vs baseline: 13.4135x; 1.1422x over previous
#include <cuda_runtime.h>
#include <cuda_fp16.h>
#include <stdint.h>
#include <math.h>

#define TT   2048
#define HIDN 2048
#define NH   32
#define NKV  8
#define DH   64
#define GRP  4
#define QSCALE 0.1803368801111204f   // (1/8) * log2(e)

// fp32 intermediates
__device__ float g_q[TT * NH * DH];
__device__ float g_k[TT * NKV * DH];
__device__ float g_v[TT * NKV * DH];
// half operands
__device__ __half g_xh[TT * HIDN];
__device__ __half g_wqh[NH * DH * HIDN];
__device__ __half g_wkh[NKV * DH * HIDN];
__device__ __half g_wvh[NKV * DH * HIDN];
__device__ __half g_woh[HIDN * NH * DH];
__device__ __half g_qh[TT * NH * DH];            // pre-scaled by QSCALE
__device__ __half g_kh[TT * NKV * DH];
__device__ __half g_vt[NKV * DH * TT];           // V transposed: [kvh][d][t]
__device__ __half g_atth[TT * NH * DH];          // attention output (half)

__device__ __forceinline__ uint32_t pack_half2(float lo, float hi) {
    uint32_t r;
    asm("cvt.rn.f16x2.f32 %0, %1, %2;" : "=r"(r) : "f"(hi), "f"(lo));
    return r;
}

__device__ __forceinline__ void mma_fp16(float* c,
                                         uint32_t a0, uint32_t a1, uint32_t a2, uint32_t a3,
                                         uint32_t b0, uint32_t b1) {
    asm volatile(
        "mma.sync.aligned.m16n8k16.row.col.f32.f16.f16.f32 "
        "{%0,%1,%2,%3},{%4,%5,%6,%7},{%8,%9},{%0,%1,%2,%3};"
        : "+f"(c[0]), "+f"(c[1]), "+f"(c[2]), "+f"(c[3])
        : "r"(a0), "r"(a1), "r"(a2), "r"(a3), "r"(b0), "r"(b1));
}

__device__ __forceinline__ void ldsm4(uint32_t& r0, uint32_t& r1,
                                      uint32_t& r2, uint32_t& r3, uint32_t addr) {
    asm volatile("ldmatrix.sync.aligned.m8n8.x4.shared.b16 {%0,%1,%2,%3}, [%4];"
                 : "=r"(r0), "=r"(r1), "=r"(r2), "=r"(r3) : "r"(addr));
}

#define CP_ASYNC16(dst, src) \
    asm volatile("cp.async.ca.shared.global [%0], [%1], 16;" :: "r"(dst), "l"(src) : "memory")
#define CP_COMMIT() asm volatile("cp.async.commit_group;" ::: "memory")
#define CP_WAIT(n)  asm volatile("cp.async.wait_group %0;" :: "n"(n) : "memory")

// ---------------------------------------------------------------------------
// fp32 -> fp16 conversion, 5 tensors in one launch (grid.y selects tensor)
// ---------------------------------------------------------------------------
__global__ void __launch_bounds__(256) tohalf_kernel(const float* x, const float* wq,
                                                     const float* wk, const float* wv,
                                                     const float* wo) {
    const float* src;
    __half* dst;
    int n;
    switch (blockIdx.y) {
        case 0: src = x;  dst = g_xh;  n = TT * HIDN;        break;
        case 1: src = wq; dst = g_wqh; n = NH * DH * HIDN;   break;
        case 2: src = wk; dst = g_wkh; n = NKV * DH * HIDN;  break;
        case 3: src = wv; dst = g_wvh; n = NKV * DH * HIDN;  break;
        default: src = wo; dst = g_woh; n = HIDN * NH * DH;  break;
    }
    int stride = gridDim.x * blockDim.x * 4;
    for (int i = (blockIdx.x * blockDim.x + threadIdx.x) * 4; i < n; i += stride) {
        float4 v = *(const float4*)(src + i);
        uint2 o = make_uint2(pack_half2(v.x, v.y), pack_half2(v.z, v.w));
        *(uint2*)(dst + i) = o;
    }
}

// ---------------------------------------------------------------------------
// half GEMM: C[row0:+128, col0:+128] = A[*,K] @ B[*,K]^T  (half in, fp32 out)
// 256 threads, 8 warps (2x4), warp tile 64x32, K-slab 64, cp.async
// double-buffered, ldmatrix fragment loads.
// ---------------------------------------------------------------------------
#define STW 36                 // words per 64-half row (32 + 4 pad)
#define HSLAB (128 * STW)      // words per operand tile
#define GEMM_SMEM (4 * HSLAB * (int)sizeof(uint32_t))

__device__ __forceinline__ void gemm_body(const __half* __restrict__ A,
                                          const __half* __restrict__ B,
                                          float* __restrict__ C,
                                          int N, int K, int row0, int col0,
                                          uint32_t* __restrict__ sm) {
    const int tid = threadIdx.x;
    const int wid = tid >> 5, lane = tid & 31;
    const int g = lane >> 2, t = lane & 3;
    const int wm = (wid >> 2) * 64;
    const int wn = (wid & 3) * 32;

    const int rA = ((lane >> 3) & 1) * 8 + (lane & 7);
    const int cA = ((lane >> 4) & 1) * 4;
    const int rB = ((lane >> 4) & 1) * 8 + (lane & 7);
    const int cB = ((lane >> 3) & 1) * 4;

    const uint32_t smb = (uint32_t)__cvta_generic_to_shared(sm);

    float acc[4][4][4];
#pragma unroll
    for (int i = 0; i < 4; i++)
#pragma unroll
        for (int j = 0; j < 4; j++)
#pragma unroll
            for (int q = 0; q < 4; q++) acc[i][j][q] = 0.f;

#define GPREF(s_, buf_) do {                                                     \
    const int kk_ = (s_) * 64;                                                   \
    _Pragma("unroll")                                                            \
    for (int i_ = 0; i_ < 4; i_++) {                                             \
        int e_ = tid + i_ * 256;                                                 \
        int r_ = e_ >> 3, ch_ = e_ & 7;                                          \
        uint32_t ad_ = smb + (uint32_t)((((buf_) * HSLAB) + r_ * STW + ch_ * 4) * 4); \
        CP_ASYNC16(ad_, A + (size_t)(row0 + r_) * K + kk_ + ch_ * 8);            \
        uint32_t bd_ = smb + (uint32_t)((((2 + (buf_)) * HSLAB) + r_ * STW + ch_ * 4) * 4); \
        CP_ASYNC16(bd_, B + (size_t)(col0 + r_) * K + kk_ + ch_ * 8);            \
    }                                                                            \
    CP_COMMIT();                                                                 \
} while (0)

    const int nslab = K >> 6;
    GPREF(0, 0);

    for (int s = 0; s < nslab; s++) {
        const int buf = s & 1;
        if (s + 1 < nslab) {
            GPREF(s + 1, buf ^ 1);
            CP_WAIT(1);
        } else {
            CP_WAIT(0);
        }
        __syncthreads();   // slab s visible to all warps

        const uint32_t Ab = smb + (uint32_t)(buf * HSLAB * 4);
        const uint32_t Bb = smb + (uint32_t)((2 + buf) * HSLAB * 4);

#pragma unroll
        for (int ks = 0; ks < 4; ks++) {
            const int kk2 = ks * 8;
            uint32_t af[4][4], bf[4][2];
#pragma unroll
            for (int mi = 0; mi < 4; mi++) {
                uint32_t addr = Ab + (uint32_t)(((wm + mi * 16 + rA) * STW + kk2 + cA) * 4);
                ldsm4(af[mi][0], af[mi][1], af[mi][2], af[mi][3], addr);
            }
#pragma unroll
            for (int njp = 0; njp < 2; njp++) {
                uint32_t addr = Bb + (uint32_t)(((wn + njp * 16 + rB) * STW + kk2 + cB) * 4);
                ldsm4(bf[2 * njp][0], bf[2 * njp][1], bf[2 * njp + 1][0], bf[2 * njp + 1][1], addr);
            }
#pragma unroll
            for (int mi = 0; mi < 4; mi++)
#pragma unroll
                for (int nj = 0; nj < 4; nj++)
                    mma_fp16(acc[mi][nj], af[mi][0], af[mi][1], af[mi][2], af[mi][3],
                             bf[nj][0], bf[nj][1]);
        }
        __syncthreads();   // readers done before buf is overwritten at s+2
    }
#undef GPREF

#pragma unroll
    for (int mi = 0; mi < 4; mi++) {
#pragma unroll
        for (int nj = 0; nj < 4; nj++) {
            int r = row0 + wm + mi * 16 + g;
            int c = col0 + wn + nj * 8 + 2 * t;
            *(float2*)(C + (size_t)r * N + c)       = make_float2(acc[mi][nj][0], acc[mi][nj][1]);
            *(float2*)(C + (size_t)(r + 8) * N + c) = make_float2(acc[mi][nj][2], acc[mi][nj][3]);
        }
    }
}

__global__ void __launch_bounds__(256, 2) qkv_gemm(float* q, float* k, float* v) {
    extern __shared__ uint32_t sm[];
    int bx = blockIdx.x;
    int row0 = blockIdx.y * 128;
    if (bx < 16)      gemm_body(g_xh, g_wqh, q, NH * DH,  HIDN, row0, bx * 128,        sm);
    else if (bx < 20) gemm_body(g_xh, g_wkh, k, NKV * DH, HIDN, row0, (bx - 16) * 128, sm);
    else              gemm_body(g_xh, g_wvh, v, NKV * DH, HIDN, row0, (bx - 20) * 128, sm);
}

__global__ void __launch_bounds__(256, 2) o_gemm(float* __restrict__ C) {
    extern __shared__ uint32_t sm[];
    gemm_body(g_atth, g_woh, C, HIDN, NH * DH, blockIdx.y * 128, blockIdx.x * 128, sm);
}

// ---------------------------------------------------------------------------
// RoPE: read fp32 q/k, write half q (pre-scaled by QSCALE) and half k.
// ---------------------------------------------------------------------------
__global__ void rope_kernel(const float* __restrict__ cosb,
                            const float* __restrict__ sinb) {
    int idx = blockIdx.x * blockDim.x + threadIdx.x;
    const int total = TT * (NH + NKV) * (DH / 2);
    if (idx >= total) return;
    int d = idx & 31;
    int r = idx >> 5;
    int head = r % (NH + NKV);
    int t = r / (NH + NKV);
    float c = cosb[t * DH + d];
    float s = sinb[t * DH + d];
    if (head < NH) {
        int off = (t * NH + head) * DH;
        float x1 = g_q[off + d], x2 = g_q[off + d + 32];
        g_qh[off + d]      = __float2half((x1 * c - x2 * s) * QSCALE);
        g_qh[off + d + 32] = __float2half((x2 * c + x1 * s) * QSCALE);
    } else {
        int off = (t * NKV + (head - NH)) * DH;
        float x1 = g_k[off + d], x2 = g_k[off + d + 32];
        g_kh[off + d]      = __float2half(x1 * c - x2 * s);
        g_kh[off + d + 32] = __float2half(x2 * c + x1 * s);
    }
}

// ---------------------------------------------------------------------------
// V transpose: g_v fp32 [t][kvh][d] -> g_vt half [kvh][d][t]
// ---------------------------------------------------------------------------
__global__ void __launch_bounds__(256) vtrans_kernel() {
    __shared__ float sm[64][65];
    const int tid = threadIdx.x;
    const int t0 = blockIdx.x * 64;
    const int kvh = blockIdx.y;
    for (int e = tid; e < 64 * 16; e += 256) {
        int r = e >> 4, c4 = (e & 15) * 4;
        float4 v = *(const float4*)&g_v[(size_t)(t0 + r) * (NKV * DH) + kvh * DH + c4];
        sm[r][c4] = v.x; sm[r][c4 + 1] = v.y; sm[r][c4 + 2] = v.z; sm[r][c4 + 3] = v.w;
    }
    __syncthreads();
    for (int e = tid; e < 64 * 8; e += 256) {
        int d = e >> 3, ch = e & 7;
        int kb = ch * 8;
        uint4 o;
        o.x = pack_half2(sm[kb + 0][d], sm[kb + 1][d]);
        o.y = pack_half2(sm[kb + 2][d], sm[kb + 3][d]);
        o.z = pack_half2(sm[kb + 4][d], sm[kb + 5][d]);
        o.w = pack_half2(sm[kb + 6][d], sm[kb + 7][d]);
        *(uint4*)&g_vt[(size_t)(kvh * DH + d) * TT + t0 + kb] = o;
    }
}

// ---------------------------------------------------------------------------
// Flash attention, fp16 MMA, register-resident P, ldmatrix fragment loads,
// cp.async double-buffered K/V tiles. 128 q-rows x 1 head, 256 threads.
// ---------------------------------------------------------------------------
#define KP2 36   // half2 stride for 64-half rows
#define TILEW (64 * KP2)

__global__ void __launch_bounds__(256) attn_kernel() {
    __shared__ uint32_t Ks[2 * TILEW];   // [buf][key][d] half2
    __shared__ uint32_t Vs[2 * TILEW];   // [buf][d][key] half2 (V^T)

    const int tid = threadIdx.x;
    const int wid = tid >> 5, lane = tid & 31;
    const int g = lane >> 2, t = lane & 3;
    const int wm = wid * 16;
    const int h = blockIdx.y;
    const int kvh = h / GRP;
    const int bx = gridDim.x - 1 - blockIdx.x;   // heavy CTAs first
    const int m0 = bx * 128;

    const int rB = ((lane >> 4) & 1) * 8 + (lane & 7);
    const int cB = ((lane >> 3) & 1) * 4;
    const uint32_t ksb = (uint32_t)__cvta_generic_to_shared(Ks);
    const uint32_t vsb = (uint32_t)__cvta_generic_to_shared(Vs);

    const int pr0 = tid >> 3,          pc0 = tid & 7;
    const int pr1 = (tid + 256) >> 3,  pc1 = tid & 7;
    const __half* kbase = &g_kh[(size_t)kvh * DH];
    const __half* vbase = &g_vt[(size_t)kvh * DH * TT];

#define PREFETCH(jt_, buf_) do {                                               \
    const int nn = (jt_) * 64;                                                 \
    uint32_t kd = ksb + (uint32_t)(((buf_) * TILEW + pr0 * KP2 + pc0 * 4) * 4);\
    CP_ASYNC16(kd, kbase + (size_t)(nn + pr0) * (NKV * DH) + pc0 * 8);         \
    kd = ksb + (uint32_t)(((buf_) * TILEW + pr1 * KP2 + pc1 * 4) * 4);         \
    CP_ASYNC16(kd, kbase + (size_t)(nn + pr1) * (NKV * DH) + pc1 * 8);         \
    uint32_t vd = vsb + (uint32_t)(((buf_) * TILEW + pr0 * KP2 + pc0 * 4) * 4);\
    CP_ASYNC16(vd, vbase + (size_t)pr0 * TT + nn + pc0 * 8);                   \
    vd = vsb + (uint32_t)(((buf_) * TILEW + pr1 * KP2 + pc1 * 4) * 4);         \
    CP_ASYNC16(vd, vbase + (size_t)pr1 * TT + nn + pc1 * 8);                   \
    CP_COMMIT();                                                               \
} while (0)

    const int r0 = m0 + wm + g, r1 = r0 + 8;
    uint32_t qf[4][4];
    {
        const __half* q0 = &g_qh[(size_t)r0 * (NH * DH) + h * DH];
        const __half* q1 = &g_qh[(size_t)r1 * (NH * DH) + h * DH];
#pragma unroll
        for (int ks = 0; ks < 4; ks++) {
            qf[ks][0] = *(const uint32_t*)(q0 + ks * 16 + 2 * t);
            qf[ks][1] = *(const uint32_t*)(q1 + ks * 16 + 2 * t);
            qf[ks][2] = *(const uint32_t*)(q0 + ks * 16 + 8 + 2 * t);
            qf[ks][3] = *(const uint32_t*)(q1 + ks * 16 + 8 + 2 * t);
        }
    }

    float mr0 = -1e30f, mr1 = -1e30f, l0 = 0.f, l1 = 0.f;
    float o[8][4];
#pragma unroll
    for (int j = 0; j < 8; j++)
#pragma unroll
        for (int q = 0; q < 4; q++) o[j][q] = 0.f;

    const int ntiles = 2 * bx + 2;
    PREFETCH(0, 0);

    for (int jt = 0; jt < ntiles; jt++) {
        const int n0 = jt * 64;
        const int buf = jt & 1;
        if (jt + 1 < ntiles) {
            PREFETCH(jt + 1, buf ^ 1);
            CP_WAIT(1);
        } else {
            CP_WAIT(0);
        }
        __syncthreads();

        const uint32_t kb = ksb + (uint32_t)(buf * TILEW * 4);
        const uint32_t vb = vsb + (uint32_t)(buf * TILEW * 4);

        float s[8][4];
#pragma unroll
        for (int j = 0; j < 8; j++)
#pragma unroll
            for (int q = 0; q < 4; q++) s[j][q] = 0.f;
#pragma unroll
        for (int ks = 0; ks < 4; ks++) {
            const int kk2 = ks * 8;
#pragma unroll
            for (int njp = 0; njp < 4; njp++) {
                uint32_t b0, b1, b2, b3;
                uint32_t addr = kb + (uint32_t)(((njp * 16 + rB) * KP2 + kk2 + cB) * 4);
                ldsm4(b0, b1, b2, b3, addr);
                mma_fp16(s[2 * njp],     qf[ks][0], qf[ks][1], qf[ks][2], qf[ks][3], b0, b1);
                mma_fp16(s[2 * njp + 1], qf[ks][0], qf[ks][1], qf[ks][2], qf[ks][3], b2, b3);
            }
        }

        if (jt >= 2 * bx) {
#pragma unroll
            for (int nj = 0; nj < 8; nj++) {
                int c0 = n0 + nj * 8 + 2 * t;
                if (c0     > r0) s[nj][0] = -1e30f;
                if (c0 + 1 > r0) s[nj][1] = -1e30f;
                if (c0     > r1) s[nj][2] = -1e30f;
                if (c0 + 1 > r1) s[nj][3] = -1e30f;
            }
        }

        float mx0 = -1e30f, mx1 = -1e30f;
#pragma unroll
        for (int nj = 0; nj < 8; nj++) {
            mx0 = fmaxf(mx0, fmaxf(s[nj][0], s[nj][1]));
            mx1 = fmaxf(mx1, fmaxf(s[nj][2], s[nj][3]));
        }
        mx0 = fmaxf(mx0, __shfl_xor_sync(0xffffffffu, mx0, 1));
        mx0 = fmaxf(mx0, __shfl_xor_sync(0xffffffffu, mx0, 2));
        mx1 = fmaxf(mx1, __shfl_xor_sync(0xffffffffu, mx1, 1));
        mx1 = fmaxf(mx1, __shfl_xor_sync(0xffffffffu, mx1, 2));
        float nm0 = fmaxf(mr0, mx0), nm1 = fmaxf(mr1, mx1);
        float f0 = exp2f(mr0 - nm0), f1 = exp2f(mr1 - nm1);
        float ps0 = 0.f, ps1 = 0.f;
#pragma unroll
        for (int nj = 0; nj < 8; nj++) {
            s[nj][0] = exp2f(s[nj][0] - nm0);
            s[nj][1] = exp2f(s[nj][1] - nm0);
            s[nj][2] = exp2f(s[nj][2] - nm1);
            s[nj][3] = exp2f(s[nj][3] - nm1);
            ps0 += s[nj][0] + s[nj][1];
            ps1 += s[nj][2] + s[nj][3];
        }
        ps0 += __shfl_xor_sync(0xffffffffu, ps0, 1);
        ps0 += __shfl_xor_sync(0xffffffffu, ps0, 2);
        ps1 += __shfl_xor_sync(0xffffffffu, ps1, 1);
        ps1 += __shfl_xor_sync(0xffffffffu, ps1, 2);
        l0 = l0 * f0 + ps0; l1 = l1 * f1 + ps1;
        mr0 = nm0; mr1 = nm1;
#pragma unroll
        for (int nj = 0; nj < 8; nj++) {
            o[nj][0] *= f0; o[nj][1] *= f0;
            o[nj][2] *= f1; o[nj][3] *= f1;
        }

#pragma unroll
        for (int ks = 0; ks < 4; ks++) {
            uint32_t a0 = pack_half2(s[2 * ks][0],     s[2 * ks][1]);
            uint32_t a1 = pack_half2(s[2 * ks][2],     s[2 * ks][3]);
            uint32_t a2 = pack_half2(s[2 * ks + 1][0], s[2 * ks + 1][1]);
            uint32_t a3 = pack_half2(s[2 * ks + 1][2], s[2 * ks + 1][3]);
            const int kk2 = ks * 8;
#pragma unroll
            for (int njp = 0; njp < 4; njp++) {
                uint32_t b0, b1, b2, b3;
                uint32_t addr = vb + (uint32_t)(((njp * 16 + rB) * KP2 + kk2 + cB) * 4);
                ldsm4(b0, b1, b2, b3, addr);
                mma_fp16(o[2 * njp],     a0, a1, a2, a3, b0, b1);
                mma_fp16(o[2 * njp + 1], a0, a1, a2, a3, b2, b3);
            }
        }
        __syncthreads();
    }

    // Normalize and store directly as half (same rounding as before, relocated)
    float i0 = 1.f / l0, i1 = 1.f / l1;
#pragma unroll
    for (int nj = 0; nj < 8; nj++) {
        int c = nj * 8 + 2 * t;
        *(uint32_t*)&g_atth[(size_t)r0 * (NH * DH) + h * DH + c] =
            pack_half2(o[nj][0] * i0, o[nj][1] * i0);
        *(uint32_t*)&g_atth[(size_t)r1 * (NH * DH) + h * DH + c] =
            pack_half2(o[nj][2] * i1, o[nj][3] * i1);
    }
#undef PREFETCH
}

// ---------------------------------------------------------------------------
extern "C" void kernel_launch(void* const* d_in, const int* in_sizes, int n_in,
                              void* d_out, int out_size) {
    const float* x    = (const float*)d_in[0];
    const float* cosb = (const float*)d_in[1];
    const float* sinb = (const float*)d_in[2];
    const float* Wq   = (const float*)d_in[4];
    const float* Wk   = (const float*)d_in[5];
    const float* Wv   = (const float*)d_in[6];
    const float* Wo   = (const float*)d_in[7];
    float* out = (float*)d_out;

    float *q, *k, *v;
    cudaGetSymbolAddress((void**)&q, g_q);
    cudaGetSymbolAddress((void**)&k, g_k);
    cudaGetSymbolAddress((void**)&v, g_v);

    cudaFuncSetAttribute(qkv_gemm, cudaFuncAttributeMaxDynamicSharedMemorySize, GEMM_SMEM);
    cudaFuncSetAttribute(o_gemm,   cudaFuncAttributeMaxDynamicSharedMemorySize, GEMM_SMEM);

    tohalf_kernel<<<dim3(256, 5), 256>>>(x, Wq, Wk, Wv, Wo);

    qkv_gemm<<<dim3(24, 16), 256, GEMM_SMEM>>>(q, k, v);

    {
        int total = TT * (NH + NKV) * (DH / 2);
        rope_kernel<<<(total + 255) / 256, 256>>>(cosb, sinb);
    }
    vtrans_kernel<<<dim3(TT / 64, NKV), 256>>>();

    attn_kernel<<<dim3(TT / 128, NH), 256>>>();

    o_gemm<<<dim3(16, 16), 256, GEMM_SMEM>>>(out);
}

// round 11
// speedup vs baseline: 13.8375x; 1.0316x over previous
#include <cuda_runtime.h>
#include <cuda_fp16.h>
#include <stdint.h>
#include <math.h>

#define TT   2048
#define HIDN 2048
#define NH   32
#define NKV  8
#define DH   64
#define GRP  4
#define QSCALE 0.1803368801111204f   // (1/8) * log2(e)

// fp32 intermediates
__device__ float g_q[TT * NH * DH];
__device__ float g_k[TT * NKV * DH];
__device__ float g_v[TT * NKV * DH];
// half operands
__device__ __half g_xh[TT * HIDN];
__device__ __half g_wqh[NH * DH * HIDN];
__device__ __half g_wkh[NKV * DH * HIDN];
__device__ __half g_wvh[NKV * DH * HIDN];
__device__ __half g_woh[HIDN * NH * DH];
__device__ __half g_qh[TT * NH * DH];            // pre-scaled by QSCALE
__device__ __half g_kh[TT * NKV * DH];
__device__ __half g_vt[NKV * DH * TT];           // V transposed: [kvh][d][t]
__device__ __half g_atth[TT * NH * DH];          // attention output (half)

__device__ __forceinline__ uint32_t pack_half2(float lo, float hi) {
    uint32_t r;
    asm("cvt.rn.f16x2.f32 %0, %1, %2;" : "=r"(r) : "f"(hi), "f"(lo));
    return r;
}

__device__ __forceinline__ float ex2(float x) {
    float r;
    asm("ex2.approx.ftz.f32 %0, %1;" : "=f"(r) : "f"(x));
    return r;
}

__device__ __forceinline__ void mma_fp16(float* c,
                                         uint32_t a0, uint32_t a1, uint32_t a2, uint32_t a3,
                                         uint32_t b0, uint32_t b1) {
    asm volatile(
        "mma.sync.aligned.m16n8k16.row.col.f32.f16.f16.f32 "
        "{%0,%1,%2,%3},{%4,%5,%6,%7},{%8,%9},{%0,%1,%2,%3};"
        : "+f"(c[0]), "+f"(c[1]), "+f"(c[2]), "+f"(c[3])
        : "r"(a0), "r"(a1), "r"(a2), "r"(a3), "r"(b0), "r"(b1));
}

__device__ __forceinline__ void ldsm4(uint32_t& r0, uint32_t& r1,
                                      uint32_t& r2, uint32_t& r3, uint32_t addr) {
    asm volatile("ldmatrix.sync.aligned.m8n8.x4.shared.b16 {%0,%1,%2,%3}, [%4];"
                 : "=r"(r0), "=r"(r1), "=r"(r2), "=r"(r3) : "r"(addr));
}

#define CP_ASYNC16(dst, src) \
    asm volatile("cp.async.ca.shared.global [%0], [%1], 16;" :: "r"(dst), "l"(src) : "memory")
#define CP_COMMIT() asm volatile("cp.async.commit_group;" ::: "memory")
#define CP_WAIT(n)  asm volatile("cp.async.wait_group %0;" :: "n"(n) : "memory")

// ---------------------------------------------------------------------------
// fp32 -> fp16 conversion, 5 tensors in one launch (grid.y selects tensor)
// ---------------------------------------------------------------------------
__global__ void __launch_bounds__(256) tohalf_kernel(const float* x, const float* wq,
                                                     const float* wk, const float* wv,
                                                     const float* wo) {
    const float* src;
    __half* dst;
    int n;
    switch (blockIdx.y) {
        case 0: src = x;  dst = g_xh;  n = TT * HIDN;        break;
        case 1: src = wq; dst = g_wqh; n = NH * DH * HIDN;   break;
        case 2: src = wk; dst = g_wkh; n = NKV * DH * HIDN;  break;
        case 3: src = wv; dst = g_wvh; n = NKV * DH * HIDN;  break;
        default: src = wo; dst = g_woh; n = HIDN * NH * DH;  break;
    }
    int stride = gridDim.x * blockDim.x * 4;
    for (int i = (blockIdx.x * blockDim.x + threadIdx.x) * 4; i < n; i += stride) {
        float4 v = *(const float4*)(src + i);
        uint2 o = make_uint2(pack_half2(v.x, v.y), pack_half2(v.z, v.w));
        *(uint2*)(dst + i) = o;
    }
}

// ---------------------------------------------------------------------------
// half GEMM: C[row0:+128, col0:+128] = A[*,K] @ B[*,K]^T  (half in, fp32 out)
// 256 threads, 8 warps (2x4), warp tile 64x32, K-slab 64, cp.async
// double-buffered, ldmatrix fragment loads.
// ---------------------------------------------------------------------------
#define STW 36                 // words per 64-half row (32 + 4 pad)
#define HSLAB (128 * STW)      // words per operand tile
#define GEMM_SMEM (4 * HSLAB * (int)sizeof(uint32_t))

__device__ __forceinline__ void gemm_body(const __half* __restrict__ A,
                                          const __half* __restrict__ B,
                                          float* __restrict__ C,
                                          int N, int K, int row0, int col0,
                                          uint32_t* __restrict__ sm) {
    const int tid = threadIdx.x;
    const int wid = tid >> 5, lane = tid & 31;
    const int g = lane >> 2, t = lane & 3;
    const int wm = (wid >> 2) * 64;
    const int wn = (wid & 3) * 32;

    const int rA = ((lane >> 3) & 1) * 8 + (lane & 7);
    const int cA = ((lane >> 4) & 1) * 4;
    const int rB = ((lane >> 4) & 1) * 8 + (lane & 7);
    const int cB = ((lane >> 3) & 1) * 4;

    const uint32_t smb = (uint32_t)__cvta_generic_to_shared(sm);

    float acc[4][4][4];
#pragma unroll
    for (int i = 0; i < 4; i++)
#pragma unroll
        for (int j = 0; j < 4; j++)
#pragma unroll
            for (int q = 0; q < 4; q++) acc[i][j][q] = 0.f;

#define GPREF(s_, buf_) do {                                                     \
    const int kk_ = (s_) * 64;                                                   \
    _Pragma("unroll")                                                            \
    for (int i_ = 0; i_ < 4; i_++) {                                             \
        int e_ = tid + i_ * 256;                                                 \
        int r_ = e_ >> 3, ch_ = e_ & 7;                                          \
        uint32_t ad_ = smb + (uint32_t)((((buf_) * HSLAB) + r_ * STW + ch_ * 4) * 4); \
        CP_ASYNC16(ad_, A + (size_t)(row0 + r_) * K + kk_ + ch_ * 8);            \
        uint32_t bd_ = smb + (uint32_t)((((2 + (buf_)) * HSLAB) + r_ * STW + ch_ * 4) * 4); \
        CP_ASYNC16(bd_, B + (size_t)(col0 + r_) * K + kk_ + ch_ * 8);            \
    }                                                                            \
    CP_COMMIT();                                                                 \
} while (0)

    const int nslab = K >> 6;
    GPREF(0, 0);

    for (int s = 0; s < nslab; s++) {
        const int buf = s & 1;
        if (s + 1 < nslab) {
            GPREF(s + 1, buf ^ 1);
            CP_WAIT(1);
        } else {
            CP_WAIT(0);
        }
        __syncthreads();   // slab s visible to all warps

        const uint32_t Ab = smb + (uint32_t)(buf * HSLAB * 4);
        const uint32_t Bb = smb + (uint32_t)((2 + buf) * HSLAB * 4);

#pragma unroll
        for (int ks = 0; ks < 4; ks++) {
            const int kk2 = ks * 8;
            uint32_t af[4][4], bf[4][2];
#pragma unroll
            for (int mi = 0; mi < 4; mi++) {
                uint32_t addr = Ab + (uint32_t)(((wm + mi * 16 + rA) * STW + kk2 + cA) * 4);
                ldsm4(af[mi][0], af[mi][1], af[mi][2], af[mi][3], addr);
            }
#pragma unroll
            for (int njp = 0; njp < 2; njp++) {
                uint32_t addr = Bb + (uint32_t)(((wn + njp * 16 + rB) * STW + kk2 + cB) * 4);
                ldsm4(bf[2 * njp][0], bf[2 * njp][1], bf[2 * njp + 1][0], bf[2 * njp + 1][1], addr);
            }
#pragma unroll
            for (int mi = 0; mi < 4; mi++)
#pragma unroll
                for (int nj = 0; nj < 4; nj++)
                    mma_fp16(acc[mi][nj], af[mi][0], af[mi][1], af[mi][2], af[mi][3],
                             bf[nj][0], bf[nj][1]);
        }
        __syncthreads();   // readers done before buf is overwritten at s+2
    }
#undef GPREF

#pragma unroll
    for (int mi = 0; mi < 4; mi++) {
#pragma unroll
        for (int nj = 0; nj < 4; nj++) {
            int r = row0 + wm + mi * 16 + g;
            int c = col0 + wn + nj * 8 + 2 * t;
            *(float2*)(C + (size_t)r * N + c)       = make_float2(acc[mi][nj][0], acc[mi][nj][1]);
            *(float2*)(C + (size_t)(r + 8) * N + c) = make_float2(acc[mi][nj][2], acc[mi][nj][3]);
        }
    }
}

__global__ void __launch_bounds__(256, 2) qkv_gemm(float* q, float* k, float* v) {
    extern __shared__ uint32_t sm[];
    int bx = blockIdx.x;
    int row0 = blockIdx.y * 128;
    if (bx < 16)      gemm_body(g_xh, g_wqh, q, NH * DH,  HIDN, row0, bx * 128,        sm);
    else if (bx < 20) gemm_body(g_xh, g_wkh, k, NKV * DH, HIDN, row0, (bx - 16) * 128, sm);
    else              gemm_body(g_xh, g_wvh, v, NKV * DH, HIDN, row0, (bx - 20) * 128, sm);
}

__global__ void __launch_bounds__(256, 2) o_gemm(float* __restrict__ C) {
    extern __shared__ uint32_t sm[];
    gemm_body(g_atth, g_woh, C, HIDN, NH * DH, blockIdx.y * 128, blockIdx.x * 128, sm);
}

// ---------------------------------------------------------------------------
// RoPE: read fp32 q/k, write half q (pre-scaled by QSCALE) and half k.
// ---------------------------------------------------------------------------
__global__ void rope_kernel(const float* __restrict__ cosb,
                            const float* __restrict__ sinb) {
    int idx = blockIdx.x * blockDim.x + threadIdx.x;
    const int total = TT * (NH + NKV) * (DH / 2);
    if (idx >= total) return;
    int d = idx & 31;
    int r = idx >> 5;
    int head = r % (NH + NKV);
    int t = r / (NH + NKV);
    float c = cosb[t * DH + d];
    float s = sinb[t * DH + d];
    if (head < NH) {
        int off = (t * NH + head) * DH;
        float x1 = g_q[off + d], x2 = g_q[off + d + 32];
        g_qh[off + d]      = __float2half((x1 * c - x2 * s) * QSCALE);
        g_qh[off + d + 32] = __float2half((x2 * c + x1 * s) * QSCALE);
    } else {
        int off = (t * NKV + (head - NH)) * DH;
        float x1 = g_k[off + d], x2 = g_k[off + d + 32];
        g_kh[off + d]      = __float2half(x1 * c - x2 * s);
        g_kh[off + d + 32] = __float2half(x2 * c + x1 * s);
    }
}

// ---------------------------------------------------------------------------
// V transpose: g_v fp32 [t][kvh][d] -> g_vt half [kvh][d][t]
// ---------------------------------------------------------------------------
__global__ void __launch_bounds__(256) vtrans_kernel() {
    __shared__ float sm[64][65];
    const int tid = threadIdx.x;
    const int t0 = blockIdx.x * 64;
    const int kvh = blockIdx.y;
    for (int e = tid; e < 64 * 16; e += 256) {
        int r = e >> 4, c4 = (e & 15) * 4;
        float4 v = *(const float4*)&g_v[(size_t)(t0 + r) * (NKV * DH) + kvh * DH + c4];
        sm[r][c4] = v.x; sm[r][c4 + 1] = v.y; sm[r][c4 + 2] = v.z; sm[r][c4 + 3] = v.w;
    }
    __syncthreads();
    for (int e = tid; e < 64 * 8; e += 256) {
        int d = e >> 3, ch = e & 7;
        int kb = ch * 8;
        uint4 o;
        o.x = pack_half2(sm[kb + 0][d], sm[kb + 1][d]);
        o.y = pack_half2(sm[kb + 2][d], sm[kb + 3][d]);
        o.z = pack_half2(sm[kb + 4][d], sm[kb + 5][d]);
        o.w = pack_half2(sm[kb + 6][d], sm[kb + 7][d]);
        *(uint4*)&g_vt[(size_t)(kvh * DH + d) * TT + t0 + kb] = o;
    }
}

// ---------------------------------------------------------------------------
// Flash attention, fp16 MMA, register-resident P, ldmatrix loads,
// 3-stage cp.async pipeline, ex2.approx softmax, deferred l-reduction.
// 128 q-rows x 1 head per block, 256 threads = 8 warps.
// ---------------------------------------------------------------------------
#define KP2 36   // half2 stride for 64-half rows
#define TILEW (64 * KP2)
#define NSTG 3
#define ATTN_SMEM (2 * NSTG * TILEW * (int)sizeof(uint32_t))

__global__ void __launch_bounds__(256) attn_kernel() {
    extern __shared__ uint32_t abuf[];
    uint32_t* Ks = abuf;                 // [NSTG][key][d] half2
    uint32_t* Vs = abuf + NSTG * TILEW;  // [NSTG][d][key] half2 (V^T)

    const int tid = threadIdx.x;
    const int wid = tid >> 5, lane = tid & 31;
    const int g = lane >> 2, t = lane & 3;
    const int wm = wid * 16;
    const int h = blockIdx.y;
    const int kvh = h / GRP;
    const int bx = gridDim.x - 1 - blockIdx.x;   // heavy CTAs first
    const int m0 = bx * 128;

    const int rB = ((lane >> 4) & 1) * 8 + (lane & 7);
    const int cB = ((lane >> 3) & 1) * 4;
    const uint32_t ksb = (uint32_t)__cvta_generic_to_shared(Ks);
    const uint32_t vsb = (uint32_t)__cvta_generic_to_shared(Vs);

    const int pr0 = tid >> 3,          pc0 = tid & 7;
    const int pr1 = (tid + 256) >> 3,  pc1 = tid & 7;
    const __half* kbase = &g_kh[(size_t)kvh * DH];
    const __half* vbase = &g_vt[(size_t)kvh * DH * TT];

#define PREFETCH(jt_, buf_) do {                                               \
    const int nn = (jt_) * 64;                                                 \
    uint32_t kd = ksb + (uint32_t)(((buf_) * TILEW + pr0 * KP2 + pc0 * 4) * 4);\
    CP_ASYNC16(kd, kbase + (size_t)(nn + pr0) * (NKV * DH) + pc0 * 8);         \
    kd = ksb + (uint32_t)(((buf_) * TILEW + pr1 * KP2 + pc1 * 4) * 4);         \
    CP_ASYNC16(kd, kbase + (size_t)(nn + pr1) * (NKV * DH) + pc1 * 8);         \
    uint32_t vd = vsb + (uint32_t)(((buf_) * TILEW + pr0 * KP2 + pc0 * 4) * 4);\
    CP_ASYNC16(vd, vbase + (size_t)pr0 * TT + nn + pc0 * 8);                   \
    vd = vsb + (uint32_t)(((buf_) * TILEW + pr1 * KP2 + pc1 * 4) * 4);         \
    CP_ASYNC16(vd, vbase + (size_t)pr1 * TT + nn + pc1 * 8);                   \
    CP_COMMIT();                                                               \
} while (0)

    const int r0 = m0 + wm + g, r1 = r0 + 8;
    uint32_t qf[4][4];
    {
        const __half* q0 = &g_qh[(size_t)r0 * (NH * DH) + h * DH];
        const __half* q1 = &g_qh[(size_t)r1 * (NH * DH) + h * DH];
#pragma unroll
        for (int ks = 0; ks < 4; ks++) {
            qf[ks][0] = *(const uint32_t*)(q0 + ks * 16 + 2 * t);
            qf[ks][1] = *(const uint32_t*)(q1 + ks * 16 + 2 * t);
            qf[ks][2] = *(const uint32_t*)(q0 + ks * 16 + 8 + 2 * t);
            qf[ks][3] = *(const uint32_t*)(q1 + ks * 16 + 8 + 2 * t);
        }
    }

    float mr0 = -1e30f, mr1 = -1e30f, l0 = 0.f, l1 = 0.f;  // l lane-partial
    float o[8][4];
#pragma unroll
    for (int j = 0; j < 8; j++)
#pragma unroll
        for (int q = 0; q < 4; q++) o[j][q] = 0.f;

    const int ntiles = 2 * bx + 2;
    PREFETCH(0, 0);
    if (ntiles > 1) PREFETCH(1, 1);

    int buf = 0;
    for (int jt = 0; jt < ntiles; jt++) {
        const int n0 = jt * 64;
        if (jt + 2 < ntiles) {
            int pb = buf + 2; if (pb >= NSTG) pb -= NSTG;
            PREFETCH(jt + 2, pb);
            CP_WAIT(2);
        } else if (jt + 1 < ntiles) {
            CP_WAIT(1);
        } else {
            CP_WAIT(0);
        }
        __syncthreads();

        const uint32_t kb = ksb + (uint32_t)(buf * TILEW * 4);
        const uint32_t vb = vsb + (uint32_t)(buf * TILEW * 4);

        float s[8][4];
#pragma unroll
        for (int j = 0; j < 8; j++)
#pragma unroll
            for (int q = 0; q < 4; q++) s[j][q] = 0.f;
#pragma unroll
        for (int ks = 0; ks < 4; ks++) {
            const int kk2 = ks * 8;
#pragma unroll
            for (int njp = 0; njp < 4; njp++) {
                uint32_t b0, b1, b2, b3;
                uint32_t addr = kb + (uint32_t)(((njp * 16 + rB) * KP2 + kk2 + cB) * 4);
                ldsm4(b0, b1, b2, b3, addr);
                mma_fp16(s[2 * njp],     qf[ks][0], qf[ks][1], qf[ks][2], qf[ks][3], b0, b1);
                mma_fp16(s[2 * njp + 1], qf[ks][0], qf[ks][1], qf[ks][2], qf[ks][3], b2, b3);
            }
        }

        if (jt >= 2 * bx) {
#pragma unroll
            for (int nj = 0; nj < 8; nj++) {
                int c0 = n0 + nj * 8 + 2 * t;
                if (c0     > r0) s[nj][0] = -1e30f;
                if (c0 + 1 > r0) s[nj][1] = -1e30f;
                if (c0     > r1) s[nj][2] = -1e30f;
                if (c0 + 1 > r1) s[nj][3] = -1e30f;
            }
        }

        // Register softmax, base 2 via ex2.approx. Max is quad-reduced so the
        // rescale factor is quad-uniform; l accumulates lane-partially.
        float mx0 = -1e30f, mx1 = -1e30f;
#pragma unroll
        for (int nj = 0; nj < 8; nj++) {
            mx0 = fmaxf(mx0, fmaxf(s[nj][0], s[nj][1]));
            mx1 = fmaxf(mx1, fmaxf(s[nj][2], s[nj][3]));
        }
        mx0 = fmaxf(mx0, __shfl_xor_sync(0xffffffffu, mx0, 1));
        mx0 = fmaxf(mx0, __shfl_xor_sync(0xffffffffu, mx0, 2));
        mx1 = fmaxf(mx1, __shfl_xor_sync(0xffffffffu, mx1, 1));
        mx1 = fmaxf(mx1, __shfl_xor_sync(0xffffffffu, mx1, 2));
        float nm0 = fmaxf(mr0, mx0), nm1 = fmaxf(mr1, mx1);
        float f0 = ex2(mr0 - nm0), f1 = ex2(mr1 - nm1);
        float ps0 = 0.f, ps1 = 0.f;
#pragma unroll
        for (int nj = 0; nj < 8; nj++) {
            s[nj][0] = ex2(s[nj][0] - nm0);
            s[nj][1] = ex2(s[nj][1] - nm0);
            s[nj][2] = ex2(s[nj][2] - nm1);
            s[nj][3] = ex2(s[nj][3] - nm1);
            ps0 += s[nj][0] + s[nj][1];
            ps1 += s[nj][2] + s[nj][3];
        }
        l0 = l0 * f0 + ps0; l1 = l1 * f1 + ps1;
        mr0 = nm0; mr1 = nm1;
#pragma unroll
        for (int nj = 0; nj < 8; nj++) {
            o[nj][0] *= f0; o[nj][1] *= f0;
            o[nj][2] *= f1; o[nj][3] *= f1;
        }

#pragma unroll
        for (int ks = 0; ks < 4; ks++) {
            uint32_t a0 = pack_half2(s[2 * ks][0],     s[2 * ks][1]);
            uint32_t a1 = pack_half2(s[2 * ks][2],     s[2 * ks][3]);
            uint32_t a2 = pack_half2(s[2 * ks + 1][0], s[2 * ks + 1][1]);
            uint32_t a3 = pack_half2(s[2 * ks + 1][2], s[2 * ks + 1][3]);
            const int kk2 = ks * 8;
#pragma unroll
            for (int njp = 0; njp < 4; njp++) {
                uint32_t b0, b1, b2, b3;
                uint32_t addr = vb + (uint32_t)(((njp * 16 + rB) * KP2 + kk2 + cB) * 4);
                ldsm4(b0, b1, b2, b3, addr);
                mma_fp16(o[2 * njp],     a0, a1, a2, a3, b0, b1);
                mma_fp16(o[2 * njp + 1], a0, a1, a2, a3, b2, b3);
            }
        }
        __syncthreads();
        if (++buf == NSTG) buf = 0;
    }

    // Final quad reduction of lane-partial l, then normalize and store (half)
    l0 += __shfl_xor_sync(0xffffffffu, l0, 1);
    l0 += __shfl_xor_sync(0xffffffffu, l0, 2);
    l1 += __shfl_xor_sync(0xffffffffu, l1, 1);
    l1 += __shfl_xor_sync(0xffffffffu, l1, 2);
    float i0 = 1.f / l0, i1 = 1.f / l1;
#pragma unroll
    for (int nj = 0; nj < 8; nj++) {
        int c = nj * 8 + 2 * t;
        *(uint32_t*)&g_atth[(size_t)r0 * (NH * DH) + h * DH + c] =
            pack_half2(o[nj][0] * i0, o[nj][1] * i0);
        *(uint32_t*)&g_atth[(size_t)r1 * (NH * DH) + h * DH + c] =
            pack_half2(o[nj][2] * i1, o[nj][3] * i1);
    }
#undef PREFETCH
}

// ---------------------------------------------------------------------------
extern "C" void kernel_launch(void* const* d_in, const int* in_sizes, int n_in,
                              void* d_out, int out_size) {
    const float* x    = (const float*)d_in[0];
    const float* cosb = (const float*)d_in[1];
    const float* sinb = (const float*)d_in[2];
    const float* Wq   = (const float*)d_in[4];
    const float* Wk   = (const float*)d_in[5];
    const float* Wv   = (const float*)d_in[6];
    const float* Wo   = (const float*)d_in[7];
    float* out = (float*)d_out;

    float *q, *k, *v;
    cudaGetSymbolAddress((void**)&q, g_q);
    cudaGetSymbolAddress((void**)&k, g_k);
    cudaGetSymbolAddress((void**)&v, g_v);

    cudaFuncSetAttribute(qkv_gemm, cudaFuncAttributeMaxDynamicSharedMemorySize, GEMM_SMEM);
    cudaFuncSetAttribute(o_gemm,   cudaFuncAttributeMaxDynamicSharedMemorySize, GEMM_SMEM);
    cudaFuncSetAttribute(attn_kernel, cudaFuncAttributeMaxDynamicSharedMemorySize, ATTN_SMEM);

    tohalf_kernel<<<dim3(256, 5), 256>>>(x, Wq, Wk, Wv, Wo);

    qkv_gemm<<<dim3(24, 16), 256, GEMM_SMEM>>>(q, k, v);

    {
        int total = TT * (NH + NKV) * (DH / 2);
        rope_kernel<<<(total + 255) / 256, 256>>>(cosb, sinb);
    }
    vtrans_kernel<<<dim3(TT / 64, NKV), 256>>>();

    attn_kernel<<<dim3(TT / 128, NH), 256, ATTN_SMEM>>>();

    o_gemm<<<dim3(16, 16), 256, GEMM_SMEM>>>(out);
}

// round 12
// speedup vs baseline: 14.6531x; 1.0589x over previous
#include <cuda_runtime.h>
#include <cuda_fp16.h>
#include <stdint.h>
#include <math.h>

#define TT   2048
#define HIDN 2048
#define NH   32
#define NKV  8
#define DH   64
#define GRP  4
#define QSCALE 0.1803368801111204f   // (1/8) * log2(e)

// half operands
__device__ __half g_xh[TT * HIDN];
__device__ __half g_wqh[NH * DH * HIDN];
__device__ __half g_wkh[NKV * DH * HIDN];
__device__ __half g_wvh[NKV * DH * HIDN];
__device__ __half g_woh[HIDN * NH * DH];
__device__ __half g_qh[TT * NH * DH];            // rope'd, pre-scaled by QSCALE
__device__ __half g_kh[TT * NKV * DH];           // rope'd
__device__ __half g_vt[NKV * DH * TT];           // V transposed: [kvh][d][t]
__device__ __half g_atth[TT * NH * DH];          // attention output (half)

__device__ __forceinline__ uint32_t pack_half2(float lo, float hi) {
    uint32_t r;
    asm("cvt.rn.f16x2.f32 %0, %1, %2;" : "=r"(r) : "f"(hi), "f"(lo));
    return r;
}

__device__ __forceinline__ float ex2(float x) {
    float r;
    asm("ex2.approx.ftz.f32 %0, %1;" : "=f"(r) : "f"(x));
    return r;
}

__device__ __forceinline__ void mma_fp16(float* c,
                                         uint32_t a0, uint32_t a1, uint32_t a2, uint32_t a3,
                                         uint32_t b0, uint32_t b1) {
    asm volatile(
        "mma.sync.aligned.m16n8k16.row.col.f32.f16.f16.f32 "
        "{%0,%1,%2,%3},{%4,%5,%6,%7},{%8,%9},{%0,%1,%2,%3};"
        : "+f"(c[0]), "+f"(c[1]), "+f"(c[2]), "+f"(c[3])
        : "r"(a0), "r"(a1), "r"(a2), "r"(a3), "r"(b0), "r"(b1));
}

__device__ __forceinline__ void ldsm4(uint32_t& r0, uint32_t& r1,
                                      uint32_t& r2, uint32_t& r3, uint32_t addr) {
    asm volatile("ldmatrix.sync.aligned.m8n8.x4.shared.b16 {%0,%1,%2,%3}, [%4];"
                 : "=r"(r0), "=r"(r1), "=r"(r2), "=r"(r3) : "r"(addr));
}

#define CP_ASYNC16(dst, src) \
    asm volatile("cp.async.ca.shared.global [%0], [%1], 16;" :: "r"(dst), "l"(src) : "memory")
#define CP_COMMIT() asm volatile("cp.async.commit_group;" ::: "memory")
#define CP_WAIT(n)  asm volatile("cp.async.wait_group %0;" :: "n"(n) : "memory")

// ---------------------------------------------------------------------------
// fp32 -> fp16 conversion, 5 tensors in one launch (grid.y selects tensor)
// ---------------------------------------------------------------------------
__global__ void __launch_bounds__(256) tohalf_kernel(const float* x, const float* wq,
                                                     const float* wk, const float* wv,
                                                     const float* wo) {
    const float* src;
    __half* dst;
    int n;
    switch (blockIdx.y) {
        case 0: src = x;  dst = g_xh;  n = TT * HIDN;        break;
        case 1: src = wq; dst = g_wqh; n = NH * DH * HIDN;   break;
        case 2: src = wk; dst = g_wkh; n = NKV * DH * HIDN;  break;
        case 3: src = wv; dst = g_wvh; n = NKV * DH * HIDN;  break;
        default: src = wo; dst = g_woh; n = HIDN * NH * DH;  break;
    }
    int stride = gridDim.x * blockDim.x * 4;
    for (int i = (blockIdx.x * blockDim.x + threadIdx.x) * 4; i < n; i += stride) {
        float4 v = *(const float4*)(src + i);
        uint2 o = make_uint2(pack_half2(v.x, v.y), pack_half2(v.z, v.w));
        *(uint2*)(dst + i) = o;
    }
}

// ---------------------------------------------------------------------------
// half GEMM with fused epilogues.
// MODE 0: store fp32 C.  MODE 1: rope+QSCALE -> g_qh.  MODE 2: rope -> g_kh.
// MODE 3: transpose -> g_vt.
// 256 threads, 8 warps (2x4), warp tile 64x32, K-slab 64, cp.async
// double-buffered, ldmatrix fragment loads.
// ---------------------------------------------------------------------------
#define STW 36                 // words per 64-half row (32 + 4 pad)
#define HSLAB (128 * STW)      // words per operand tile
#define GEMM_SMEM (4 * HSLAB * (int)sizeof(uint32_t))
#define SST 132                // fp32 staging stride for rope epilogue

template <int MODE>
__device__ __forceinline__ void gemm_body(const __half* __restrict__ A,
                                          const __half* __restrict__ B,
                                          float* __restrict__ C,
                                          int N, int K, int row0, int col0,
                                          uint32_t* __restrict__ sm,
                                          const float* __restrict__ cosb,
                                          const float* __restrict__ sinb) {
    const int tid = threadIdx.x;
    const int wid = tid >> 5, lane = tid & 31;
    const int g = lane >> 2, t = lane & 3;
    const int wm = (wid >> 2) * 64;
    const int wn = (wid & 3) * 32;

    const int rA = ((lane >> 3) & 1) * 8 + (lane & 7);
    const int cA = ((lane >> 4) & 1) * 4;
    const int rB = ((lane >> 4) & 1) * 8 + (lane & 7);
    const int cB = ((lane >> 3) & 1) * 4;

    const uint32_t smb = (uint32_t)__cvta_generic_to_shared(sm);

    float acc[4][4][4];
#pragma unroll
    for (int i = 0; i < 4; i++)
#pragma unroll
        for (int j = 0; j < 4; j++)
#pragma unroll
            for (int q = 0; q < 4; q++) acc[i][j][q] = 0.f;

#define GPREF(s_, buf_) do {                                                     \
    const int kk_ = (s_) * 64;                                                   \
    _Pragma("unroll")                                                            \
    for (int i_ = 0; i_ < 4; i_++) {                                             \
        int e_ = tid + i_ * 256;                                                 \
        int r_ = e_ >> 3, ch_ = e_ & 7;                                          \
        uint32_t ad_ = smb + (uint32_t)((((buf_) * HSLAB) + r_ * STW + ch_ * 4) * 4); \
        CP_ASYNC16(ad_, A + (size_t)(row0 + r_) * K + kk_ + ch_ * 8);            \
        uint32_t bd_ = smb + (uint32_t)((((2 + (buf_)) * HSLAB) + r_ * STW + ch_ * 4) * 4); \
        CP_ASYNC16(bd_, B + (size_t)(col0 + r_) * K + kk_ + ch_ * 8);            \
    }                                                                            \
    CP_COMMIT();                                                                 \
} while (0)

    const int nslab = K >> 6;
    GPREF(0, 0);

    for (int s = 0; s < nslab; s++) {
        const int buf = s & 1;
        if (s + 1 < nslab) {
            GPREF(s + 1, buf ^ 1);
            CP_WAIT(1);
        } else {
            CP_WAIT(0);
        }
        __syncthreads();

        const uint32_t Ab = smb + (uint32_t)(buf * HSLAB * 4);
        const uint32_t Bb = smb + (uint32_t)((2 + buf) * HSLAB * 4);

#pragma unroll
        for (int ks = 0; ks < 4; ks++) {
            const int kk2 = ks * 8;
            uint32_t af[4][4], bf[4][2];
#pragma unroll
            for (int mi = 0; mi < 4; mi++) {
                uint32_t addr = Ab + (uint32_t)(((wm + mi * 16 + rA) * STW + kk2 + cA) * 4);
                ldsm4(af[mi][0], af[mi][1], af[mi][2], af[mi][3], addr);
            }
#pragma unroll
            for (int njp = 0; njp < 2; njp++) {
                uint32_t addr = Bb + (uint32_t)(((wn + njp * 16 + rB) * STW + kk2 + cB) * 4);
                ldsm4(bf[2 * njp][0], bf[2 * njp][1], bf[2 * njp + 1][0], bf[2 * njp + 1][1], addr);
            }
#pragma unroll
            for (int mi = 0; mi < 4; mi++)
#pragma unroll
                for (int nj = 0; nj < 4; nj++)
                    mma_fp16(acc[mi][nj], af[mi][0], af[mi][1], af[mi][2], af[mi][3],
                             bf[nj][0], bf[nj][1]);
        }
        __syncthreads();
    }
#undef GPREF

    if (MODE == 0) {
#pragma unroll
        for (int mi = 0; mi < 4; mi++)
#pragma unroll
            for (int nj = 0; nj < 4; nj++) {
                int r = row0 + wm + mi * 16 + g;
                int c = col0 + wn + nj * 8 + 2 * t;
                *(float2*)(C + (size_t)r * N + c)       = make_float2(acc[mi][nj][0], acc[mi][nj][1]);
                *(float2*)(C + (size_t)(r + 8) * N + c) = make_float2(acc[mi][nj][2], acc[mi][nj][3]);
            }
    } else if (MODE == 3) {
        // V: direct transposed half store. g_vt[(c_global)*TT + time]
#pragma unroll
        for (int mi = 0; mi < 4; mi++)
#pragma unroll
            for (int nj = 0; nj < 4; nj++) {
                int time0 = row0 + wm + mi * 16 + g;
                int c = col0 + wn + nj * 8 + 2 * t;
                g_vt[(size_t)c * TT + time0]           = __float2half(acc[mi][nj][0]);
                g_vt[(size_t)(c + 1) * TT + time0]     = __float2half(acc[mi][nj][1]);
                g_vt[(size_t)c * TT + time0 + 8]       = __float2half(acc[mi][nj][2]);
                g_vt[(size_t)(c + 1) * TT + time0 + 8] = __float2half(acc[mi][nj][3]);
            }
    } else {
        // Q/K rope epilogue: stage fp32 tile to smem, pair d with d+32.
        float* smf = (float*)sm;
#pragma unroll
        for (int mi = 0; mi < 4; mi++)
#pragma unroll
            for (int nj = 0; nj < 4; nj++) {
                int r = wm + mi * 16 + g;
                int c = wn + nj * 8 + 2 * t;
                *(float2*)&smf[r * SST + c]       = make_float2(acc[mi][nj][0], acc[mi][nj][1]);
                *(float2*)&smf[(r + 8) * SST + c] = make_float2(acc[mi][nj][2], acc[mi][nj][3]);
            }
        __syncthreads();
        const float sc = (MODE == 1) ? QSCALE : 1.0f;
        __half* dst = (MODE == 1) ? g_qh : g_kh;
        const int rowstride = (MODE == 1) ? (NH * DH) : (NKV * DH);
#pragma unroll
        for (int i = 0; i < 16; i++) {
            int e = tid + i * 256;
            int d2 = (e & 15) * 2;          // d (even), pairs (d, d+1)
            int head = (e >> 4) & 1;
            int r = e >> 5;
            int cb = head * 64 + d2;
            float2 x1 = *(float2*)&smf[r * SST + cb];
            float2 x2 = *(float2*)&smf[r * SST + cb + 32];
            float2 cc = *(const float2*)&cosb[(size_t)(row0 + r) * DH + d2];
            float2 ss = *(const float2*)&sinb[(size_t)(row0 + r) * DH + d2];
            float o1a = (x1.x * cc.x - x2.x * ss.x) * sc;
            float o1b = (x1.y * cc.y - x2.y * ss.y) * sc;
            float o2a = (x2.x * cc.x + x1.x * ss.x) * sc;
            float o2b = (x2.y * cc.y + x1.y * ss.y) * sc;
            size_t base = (size_t)(row0 + r) * rowstride + col0 + cb;
            *(uint32_t*)&dst[base]      = pack_half2(o1a, o1b);
            *(uint32_t*)&dst[base + 32] = pack_half2(o2a, o2b);
        }
    }
}

__global__ void __launch_bounds__(256, 2) qkv_gemm(const float* __restrict__ cosb,
                                                   const float* __restrict__ sinb) {
    extern __shared__ uint32_t sm[];
    int bx = blockIdx.x;
    int row0 = blockIdx.y * 128;
    if (bx < 16)
        gemm_body<1>(g_xh, g_wqh, nullptr, NH * DH,  HIDN, row0, bx * 128,        sm, cosb, sinb);
    else if (bx < 20)
        gemm_body<2>(g_xh, g_wkh, nullptr, NKV * DH, HIDN, row0, (bx - 16) * 128, sm, cosb, sinb);
    else
        gemm_body<3>(g_xh, g_wvh, nullptr, NKV * DH, HIDN, row0, (bx - 20) * 128, sm, cosb, sinb);
}

__global__ void __launch_bounds__(256, 2) o_gemm(float* __restrict__ C) {
    extern __shared__ uint32_t sm[];
    gemm_body<0>(g_atth, g_woh, C, HIDN, NH * DH, blockIdx.y * 128, blockIdx.x * 128, sm,
                 nullptr, nullptr);
}

// ---------------------------------------------------------------------------
// Flash attention, fp16 MMA, register-resident P, ldmatrix loads,
// 3-stage cp.async pipeline, ex2 softmax, deferred l-reduction.
// 128 q-rows x 1 head per block, 256 threads = 8 warps.
// ---------------------------------------------------------------------------
#define KP2 36   // half2 stride for 64-half rows
#define TILEW (64 * KP2)
#define NSTG 3
#define ATTN_SMEM (2 * NSTG * TILEW * (int)sizeof(uint32_t))

__global__ void __launch_bounds__(256) attn_kernel() {
    extern __shared__ uint32_t abuf[];
    uint32_t* Ks = abuf;                 // [NSTG][key][d] half2
    uint32_t* Vs = abuf + NSTG * TILEW;  // [NSTG][d][key] half2 (V^T)

    const int tid = threadIdx.x;
    const int wid = tid >> 5, lane = tid & 31;
    const int g = lane >> 2, t = lane & 3;
    const int wm = wid * 16;
    const int h = blockIdx.y;
    const int kvh = h / GRP;
    const int bx = gridDim.x - 1 - blockIdx.x;   // heavy CTAs first
    const int m0 = bx * 128;

    const int rB = ((lane >> 4) & 1) * 8 + (lane & 7);
    const int cB = ((lane >> 3) & 1) * 4;
    const uint32_t ksb = (uint32_t)__cvta_generic_to_shared(Ks);
    const uint32_t vsb = (uint32_t)__cvta_generic_to_shared(Vs);

    const int pr0 = tid >> 3,          pc0 = tid & 7;
    const int pr1 = (tid + 256) >> 3,  pc1 = tid & 7;
    const __half* kbase = &g_kh[(size_t)kvh * DH];
    const __half* vbase = &g_vt[(size_t)kvh * DH * TT];

#define PREFETCH(jt_, buf_) do {                                               \
    const int nn = (jt_) * 64;                                                 \
    uint32_t kd = ksb + (uint32_t)(((buf_) * TILEW + pr0 * KP2 + pc0 * 4) * 4);\
    CP_ASYNC16(kd, kbase + (size_t)(nn + pr0) * (NKV * DH) + pc0 * 8);         \
    kd = ksb + (uint32_t)(((buf_) * TILEW + pr1 * KP2 + pc1 * 4) * 4);         \
    CP_ASYNC16(kd, kbase + (size_t)(nn + pr1) * (NKV * DH) + pc1 * 8);         \
    uint32_t vd = vsb + (uint32_t)(((buf_) * TILEW + pr0 * KP2 + pc0 * 4) * 4);\
    CP_ASYNC16(vd, vbase + (size_t)pr0 * TT + nn + pc0 * 8);                   \
    vd = vsb + (uint32_t)(((buf_) * TILEW + pr1 * KP2 + pc1 * 4) * 4);         \
    CP_ASYNC16(vd, vbase + (size_t)pr1 * TT + nn + pc1 * 8);                   \
    CP_COMMIT();                                                               \
} while (0)

    const int r0 = m0 + wm + g, r1 = r0 + 8;
    uint32_t qf[4][4];
    {
        const __half* q0 = &g_qh[(size_t)r0 * (NH * DH) + h * DH];
        const __half* q1 = &g_qh[(size_t)r1 * (NH * DH) + h * DH];
#pragma unroll
        for (int ks = 0; ks < 4; ks++) {
            qf[ks][0] = *(const uint32_t*)(q0 + ks * 16 + 2 * t);
            qf[ks][1] = *(const uint32_t*)(q1 + ks * 16 + 2 * t);
            qf[ks][2] = *(const uint32_t*)(q0 + ks * 16 + 8 + 2 * t);
            qf[ks][3] = *(const uint32_t*)(q1 + ks * 16 + 8 + 2 * t);
        }
    }

    float mr0 = -1e30f, mr1 = -1e30f, l0 = 0.f, l1 = 0.f;  // l lane-partial
    float o[8][4];
#pragma unroll
    for (int j = 0; j < 8; j++)
#pragma unroll
        for (int q = 0; q < 4; q++) o[j][q] = 0.f;

    const int ntiles = 2 * bx + 2;
    PREFETCH(0, 0);
    if (ntiles > 1) PREFETCH(1, 1);

    int buf = 0;
    for (int jt = 0; jt < ntiles; jt++) {
        const int n0 = jt * 64;
        if (jt + 2 < ntiles) {
            int pb = buf + 2; if (pb >= NSTG) pb -= NSTG;
            PREFETCH(jt + 2, pb);
            CP_WAIT(2);
        } else if (jt + 1 < ntiles) {
            CP_WAIT(1);
        } else {
            CP_WAIT(0);
        }
        __syncthreads();

        const uint32_t kb = ksb + (uint32_t)(buf * TILEW * 4);
        const uint32_t vb = vsb + (uint32_t)(buf * TILEW * 4);

        float s[8][4];
#pragma unroll
        for (int j = 0; j < 8; j++)
#pragma unroll
            for (int q = 0; q < 4; q++) s[j][q] = 0.f;
#pragma unroll
        for (int ks = 0; ks < 4; ks++) {
            const int kk2 = ks * 8;
#pragma unroll
            for (int njp = 0; njp < 4; njp++) {
                uint32_t b0, b1, b2, b3;
                uint32_t addr = kb + (uint32_t)(((njp * 16 + rB) * KP2 + kk2 + cB) * 4);
                ldsm4(b0, b1, b2, b3, addr);
                mma_fp16(s[2 * njp],     qf[ks][0], qf[ks][1], qf[ks][2], qf[ks][3], b0, b1);
                mma_fp16(s[2 * njp + 1], qf[ks][0], qf[ks][1], qf[ks][2], qf[ks][3], b2, b3);
            }
        }

        if (jt >= 2 * bx) {
#pragma unroll
            for (int nj = 0; nj < 8; nj++) {
                int c0 = n0 + nj * 8 + 2 * t;
                if (c0     > r0) s[nj][0] = -1e30f;
                if (c0 + 1 > r0) s[nj][1] = -1e30f;
                if (c0     > r1) s[nj][2] = -1e30f;
                if (c0 + 1 > r1) s[nj][3] = -1e30f;
            }
        }

        float mx0 = -1e30f, mx1 = -1e30f;
#pragma unroll
        for (int nj = 0; nj < 8; nj++) {
            mx0 = fmaxf(mx0, fmaxf(s[nj][0], s[nj][1]));
            mx1 = fmaxf(mx1, fmaxf(s[nj][2], s[nj][3]));
        }
        mx0 = fmaxf(mx0, __shfl_xor_sync(0xffffffffu, mx0, 1));
        mx0 = fmaxf(mx0, __shfl_xor_sync(0xffffffffu, mx0, 2));
        mx1 = fmaxf(mx1, __shfl_xor_sync(0xffffffffu, mx1, 1));
        mx1 = fmaxf(mx1, __shfl_xor_sync(0xffffffffu, mx1, 2));
        float nm0 = fmaxf(mr0, mx0), nm1 = fmaxf(mr1, mx1);
        float f0 = ex2(mr0 - nm0), f1 = ex2(mr1 - nm1);
        float ps0 = 0.f, ps1 = 0.f;
#pragma unroll
        for (int nj = 0; nj < 8; nj++) {
            s[nj][0] = ex2(s[nj][0] - nm0);
            s[nj][1] = ex2(s[nj][1] - nm0);
            s[nj][2] = ex2(s[nj][2] - nm1);
            s[nj][3] = ex2(s[nj][3] - nm1);
            ps0 += s[nj][0] + s[nj][1];
            ps1 += s[nj][2] + s[nj][3];
        }
        l0 = l0 * f0 + ps0; l1 = l1 * f1 + ps1;
        mr0 = nm0; mr1 = nm1;
#pragma unroll
        for (int nj = 0; nj < 8; nj++) {
            o[nj][0] *= f0; o[nj][1] *= f0;
            o[nj][2] *= f1; o[nj][3] *= f1;
        }

#pragma unroll
        for (int ks = 0; ks < 4; ks++) {
            uint32_t a0 = pack_half2(s[2 * ks][0],     s[2 * ks][1]);
            uint32_t a1 = pack_half2(s[2 * ks][2],     s[2 * ks][3]);
            uint32_t a2 = pack_half2(s[2 * ks + 1][0], s[2 * ks + 1][1]);
            uint32_t a3 = pack_half2(s[2 * ks + 1][2], s[2 * ks + 1][3]);
            const int kk2 = ks * 8;
#pragma unroll
            for (int njp = 0; njp < 4; njp++) {
                uint32_t b0, b1, b2, b3;
                uint32_t addr = vb + (uint32_t)(((njp * 16 + rB) * KP2 + kk2 + cB) * 4);
                ldsm4(b0, b1, b2, b3, addr);
                mma_fp16(o[2 * njp],     a0, a1, a2, a3, b0, b1);
                mma_fp16(o[2 * njp + 1], a0, a1, a2, a3, b2, b3);
            }
        }
        __syncthreads();
        if (++buf == NSTG) buf = 0;
    }

    l0 += __shfl_xor_sync(0xffffffffu, l0, 1);
    l0 += __shfl_xor_sync(0xffffffffu, l0, 2);
    l1 += __shfl_xor_sync(0xffffffffu, l1, 1);
    l1 += __shfl_xor_sync(0xffffffffu, l1, 2);
    float i0 = 1.f / l0, i1 = 1.f / l1;
#pragma unroll
    for (int nj = 0; nj < 8; nj++) {
        int c = nj * 8 + 2 * t;
        *(uint32_t*)&g_atth[(size_t)r0 * (NH * DH) + h * DH + c] =
            pack_half2(o[nj][0] * i0, o[nj][1] * i0);
        *(uint32_t*)&g_atth[(size_t)r1 * (NH * DH) + h * DH + c] =
            pack_half2(o[nj][2] * i1, o[nj][3] * i1);
    }
#undef PREFETCH
}

// ---------------------------------------------------------------------------
extern "C" void kernel_launch(void* const* d_in, const int* in_sizes, int n_in,
                              void* d_out, int out_size) {
    const float* x    = (const float*)d_in[0];
    const float* cosb = (const float*)d_in[1];
    const float* sinb = (const float*)d_in[2];
    const float* Wq   = (const float*)d_in[4];
    const float* Wk   = (const float*)d_in[5];
    const float* Wv   = (const float*)d_in[6];
    const float* Wo   = (const float*)d_in[7];
    float* out = (float*)d_out;

    cudaFuncSetAttribute(qkv_gemm, cudaFuncAttributeMaxDynamicSharedMemorySize, GEMM_SMEM);
    cudaFuncSetAttribute(o_gemm,   cudaFuncAttributeMaxDynamicSharedMemorySize, GEMM_SMEM);
    cudaFuncSetAttribute(attn_kernel, cudaFuncAttributeMaxDynamicSharedMemorySize, ATTN_SMEM);

    tohalf_kernel<<<dim3(256, 5), 256>>>(x, Wq, Wk, Wv, Wo);

    qkv_gemm<<<dim3(24, 16), 256, GEMM_SMEM>>>(cosb, sinb);

    attn_kernel<<<dim3(TT / 128, NH), 256, ATTN_SMEM>>>();

    o_gemm<<<dim3(16, 16), 256, GEMM_SMEM>>>(out);
}

// round 13
// speedup vs baseline: 14.9374x; 1.0194x over previous
#include <cuda_runtime.h>
#include <cuda_fp16.h>
#include <stdint.h>
#include <math.h>

#define TT   2048
#define HIDN 2048
#define NH   32
#define NKV  8
#define DH   64
#define GRP  4
#define QSCALE 0.1803368801111204f   // (1/8) * log2(e)

// half operands
__device__ __half g_xh[TT * HIDN];
__device__ __half g_wqh[NH * DH * HIDN];
__device__ __half g_wkh[NKV * DH * HIDN];
__device__ __half g_wvh[NKV * DH * HIDN];
__device__ __half g_woh[HIDN * NH * DH];
__device__ __half g_qh[TT * NH * DH];            // rope'd, pre-scaled by QSCALE
__device__ __half g_kh[TT * NKV * DH];           // rope'd
__device__ __half g_vt[NKV * DH * TT];           // V transposed: [kvh][d][t]
__device__ __half g_atth[TT * NH * DH];          // attention output (half)

__device__ __forceinline__ uint32_t pack_half2(float lo, float hi) {
    uint32_t r;
    asm("cvt.rn.f16x2.f32 %0, %1, %2;" : "=r"(r) : "f"(hi), "f"(lo));
    return r;
}

__device__ __forceinline__ float ex2(float x) {
    float r;
    asm("ex2.approx.ftz.f32 %0, %1;" : "=f"(r) : "f"(x));
    return r;
}

__device__ __forceinline__ void mma_fp16(float* c,
                                         uint32_t a0, uint32_t a1, uint32_t a2, uint32_t a3,
                                         uint32_t b0, uint32_t b1) {
    asm volatile(
        "mma.sync.aligned.m16n8k16.row.col.f32.f16.f16.f32 "
        "{%0,%1,%2,%3},{%4,%5,%6,%7},{%8,%9},{%0,%1,%2,%3};"
        : "+f"(c[0]), "+f"(c[1]), "+f"(c[2]), "+f"(c[3])
        : "r"(a0), "r"(a1), "r"(a2), "r"(a3), "r"(b0), "r"(b1));
}

__device__ __forceinline__ void ldsm4(uint32_t& r0, uint32_t& r1,
                                      uint32_t& r2, uint32_t& r3, uint32_t addr) {
    asm volatile("ldmatrix.sync.aligned.m8n8.x4.shared.b16 {%0,%1,%2,%3}, [%4];"
                 : "=r"(r0), "=r"(r1), "=r"(r2), "=r"(r3) : "r"(addr));
}

#define CP_ASYNC16(dst, src) \
    asm volatile("cp.async.ca.shared.global [%0], [%1], 16;" :: "r"(dst), "l"(src) : "memory")
#define CP_COMMIT() asm volatile("cp.async.commit_group;" ::: "memory")
#define CP_WAIT(n)  asm volatile("cp.async.wait_group %0;" :: "n"(n) : "memory")

// ---------------------------------------------------------------------------
// fp32 -> fp16 conversion, 5 tensors in one launch (grid.y selects tensor)
// ---------------------------------------------------------------------------
__global__ void __launch_bounds__(256) tohalf_kernel(const float* x, const float* wq,
                                                     const float* wk, const float* wv,
                                                     const float* wo) {
    const float* src;
    __half* dst;
    int n;
    switch (blockIdx.y) {
        case 0: src = x;  dst = g_xh;  n = TT * HIDN;        break;
        case 1: src = wq; dst = g_wqh; n = NH * DH * HIDN;   break;
        case 2: src = wk; dst = g_wkh; n = NKV * DH * HIDN;  break;
        case 3: src = wv; dst = g_wvh; n = NKV * DH * HIDN;  break;
        default: src = wo; dst = g_woh; n = HIDN * NH * DH;  break;
    }
    int stride = gridDim.x * blockDim.x * 8;
    for (int i = (blockIdx.x * blockDim.x + threadIdx.x) * 8; i < n; i += stride) {
        float4 v0 = *(const float4*)(src + i);
        float4 v1 = *(const float4*)(src + i + 4);
        uint4 o = make_uint4(pack_half2(v0.x, v0.y), pack_half2(v0.z, v0.w),
                             pack_half2(v1.x, v1.y), pack_half2(v1.z, v1.w));
        *(uint4*)(dst + i) = o;
    }
}

// ---------------------------------------------------------------------------
// half GEMM with fused epilogues (128x128 tile variant for qkv).
// MODE 1: rope+QSCALE -> g_qh.  MODE 2: rope -> g_kh.  MODE 3: transpose -> g_vt.
// ---------------------------------------------------------------------------
#define STW 36                 // words per 64-half row (32 + 4 pad)
#define HSLAB (128 * STW)      // words per 128-row operand tile
#define GEMM_SMEM (4 * HSLAB * (int)sizeof(uint32_t))
#define SST 132                // fp32 staging stride for rope epilogue

template <int MODE>
__device__ __forceinline__ void gemm_body(const __half* __restrict__ A,
                                          const __half* __restrict__ B,
                                          int K, int row0, int col0,
                                          uint32_t* __restrict__ sm,
                                          const float* __restrict__ cosb,
                                          const float* __restrict__ sinb) {
    const int tid = threadIdx.x;
    const int wid = tid >> 5, lane = tid & 31;
    const int g = lane >> 2, t = lane & 3;
    const int wm = (wid >> 2) * 64;
    const int wn = (wid & 3) * 32;

    const int rA = ((lane >> 3) & 1) * 8 + (lane & 7);
    const int cA = ((lane >> 4) & 1) * 4;
    const int rB = ((lane >> 4) & 1) * 8 + (lane & 7);
    const int cB = ((lane >> 3) & 1) * 4;

    const uint32_t smb = (uint32_t)__cvta_generic_to_shared(sm);

    float acc[4][4][4];
#pragma unroll
    for (int i = 0; i < 4; i++)
#pragma unroll
        for (int j = 0; j < 4; j++)
#pragma unroll
            for (int q = 0; q < 4; q++) acc[i][j][q] = 0.f;

#define GPREF(s_, buf_) do {                                                     \
    const int kk_ = (s_) * 64;                                                   \
    _Pragma("unroll")                                                            \
    for (int i_ = 0; i_ < 4; i_++) {                                             \
        int e_ = tid + i_ * 256;                                                 \
        int r_ = e_ >> 3, ch_ = e_ & 7;                                          \
        uint32_t ad_ = smb + (uint32_t)((((buf_) * HSLAB) + r_ * STW + ch_ * 4) * 4); \
        CP_ASYNC16(ad_, A + (size_t)(row0 + r_) * K + kk_ + ch_ * 8);            \
        uint32_t bd_ = smb + (uint32_t)((((2 + (buf_)) * HSLAB) + r_ * STW + ch_ * 4) * 4); \
        CP_ASYNC16(bd_, B + (size_t)(col0 + r_) * K + kk_ + ch_ * 8);            \
    }                                                                            \
    CP_COMMIT();                                                                 \
} while (0)

    const int nslab = K >> 6;
    GPREF(0, 0);

    for (int s = 0; s < nslab; s++) {
        const int buf = s & 1;
        if (s + 1 < nslab) {
            GPREF(s + 1, buf ^ 1);
            CP_WAIT(1);
        } else {
            CP_WAIT(0);
        }
        __syncthreads();

        const uint32_t Ab = smb + (uint32_t)(buf * HSLAB * 4);
        const uint32_t Bb = smb + (uint32_t)((2 + buf) * HSLAB * 4);

#pragma unroll
        for (int ks = 0; ks < 4; ks++) {
            const int kk2 = ks * 8;
            uint32_t af[4][4], bf[4][2];
#pragma unroll
            for (int mi = 0; mi < 4; mi++) {
                uint32_t addr = Ab + (uint32_t)(((wm + mi * 16 + rA) * STW + kk2 + cA) * 4);
                ldsm4(af[mi][0], af[mi][1], af[mi][2], af[mi][3], addr);
            }
#pragma unroll
            for (int njp = 0; njp < 2; njp++) {
                uint32_t addr = Bb + (uint32_t)(((wn + njp * 16 + rB) * STW + kk2 + cB) * 4);
                ldsm4(bf[2 * njp][0], bf[2 * njp][1], bf[2 * njp + 1][0], bf[2 * njp + 1][1], addr);
            }
#pragma unroll
            for (int mi = 0; mi < 4; mi++)
#pragma unroll
                for (int nj = 0; nj < 4; nj++)
                    mma_fp16(acc[mi][nj], af[mi][0], af[mi][1], af[mi][2], af[mi][3],
                             bf[nj][0], bf[nj][1]);
        }
        __syncthreads();
    }
#undef GPREF

    if (MODE == 3) {
        // V: direct transposed half store. g_vt[(c_global)*TT + time]
#pragma unroll
        for (int mi = 0; mi < 4; mi++)
#pragma unroll
            for (int nj = 0; nj < 4; nj++) {
                int time0 = row0 + wm + mi * 16 + g;
                int c = col0 + wn + nj * 8 + 2 * t;
                g_vt[(size_t)c * TT + time0]           = __float2half(acc[mi][nj][0]);
                g_vt[(size_t)(c + 1) * TT + time0]     = __float2half(acc[mi][nj][1]);
                g_vt[(size_t)c * TT + time0 + 8]       = __float2half(acc[mi][nj][2]);
                g_vt[(size_t)(c + 1) * TT + time0 + 8] = __float2half(acc[mi][nj][3]);
            }
    } else {
        // Q/K rope epilogue: stage fp32 tile to smem, pair d with d+32.
        float* smf = (float*)sm;
#pragma unroll
        for (int mi = 0; mi < 4; mi++)
#pragma unroll
            for (int nj = 0; nj < 4; nj++) {
                int r = wm + mi * 16 + g;
                int c = wn + nj * 8 + 2 * t;
                *(float2*)&smf[r * SST + c]       = make_float2(acc[mi][nj][0], acc[mi][nj][1]);
                *(float2*)&smf[(r + 8) * SST + c] = make_float2(acc[mi][nj][2], acc[mi][nj][3]);
            }
        __syncthreads();
        const float sc = (MODE == 1) ? QSCALE : 1.0f;
        __half* dst = (MODE == 1) ? g_qh : g_kh;
        const int rowstride = (MODE == 1) ? (NH * DH) : (NKV * DH);
#pragma unroll
        for (int i = 0; i < 16; i++) {
            int e = tid + i * 256;
            int d2 = (e & 15) * 2;
            int head = (e >> 4) & 1;
            int r = e >> 5;
            int cb = head * 64 + d2;
            float2 x1 = *(float2*)&smf[r * SST + cb];
            float2 x2 = *(float2*)&smf[r * SST + cb + 32];
            float2 cc = *(const float2*)&cosb[(size_t)(row0 + r) * DH + d2];
            float2 ss = *(const float2*)&sinb[(size_t)(row0 + r) * DH + d2];
            float o1a = (x1.x * cc.x - x2.x * ss.x) * sc;
            float o1b = (x1.y * cc.y - x2.y * ss.y) * sc;
            float o2a = (x2.x * cc.x + x1.x * ss.x) * sc;
            float o2b = (x2.y * cc.y + x1.y * ss.y) * sc;
            size_t base = (size_t)(row0 + r) * rowstride + col0 + cb;
            *(uint32_t*)&dst[base]      = pack_half2(o1a, o1b);
            *(uint32_t*)&dst[base + 32] = pack_half2(o2a, o2b);
        }
    }
}

__global__ void __launch_bounds__(256, 2) qkv_gemm(const float* __restrict__ cosb,
                                                   const float* __restrict__ sinb) {
    extern __shared__ uint32_t sm[];
    int bx = blockIdx.x;
    int row0 = blockIdx.y * 128;
    if (bx < 16)
        gemm_body<1>(g_xh, g_wqh, HIDN, row0, bx * 128,        sm, cosb, sinb);
    else if (bx < 20)
        gemm_body<2>(g_xh, g_wkh, HIDN, row0, (bx - 16) * 128, sm, cosb, sinb);
    else
        gemm_body<3>(g_xh, g_wvh, HIDN, row0, (bx - 20) * 128, sm, cosb, sinb);
}

// ---------------------------------------------------------------------------
// o_gemm: 128x256 CTA tile, warp tile 64x64 (2x4 warp grid), cp.async
// double-buffered, ldsm fragments. out = g_atth @ g_woh^T, fp32 out.
// ---------------------------------------------------------------------------
#define HSLAB_A (128 * STW)
#define HSLAB_B (256 * STW)
#define OGEMM_SMEM ((2 * HSLAB_A + 2 * HSLAB_B) * (int)sizeof(uint32_t))

__global__ void __launch_bounds__(256, 1) o_gemm(float* __restrict__ C) {
    extern __shared__ uint32_t sm[];
    const __half* __restrict__ A = g_atth;
    const __half* __restrict__ B = g_woh;
    const int N = HIDN, K = NH * DH;
    const int row0 = blockIdx.y * 128;
    const int col0 = blockIdx.x * 256;

    const int tid = threadIdx.x;
    const int wid = tid >> 5, lane = tid & 31;
    const int g = lane >> 2, t = lane & 3;
    const int wm = (wid >> 2) * 64;
    const int wn = (wid & 3) * 64;

    const int rA = ((lane >> 3) & 1) * 8 + (lane & 7);
    const int cA = ((lane >> 4) & 1) * 4;
    const int rB = ((lane >> 4) & 1) * 8 + (lane & 7);
    const int cB = ((lane >> 3) & 1) * 4;

    const uint32_t smb = (uint32_t)__cvta_generic_to_shared(sm);
    const uint32_t Boff = (uint32_t)(2 * HSLAB_A * 4);

    float acc[4][8][4];
#pragma unroll
    for (int i = 0; i < 4; i++)
#pragma unroll
        for (int j = 0; j < 8; j++)
#pragma unroll
            for (int q = 0; q < 4; q++) acc[i][j][q] = 0.f;

#define OPREF(s_, buf_) do {                                                     \
    const int kk_ = (s_) * 64;                                                   \
    _Pragma("unroll")                                                            \
    for (int i_ = 0; i_ < 4; i_++) {                                             \
        int e_ = tid + i_ * 256;                                                 \
        int r_ = e_ >> 3, ch_ = e_ & 7;                                          \
        uint32_t ad_ = smb + (uint32_t)((((buf_) * HSLAB_A) + r_ * STW + ch_ * 4) * 4); \
        CP_ASYNC16(ad_, A + (size_t)(row0 + r_) * K + kk_ + ch_ * 8);            \
    }                                                                            \
    _Pragma("unroll")                                                            \
    for (int i_ = 0; i_ < 8; i_++) {                                             \
        int e_ = tid + i_ * 256;                                                 \
        int r_ = e_ >> 3, ch_ = e_ & 7;                                          \
        uint32_t bd_ = smb + Boff + (uint32_t)((((buf_) * HSLAB_B) + r_ * STW + ch_ * 4) * 4); \
        CP_ASYNC16(bd_, B + (size_t)(col0 + r_) * K + kk_ + ch_ * 8);            \
    }                                                                            \
    CP_COMMIT();                                                                 \
} while (0)

    const int nslab = K >> 6;
    OPREF(0, 0);

    for (int s = 0; s < nslab; s++) {
        const int buf = s & 1;
        if (s + 1 < nslab) {
            OPREF(s + 1, buf ^ 1);
            CP_WAIT(1);
        } else {
            CP_WAIT(0);
        }
        __syncthreads();

        const uint32_t Ab = smb + (uint32_t)(buf * HSLAB_A * 4);
        const uint32_t Bb = smb + Boff + (uint32_t)(buf * HSLAB_B * 4);

#pragma unroll
        for (int ks = 0; ks < 4; ks++) {
            const int kk2 = ks * 8;
            uint32_t af[4][4], bf[8][2];
#pragma unroll
            for (int mi = 0; mi < 4; mi++) {
                uint32_t addr = Ab + (uint32_t)(((wm + mi * 16 + rA) * STW + kk2 + cA) * 4);
                ldsm4(af[mi][0], af[mi][1], af[mi][2], af[mi][3], addr);
            }
#pragma unroll
            for (int njp = 0; njp < 4; njp++) {
                uint32_t addr = Bb + (uint32_t)(((wn + njp * 16 + rB) * STW + kk2 + cB) * 4);
                ldsm4(bf[2 * njp][0], bf[2 * njp][1], bf[2 * njp + 1][0], bf[2 * njp + 1][1], addr);
            }
#pragma unroll
            for (int mi = 0; mi < 4; mi++)
#pragma unroll
                for (int nj = 0; nj < 8; nj++)
                    mma_fp16(acc[mi][nj], af[mi][0], af[mi][1], af[mi][2], af[mi][3],
                             bf[nj][0], bf[nj][1]);
        }
        __syncthreads();
    }
#undef OPREF

#pragma unroll
    for (int mi = 0; mi < 4; mi++)
#pragma unroll
        for (int nj = 0; nj < 8; nj++) {
            int r = row0 + wm + mi * 16 + g;
            int c = col0 + wn + nj * 8 + 2 * t;
            *(float2*)(C + (size_t)r * N + c)       = make_float2(acc[mi][nj][0], acc[mi][nj][1]);
            *(float2*)(C + (size_t)(r + 8) * N + c) = make_float2(acc[mi][nj][2], acc[mi][nj][3]);
        }
}

// ---------------------------------------------------------------------------
// Flash attention (unchanged from R12): fp16 MMA, register-resident P,
// ldmatrix loads, 3-stage cp.async pipeline, ex2 softmax.
// ---------------------------------------------------------------------------
#define KP2 36
#define TILEW (64 * KP2)
#define NSTG 3
#define ATTN_SMEM (2 * NSTG * TILEW * (int)sizeof(uint32_t))

__global__ void __launch_bounds__(256) attn_kernel() {
    extern __shared__ uint32_t abuf[];
    uint32_t* Ks = abuf;
    uint32_t* Vs = abuf + NSTG * TILEW;

    const int tid = threadIdx.x;
    const int wid = tid >> 5, lane = tid & 31;
    const int g = lane >> 2, t = lane & 3;
    const int wm = wid * 16;
    const int h = blockIdx.y;
    const int kvh = h / GRP;
    const int bx = gridDim.x - 1 - blockIdx.x;
    const int m0 = bx * 128;

    const int rB = ((lane >> 4) & 1) * 8 + (lane & 7);
    const int cB = ((lane >> 3) & 1) * 4;
    const uint32_t ksb = (uint32_t)__cvta_generic_to_shared(Ks);
    const uint32_t vsb = (uint32_t)__cvta_generic_to_shared(Vs);

    const int pr0 = tid >> 3,          pc0 = tid & 7;
    const int pr1 = (tid + 256) >> 3,  pc1 = tid & 7;
    const __half* kbase = &g_kh[(size_t)kvh * DH];
    const __half* vbase = &g_vt[(size_t)kvh * DH * TT];

#define PREFETCH(jt_, buf_) do {                                               \
    const int nn = (jt_) * 64;                                                 \
    uint32_t kd = ksb + (uint32_t)(((buf_) * TILEW + pr0 * KP2 + pc0 * 4) * 4);\
    CP_ASYNC16(kd, kbase + (size_t)(nn + pr0) * (NKV * DH) + pc0 * 8);         \
    kd = ksb + (uint32_t)(((buf_) * TILEW + pr1 * KP2 + pc1 * 4) * 4);         \
    CP_ASYNC16(kd, kbase + (size_t)(nn + pr1) * (NKV * DH) + pc1 * 8);         \
    uint32_t vd = vsb + (uint32_t)(((buf_) * TILEW + pr0 * KP2 + pc0 * 4) * 4);\
    CP_ASYNC16(vd, vbase + (size_t)pr0 * TT + nn + pc0 * 8);                   \
    vd = vsb + (uint32_t)(((buf_) * TILEW + pr1 * KP2 + pc1 * 4) * 4);         \
    CP_ASYNC16(vd, vbase + (size_t)pr1 * TT + nn + pc1 * 8);                   \
    CP_COMMIT();                                                               \
} while (0)

    const int r0 = m0 + wm + g, r1 = r0 + 8;
    uint32_t qf[4][4];
    {
        const __half* q0 = &g_qh[(size_t)r0 * (NH * DH) + h * DH];
        const __half* q1 = &g_qh[(size_t)r1 * (NH * DH) + h * DH];
#pragma unroll
        for (int ks = 0; ks < 4; ks++) {
            qf[ks][0] = *(const uint32_t*)(q0 + ks * 16 + 2 * t);
            qf[ks][1] = *(const uint32_t*)(q1 + ks * 16 + 2 * t);
            qf[ks][2] = *(const uint32_t*)(q0 + ks * 16 + 8 + 2 * t);
            qf[ks][3] = *(const uint32_t*)(q1 + ks * 16 + 8 + 2 * t);
        }
    }

    float mr0 = -1e30f, mr1 = -1e30f, l0 = 0.f, l1 = 0.f;
    float o[8][4];
#pragma unroll
    for (int j = 0; j < 8; j++)
#pragma unroll
        for (int q = 0; q < 4; q++) o[j][q] = 0.f;

    const int ntiles = 2 * bx + 2;
    PREFETCH(0, 0);
    if (ntiles > 1) PREFETCH(1, 1);

    int buf = 0;
    for (int jt = 0; jt < ntiles; jt++) {
        const int n0 = jt * 64;
        if (jt + 2 < ntiles) {
            int pb = buf + 2; if (pb >= NSTG) pb -= NSTG;
            PREFETCH(jt + 2, pb);
            CP_WAIT(2);
        } else if (jt + 1 < ntiles) {
            CP_WAIT(1);
        } else {
            CP_WAIT(0);
        }
        __syncthreads();

        const uint32_t kb = ksb + (uint32_t)(buf * TILEW * 4);
        const uint32_t vb = vsb + (uint32_t)(buf * TILEW * 4);

        float s[8][4];
#pragma unroll
        for (int j = 0; j < 8; j++)
#pragma unroll
            for (int q = 0; q < 4; q++) s[j][q] = 0.f;
#pragma unroll
        for (int ks = 0; ks < 4; ks++) {
            const int kk2 = ks * 8;
#pragma unroll
            for (int njp = 0; njp < 4; njp++) {
                uint32_t b0, b1, b2, b3;
                uint32_t addr = kb + (uint32_t)(((njp * 16 + rB) * KP2 + kk2 + cB) * 4);
                ldsm4(b0, b1, b2, b3, addr);
                mma_fp16(s[2 * njp],     qf[ks][0], qf[ks][1], qf[ks][2], qf[ks][3], b0, b1);
                mma_fp16(s[2 * njp + 1], qf[ks][0], qf[ks][1], qf[ks][2], qf[ks][3], b2, b3);
            }
        }

        if (jt >= 2 * bx) {
#pragma unroll
            for (int nj = 0; nj < 8; nj++) {
                int c0 = n0 + nj * 8 + 2 * t;
                if (c0     > r0) s[nj][0] = -1e30f;
                if (c0 + 1 > r0) s[nj][1] = -1e30f;
                if (c0     > r1) s[nj][2] = -1e30f;
                if (c0 + 1 > r1) s[nj][3] = -1e30f;
            }
        }

        float mx0 = -1e30f, mx1 = -1e30f;
#pragma unroll
        for (int nj = 0; nj < 8; nj++) {
            mx0 = fmaxf(mx0, fmaxf(s[nj][0], s[nj][1]));
            mx1 = fmaxf(mx1, fmaxf(s[nj][2], s[nj][3]));
        }
        mx0 = fmaxf(mx0, __shfl_xor_sync(0xffffffffu, mx0, 1));
        mx0 = fmaxf(mx0, __shfl_xor_sync(0xffffffffu, mx0, 2));
        mx1 = fmaxf(mx1, __shfl_xor_sync(0xffffffffu, mx1, 1));
        mx1 = fmaxf(mx1, __shfl_xor_sync(0xffffffffu, mx1, 2));
        float nm0 = fmaxf(mr0, mx0), nm1 = fmaxf(mr1, mx1);
        float f0 = ex2(mr0 - nm0), f1 = ex2(mr1 - nm1);
        float ps0 = 0.f, ps1 = 0.f;
#pragma unroll
        for (int nj = 0; nj < 8; nj++) {
            s[nj][0] = ex2(s[nj][0] - nm0);
            s[nj][1] = ex2(s[nj][1] - nm0);
            s[nj][2] = ex2(s[nj][2] - nm1);
            s[nj][3] = ex2(s[nj][3] - nm1);
            ps0 += s[nj][0] + s[nj][1];
            ps1 += s[nj][2] + s[nj][3];
        }
        l0 = l0 * f0 + ps0; l1 = l1 * f1 + ps1;
        mr0 = nm0; mr1 = nm1;
#pragma unroll
        for (int nj = 0; nj < 8; nj++) {
            o[nj][0] *= f0; o[nj][1] *= f0;
            o[nj][2] *= f1; o[nj][3] *= f1;
        }

#pragma unroll
        for (int ks = 0; ks < 4; ks++) {
            uint32_t a0 = pack_half2(s[2 * ks][0],     s[2 * ks][1]);
            uint32_t a1 = pack_half2(s[2 * ks][2],     s[2 * ks][3]);
            uint32_t a2 = pack_half2(s[2 * ks + 1][0], s[2 * ks + 1][1]);
            uint32_t a3 = pack_half2(s[2 * ks + 1][2], s[2 * ks + 1][3]);
            const int kk2 = ks * 8;
#pragma unroll
            for (int njp = 0; njp < 4; njp++) {
                uint32_t b0, b1, b2, b3;
                uint32_t addr = vb + (uint32_t)(((njp * 16 + rB) * KP2 + kk2 + cB) * 4);
                ldsm4(b0, b1, b2, b3, addr);
                mma_fp16(o[2 * njp],     a0, a1, a2, a3, b0, b1);
                mma_fp16(o[2 * njp + 1], a0, a1, a2, a3, b2, b3);
            }
        }
        __syncthreads();
        if (++buf == NSTG) buf = 0;
    }

    l0 += __shfl_xor_sync(0xffffffffu, l0, 1);
    l0 += __shfl_xor_sync(0xffffffffu, l0, 2);
    l1 += __shfl_xor_sync(0xffffffffu, l1, 1);
    l1 += __shfl_xor_sync(0xffffffffu, l1, 2);
    float i0 = 1.f / l0, i1 = 1.f / l1;
#pragma unroll
    for (int nj = 0; nj < 8; nj++) {
        int c = nj * 8 + 2 * t;
        *(uint32_t*)&g_atth[(size_t)r0 * (NH * DH) + h * DH + c] =
            pack_half2(o[nj][0] * i0, o[nj][1] * i0);
        *(uint32_t*)&g_atth[(size_t)r1 * (NH * DH) + h * DH + c] =
            pack_half2(o[nj][2] * i1, o[nj][3] * i1);
    }
#undef PREFETCH
}

// ---------------------------------------------------------------------------
extern "C" void kernel_launch(void* const* d_in, const int* in_sizes, int n_in,
                              void* d_out, int out_size) {
    const float* x    = (const float*)d_in[0];
    const float* cosb = (const float*)d_in[1];
    const float* sinb = (const float*)d_in[2];
    const float* Wq   = (const float*)d_in[4];
    const float* Wk   = (const float*)d_in[5];
    const float* Wv   = (const float*)d_in[6];
    const float* Wo   = (const float*)d_in[7];
    float* out = (float*)d_out;

    cudaFuncSetAttribute(qkv_gemm, cudaFuncAttributeMaxDynamicSharedMemorySize, GEMM_SMEM);
    cudaFuncSetAttribute(o_gemm,   cudaFuncAttributeMaxDynamicSharedMemorySize, OGEMM_SMEM);
    cudaFuncSetAttribute(attn_kernel, cudaFuncAttributeMaxDynamicSharedMemorySize, ATTN_SMEM);

    tohalf_kernel<<<dim3(592, 5), 256>>>(x, Wq, Wk, Wv, Wo);

    qkv_gemm<<<dim3(24, 16), 256, GEMM_SMEM>>>(cosb, sinb);

    attn_kernel<<<dim3(TT / 128, NH), 256, ATTN_SMEM>>>();

    o_gemm<<<dim3(8, 16), 256, OGEMM_SMEM>>>(out);
}